// round 5
// baseline (speedup 1.0000x reference)
#include <cuda_runtime.h>
#include <math.h>

#define NSH  49
#define CC   128
#define HH   256
#define EPSV 1e-5f
#define HPAD 52      // hbuf rows padded (49 real + 3 zero)
#define PPAD 28      // padded grid-point dim per chunk (26 real + 2 zero)
#define WCPAD 132    // C weight row stride (128 K + pad)
#define WEPAD 260    // E weight row stride (256 K + pad)
#define TGDS 52      // tgd row stride in u64 (49 real + 3 zero-pad cols)
#define PPD  28      // fgdT row stride in u64

// smem layout (floats), all bases multiple of 4 (16B aligned):
// xn    : 0      .. +6272   (49x128)     [E: reduction scratch]
// hbuf  : 6272   .. +13312  (52x256)     [after D: htbf 49x256]
// S     : 19584  .. +33792  scratch:
//     C: wstC = S (256x132)
//     D: gbuf = S (28x256=7168); tgd = S+7168 (26x52 u64 = 2704 f);
//        fgdT = S+9872 (49x28 u64 = 2744 f -> pad 2752)
//     E: wstE = S (128x260)
// sgate : 53376 .. +256
// rbuf  : 53632 .. +32
#define O_XN    0
#define O_HBUF  6272
#define O_S     19584
#define O_SGATE 53376
#define O_RBUF  53632
#define SMEM_FLOATS 53664

typedef unsigned long long u64;

__device__ __forceinline__ u64 pack2(float lo, float hi) {
    u64 r; asm("mov.b64 %0, {%1, %2};" : "=l"(r) : "f"(lo), "f"(hi)); return r;
}
__device__ __forceinline__ void unpack2(u64 v, float& lo, float& hi) {
    asm("mov.b64 {%0, %1}, %2;" : "=f"(lo), "=f"(hi) : "l"(v));
}
__device__ __forceinline__ u64 fma2(u64 a, u64 b, u64 c) {
    u64 d; asm("fma.rn.f32x2 %0, %1, %2, %3;" : "=l"(d) : "l"(a), "l"(b), "l"(c)); return d;
}

__constant__ int c_ltab[NSH] = {
    0,
    1,1,1,
    2,2,2,2,2,
    3,3,3,3,3,3,3,
    4,4,4,4,4,4,4,4,4,
    5,5,5,5,5,5,5,5,5,5,5,
    6,6,6,6,6,6,6,6,6,6,6,6,6};

__constant__ float c_bal[NSH] = {
    0.0f,
    0.05555555556f,0.05555555556f,0.05555555556f,
    0.03333333333f,0.03333333333f,0.03333333333f,0.03333333333f,0.03333333333f,
    0.02380952381f,0.02380952381f,0.02380952381f,0.02380952381f,0.02380952381f,0.02380952381f,0.02380952381f,
    0.01851851852f,0.01851851852f,0.01851851852f,0.01851851852f,0.01851851852f,0.01851851852f,0.01851851852f,0.01851851852f,0.01851851852f,
    0.01515151515f,0.01515151515f,0.01515151515f,0.01515151515f,0.01515151515f,0.01515151515f,0.01515151515f,0.01515151515f,0.01515151515f,0.01515151515f,0.01515151515f,
    0.01282051282f,0.01282051282f,0.01282051282f,0.01282051282f,0.01282051282f,0.01282051282f,0.01282051282f,0.01282051282f,0.01282051282f,0.01282051282f,0.01282051282f,0.01282051282f,0.01282051282f};

__device__ __forceinline__ float fast_silu(float v) {
    return __fdividef(v, 1.0f + __expf(-v));
}

// dot over K=128 with packed f32x2 FMA: thread owns one weight column,
// CNT activation rows. Two packed partial sums per row, combined at the end.
template<int CNT>
__device__ __forceinline__ void dotc(const float* __restrict__ wcol,
                                     const float* __restrict__ xbase,
                                     int xstride, float* __restrict__ accout)
{
    u64 a0[CNT], a1[CNT];
    #pragma unroll
    for (int k = 0; k < CNT; k++) { a0[k] = 0ull; a1[k] = 0ull; }
    #pragma unroll 2
    for (int c4 = 0; c4 < CC; c4 += 4) {
        ulonglong2 w = *reinterpret_cast<const ulonglong2*>(wcol + c4);
        #pragma unroll
        for (int k = 0; k < CNT; k++) {
            ulonglong2 xv = *reinterpret_cast<const ulonglong2*>(xbase + k * xstride + c4);
            a0[k] = fma2(w.x, xv.x, a0[k]);
            a1[k] = fma2(w.y, xv.y, a1[k]);
        }
    }
    #pragma unroll
    for (int k = 0; k < CNT; k++) {
        float p0, p1, p2, p3;
        unpack2(a0[k], p0, p1);
        unpack2(a1[k], p2, p3);
        accout[k] = (p0 + p2) + (p1 + p3);
    }
}

__device__ __forceinline__ void dotc_dispatch(int g, const float* wcol,
                                              const float* xbase, int xstride,
                                              float* acc)
{
    switch (g) {
        case 1:  dotc<1>(wcol, xbase, xstride, acc);  break;
        case 3:  dotc<3>(wcol, xbase, xstride, acc);  break;
        case 5:  dotc<5>(wcol, xbase, xstride, acc);  break;
        case 7:  dotc<7>(wcol, xbase, xstride, acc);  break;
        case 9:  dotc<9>(wcol, xbase, xstride, acc);  break;
        case 11: dotc<11>(wcol, xbase, xstride, acc); break;
        case 13: dotc<13>(wcol, xbase, xstride, acc); break;
        default: break;
    }
}

// Grid forward, packed: tgd holds duplicated (t,t) pairs. Per i-pair:
// 2 x ull2 h loads + KC x ull2 t broadcasts, 4*KC f32x2 FMA.
template<int KC>
__device__ __forceinline__ void fwd_grid(const float* __restrict__ hb,
                                         const u64* __restrict__ tgd,
                                         int psel, int o4,
                                         u64* __restrict__ acc0,
                                         u64* __restrict__ acc1)
{
    #pragma unroll 2
    for (int i2 = 0; i2 < HPAD; i2 += 2) {
        ulonglong2 h0 = *reinterpret_cast<const ulonglong2*>(hb + (i2 + 0) * HH + o4);
        ulonglong2 h1 = *reinterpret_cast<const ulonglong2*>(hb + (i2 + 1) * HH + o4);
        #pragma unroll
        for (int k = 0; k < KC; k++) {
            ulonglong2 tt = *reinterpret_cast<const ulonglong2*>(tgd + (psel + 4 * k) * TGDS + i2);
            acc0[k] = fma2(tt.x, h0.x, acc0[k]);
            acc1[k] = fma2(tt.x, h0.y, acc1[k]);
            acc0[k] = fma2(tt.y, h1.x, acc0[k]);
            acc1[k] = fma2(tt.y, h1.y, acc1[k]);
        }
    }
}

// Grid backward, packed: fgdT holds duplicated (f,f) pairs; hacc persists
// across chunks in registers.
template<int KI>
__device__ __forceinline__ void bwd_grid(const float* __restrict__ gb,
                                         const u64* __restrict__ fgdT,
                                         int isel, int o4,
                                         u64* __restrict__ acc0,
                                         u64* __restrict__ acc1)
{
    #pragma unroll 2
    for (int p2 = 0; p2 < PPAD; p2 += 2) {
        ulonglong2 g0 = *reinterpret_cast<const ulonglong2*>(gb + (p2 + 0) * HH + o4);
        ulonglong2 g1 = *reinterpret_cast<const ulonglong2*>(gb + (p2 + 1) * HH + o4);
        #pragma unroll
        for (int k = 0; k < KI; k++) {
            ulonglong2 ff = *reinterpret_cast<const ulonglong2*>(fgdT + (isel + 4 * k) * PPD + p2);
            acc0[k] = fma2(ff.x, g0.x, acc0[k]);
            acc1[k] = fma2(ff.x, g0.y, acc1[k]);
            acc0[k] = fma2(ff.y, g1.x, acc0[k]);
            acc1[k] = fma2(ff.y, g1.y, acc1[k]);
        }
    }
}

__global__ void __launch_bounds__(256, 1)
ffn_fused(const float* __restrict__ x,
          const float* __restrict__ ln0_w, const float* __restrict__ ln0_b,
          const float* __restrict__ aff_w,
          const float* __restrict__ w1, const float* __restrict__ b1,
          const float* __restrict__ gate_w, const float* __restrict__ gate_b,
          const float* __restrict__ w2, const float* __restrict__ b2,
          const float* __restrict__ to_grid, const float* __restrict__ from_grid,
          float* __restrict__ out)
{
    extern __shared__ float sm[];
    float* xn    = sm + O_XN;
    float* hbuf  = sm + O_HBUF;
    float* S     = sm + O_S;
    float* sgate = sm + O_SGATE;
    float* rbuf  = sm + O_RBUF;

    const int tid = threadIdx.x;
    const int n   = blockIdx.x;
    const int wid = tid >> 5;
    const int lid = tid & 31;

    // ---------------- Phase A: load + norms ----------------
    const float4* xin = reinterpret_cast<const float4*>(x + (size_t)n * (NSH * CC));
    float4* xns = reinterpret_cast<float4*>(xn);
    #pragma unroll 4
    for (int j4 = tid; j4 < NSH * CC / 4; j4 += 256) xns[j4] = xin[j4];
    __syncthreads();

    float s0 = 0.f, q0 = 0.f, sw = 0.f;
    #pragma unroll 4
    for (int j4 = tid; j4 < NSH * CC / 4; j4 += 256) {
        float4 v = xns[j4];
        int m = j4 >> 5;
        float d = v.x * v.x + v.y * v.y + v.z * v.z + v.w * v.w;
        if (m == 0) { s0 += v.x + v.y + v.z + v.w; q0 += d; }
        else        sw += c_bal[m] * d;
    }
    #pragma unroll
    for (int o = 16; o > 0; o >>= 1) {
        s0 += __shfl_xor_sync(0xffffffffu, s0, o);
        q0 += __shfl_xor_sync(0xffffffffu, q0, o);
        sw += __shfl_xor_sync(0xffffffffu, sw, o);
    }
    if (lid == 0) { rbuf[wid] = s0; rbuf[8 + wid] = q0; rbuf[16 + wid] = sw; }
    __syncthreads();
    if (tid == 0) {
        float a = 0.f, b = 0.f, c = 0.f;
        #pragma unroll
        for (int k = 0; k < 8; k++) { a += rbuf[k]; b += rbuf[8 + k]; c += rbuf[16 + k]; }
        float muv  = a * (1.0f / CC);
        float varv = b * (1.0f / CC) - muv * muv;
        rbuf[24] = muv;
        rbuf[25] = rsqrtf(varv + EPSV);
        rbuf[26] = rsqrtf(c * (1.0f / CC) + EPSV);
    }
    __syncthreads();
    const float mu = rbuf[24], rstd = rbuf[25], inv = rbuf[26];

    #pragma unroll 4
    for (int j4 = tid; j4 < NSH * CC / 4; j4 += 256) {
        int m = j4 >> 5, c4 = (j4 & 31) << 2;
        float4 v = xns[j4];
        if (m == 0) {
            float4 w = *reinterpret_cast<const float4*>(ln0_w + c4);
            float4 b = *reinterpret_cast<const float4*>(ln0_b + c4);
            v.x = (v.x - mu) * rstd * w.x + b.x;
            v.y = (v.y - mu) * rstd * w.y + b.y;
            v.z = (v.z - mu) * rstd * w.z + b.z;
            v.w = (v.w - mu) * rstd * w.w + b.w;
        } else {
            float4 a = *reinterpret_cast<const float4*>(aff_w + (c_ltab[m] - 1) * CC + c4);
            v.x *= inv * a.x; v.y *= inv * a.y; v.z *= inv * a.z; v.w *= inv * a.w;
        }
        xns[j4] = v;
    }
    __syncthreads();

    // ---------------- Phase B: gate = silu(xn0 @ gate_w^T + gate_b) ----------------
    {
        const int c4 = lid << 2;
        float4 x0 = *reinterpret_cast<const float4*>(xn + c4);
        for (int ho = wid; ho < HH; ho += 8) {
            float4 g = *reinterpret_cast<const float4*>(gate_w + ho * CC + c4);
            float p = g.x * x0.x + g.y * x0.y + g.z * x0.z + g.w * x0.w;
            #pragma unroll
            for (int o = 16; o > 0; o >>= 1) p += __shfl_xor_sync(0xffffffffu, p, o);
            if (lid == 0) sgate[ho] = fast_silu(p + gate_b[ho]);
        }
    }

    // ---------------- Phase C: h[m,:] = xn[m,:] @ w1[l]^T ----------------
    {
        const int och = tid;
        float* wstC = S;
        for (int l = 0; l <= 6; l++) {
            const int g = 2 * l + 1, mbase = l * l;
            __syncthreads();   // protect wstC from previous readers
            const float4* wsrc = reinterpret_cast<const float4*>(w1 + (size_t)l * HH * CC);
            #pragma unroll 4
            for (int j4 = tid; j4 < HH * CC / 4; j4 += 256) {
                int o = j4 >> 5, c4 = (j4 & 31) << 2;
                *reinterpret_cast<float4*>(wstC + o * WCPAD + c4) = wsrc[j4];
            }
            __syncthreads();
            float acc[13];
            dotc_dispatch(g, wstC + och * WCPAD, xn + mbase * CC, CC, acc);
            #pragma unroll
            for (int k = 0; k < 13; k++) {
                if (k < g) {
                    float v = acc[k];
                    if (l == 0) v += b1[och];
                    hbuf[(mbase + k) * HH + och] = v;
                }
            }
        }
    }
    // zero hbuf pad rows 49..51
    for (int j = tid; j < 3 * HH; j += 256) hbuf[NSH * HH + j] = 0.f;
    __syncthreads();   // C compute done reading wstC, hbuf complete

    // ---------------- Phase D: ht = from_grid^T @ silu(to_grid @ h) ----------------
    float* gbuf = S;
    u64*   tgd  = reinterpret_cast<u64*>(S + 7168);   // 26 rows x TGDS u64
    u64*   fgdT = reinterpret_cast<u64*>(S + 9872);   // 49 rows x PPD u64
    const int o4   = (tid & 63) << 2;
    const int psel = tid >> 6;             // also isel for backward
    // zero pads once (S is free now)
    for (int j = tid; j < 2 * HH; j += 256) gbuf[26 * HH + j] = 0.f;
    for (int j = tid; j < 26 * 3; j += 256) {
        int p = j / 3, c = j - p * 3;
        tgd[p * TGDS + NSH + c] = 0ull;
    }
    for (int i = tid; i < NSH; i += 256) {
        fgdT[i * PPD + 26] = 0ull; fgdT[i * PPD + 27] = 0ull;
    }

    const int KI = (psel == 0) ? 13 : 12;  // i = psel + 4k
    u64 hacc0[13], hacc1[13];
    #pragma unroll
    for (int k = 0; k < 13; k++) { hacc0[k] = 0ull; hacc1[k] = 0ull; }

    for (int ch = 0; ch < 7; ch++) {
        const int pbase = ch * 26;
        __syncthreads();   // prev chunk's bwd reads done (or pad-zero init)
        #pragma unroll 2
        for (int j = tid; j < 26 * NSH; j += 256) {
            int p = j / NSH, i = j - p * NSH;
            float tv = to_grid[(size_t)(pbase + p) * NSH + i];
            float fv = from_grid[(size_t)(pbase + p) * NSH + i];
            tgd[p * TGDS + i]  = pack2(tv, tv);
            fgdT[i * PPD + p]  = pack2(fv, fv);
        }
        __syncthreads();
        {
            u64 acc0[7], acc1[7];
            const int kcnt = (psel < 2) ? 7 : 6;
            #pragma unroll
            for (int k = 0; k < 7; k++) { acc0[k] = 0ull; acc1[k] = 0ull; }
            if (psel < 2) fwd_grid<7>(hbuf, tgd, psel, o4, acc0, acc1);
            else          fwd_grid<6>(hbuf, tgd, psel, o4, acc0, acc1);
            #pragma unroll
            for (int k = 0; k < 7; k++) {
                if (k < kcnt) {
                    float4 v;
                    unpack2(acc0[k], v.x, v.y);
                    unpack2(acc1[k], v.z, v.w);
                    v.x = fast_silu(v.x); v.y = fast_silu(v.y);
                    v.z = fast_silu(v.z); v.w = fast_silu(v.w);
                    *reinterpret_cast<float4*>(gbuf + (psel + 4 * k) * HH + o4) = v;
                }
            }
        }
        __syncthreads();   // gbuf complete (also: all fwd reads of hbuf done)
        if (psel == 0) bwd_grid<13>(gbuf, fgdT, psel, o4, hacc0, hacc1);
        else           bwd_grid<12>(gbuf, fgdT, psel, o4, hacc0, hacc1);
    }
    // ht retires into the (now dead) hbuf region
    float* htbf = hbuf;
    #pragma unroll
    for (int k = 0; k < 13; k++) {
        if (k < KI) {
            float4 v;
            unpack2(hacc0[k], v.x, v.y);
            unpack2(hacc1[k], v.z, v.w);
            *reinterpret_cast<float4*>(htbf + (psel + 4 * k) * HH + o4) = v;
        }
    }

    // ---------------- Phase E: out[m,:] = h2[m,:] @ w2[l]^T (+b2 on m==0) ----------------
    {
        float* wstE  = S;
        float* redn  = xn;    // xn dead after C
        float* outn  = out + (size_t)n * (NSH * CC);
        const int oc = tid & 127;
        const int kh = tid >> 7;
        for (int l = 0; l <= 6; l++) {
            const int g = 2 * l + 1, mbase = l * l;
            __syncthreads();   // protect wstE + redn
            const float4* wsrc = reinterpret_cast<const float4*>(w2 + (size_t)l * CC * HH);
            #pragma unroll 4
            for (int j4 = tid; j4 < CC * HH / 4; j4 += 256) {
                int o = j4 >> 6, i4 = (j4 & 63) << 2;
                *reinterpret_cast<float4*>(wstE + o * WEPAD + i4) = wsrc[j4];
            }
            __syncthreads();
            float acc[13];
            const float* xr = (l == 0) ? (sgate + kh * 128)
                                       : (htbf + mbase * HH + kh * 128);
            dotc_dispatch(g, wstE + oc * WEPAD + kh * 128, xr, HH, acc);
            if (kh == 1) {
                #pragma unroll
                for (int k = 0; k < 13; k++)
                    if (k < g) redn[k * 128 + oc] = acc[k];
            }
            __syncthreads();
            if (kh == 0) {
                #pragma unroll
                for (int k = 0; k < 13; k++) {
                    if (k < g) {
                        float v = acc[k] + redn[k * 128 + oc];
                        if (l == 0) v += b2[oc];
                        outn[(mbase + k) * CC + oc] = v;
                    }
                }
            }
        }
    }
}

extern "C" void kernel_launch(void* const* d_in, const int* in_sizes, int n_in,
                              void* d_out, int out_size)
{
    const float* x      = (const float*)d_in[0];
    const float* ln0_w  = (const float*)d_in[1];
    const float* ln0_b  = (const float*)d_in[2];
    const float* aff_w  = (const float*)d_in[3];
    const float* w1     = (const float*)d_in[4];
    const float* b1     = (const float*)d_in[5];
    const float* gate_w = (const float*)d_in[6];
    const float* gate_b = (const float*)d_in[7];
    const float* w2     = (const float*)d_in[8];
    const float* b2     = (const float*)d_in[9];
    const float* tg     = (const float*)d_in[10];
    const float* fg     = (const float*)d_in[11];
    float* out = (float*)d_out;

    const int n_nodes = in_sizes[0] / (NSH * CC);
    const int smem_bytes = SMEM_FLOATS * (int)sizeof(float);
    cudaFuncSetAttribute(ffn_fused, cudaFuncAttributeMaxDynamicSharedMemorySize, smem_bytes);
    ffn_fused<<<n_nodes, 256, smem_bytes>>>(x, ln0_w, ln0_b, aff_w, w1, b1,
                                            gate_w, gate_b, w2, b2, tg, fg, out);
}

// round 7
// speedup vs baseline: 1.0012x; 1.0012x over previous
#include <cuda_runtime.h>
#include <cuda_bf16.h>
#include <math.h>
#include <cstdint>

#define NSH  49
#define CC   128
#define HH   256
#define EPSV 1e-5f
#define WCPAD 68     // C weight row stride (64 K-half + 4)
#define WEPAD 132    // E weight row stride (128 K-half + 4)
#define BFS  72      // bf16 operand row stride (64 K + 8 pad) -> conflict-free frags

// ---- smem layout (floats), all bases 16B aligned ----
// sgate @0 (256) | rbuf @256 (64)
// xn   @320 (6272)          [after D: htA 49x128]
// B1hi @6592 (9216=256x72 bf16)   [after D half1: htB 49x128]
// B1lo @15808 (9216)
// S    @25024 (18432):
//    C: wstC 256x68=17408
//    D: A1hi+0(2304) A1lo+2304 A2hi+4608 A2lo+6912 B2hi+9216(4608) B2lo+13824
//    E: wstE 128x132=16896
#define O_SGATE 0
#define O_RBUF  256
#define O_XN    320
#define O_B1HI  6592
#define O_B1LO  15808
#define O_S     25024
#define SMEM_FLOATS 43456

__constant__ int c_ltab[NSH] = {
    0,
    1,1,1,
    2,2,2,2,2,
    3,3,3,3,3,3,3,
    4,4,4,4,4,4,4,4,4,
    5,5,5,5,5,5,5,5,5,5,5,
    6,6,6,6,6,6,6,6,6,6,6,6,6};

__constant__ float c_bal[NSH] = {
    0.0f,
    0.05555555556f,0.05555555556f,0.05555555556f,
    0.03333333333f,0.03333333333f,0.03333333333f,0.03333333333f,0.03333333333f,
    0.02380952381f,0.02380952381f,0.02380952381f,0.02380952381f,0.02380952381f,0.02380952381f,0.02380952381f,
    0.01851851852f,0.01851851852f,0.01851851852f,0.01851851852f,0.01851851852f,0.01851851852f,0.01851851852f,0.01851851852f,0.01851851852f,
    0.01515151515f,0.01515151515f,0.01515151515f,0.01515151515f,0.01515151515f,0.01515151515f,0.01515151515f,0.01515151515f,0.01515151515f,0.01515151515f,0.01515151515f,
    0.01282051282f,0.01282051282f,0.01282051282f,0.01282051282f,0.01282051282f,0.01282051282f,0.01282051282f,0.01282051282f,0.01282051282f,0.01282051282f,0.01282051282f,0.01282051282f,0.01282051282f};

__device__ __forceinline__ float fast_silu(float v) {
    return __fdividef(v, 1.0f + __expf(-v));
}

// v -> bf16 hi + bf16 lo stored at same byte offset in two buffers
__device__ __forceinline__ void st_split(char* hib, char* lob, int byteoff, float v) {
    __nv_bfloat16 h = __float2bfloat16(v);
    float vh = __bfloat162float(h);
    __nv_bfloat16 l = __float2bfloat16(v - vh);
    *reinterpret_cast<__nv_bfloat16*>(hib + byteoff) = h;
    *reinterpret_cast<__nv_bfloat16*>(lob + byteoff) = l;
}

__device__ __forceinline__ void mma16816(float* d, const uint32_t* a,
                                         uint32_t b0, uint32_t b1) {
    asm volatile(
        "mma.sync.aligned.m16n8k16.row.col.f32.bf16.bf16.f32 "
        "{%0,%1,%2,%3}, {%4,%5,%6,%7}, {%8,%9}, {%0,%1,%2,%3};\n"
        : "+f"(d[0]), "+f"(d[1]), "+f"(d[2]), "+f"(d[3])
        : "r"(a[0]), "r"(a[1]), "r"(a[2]), "r"(a[3]), "r"(b0), "r"(b1));
}

// A fragment 16x16 bf16 from row-major [row][k], stride BFS bf16 (144B)
__device__ __forceinline__ void ldfragA(uint32_t* f, const char* base,
                                        int row, int k, int r0, int tig) {
    const char* p = base + (row + r0) * (BFS * 2) + (k + 2 * tig) * 2;
    f[0] = *reinterpret_cast<const uint32_t*>(p);
    f[1] = *reinterpret_cast<const uint32_t*>(p + 8 * BFS * 2);
    f[2] = *reinterpret_cast<const uint32_t*>(p + 16);
    f[3] = *reinterpret_cast<const uint32_t*>(p + 8 * BFS * 2 + 16);
}
// B fragment 16(K)x8(N) from B^T row-major [n][k], stride BFS
__device__ __forceinline__ void ldfragB(uint32_t* f, const char* base,
                                        int nrow, int k, int r0, int tig) {
    const char* p = base + (nrow + r0) * (BFS * 2) + (k + 2 * tig) * 2;
    f[0] = *reinterpret_cast<const uint32_t*>(p);
    f[1] = *reinterpret_cast<const uint32_t*>(p + 16);
}

// dot over K: thread owns one weight column, CNT activation rows.
template<int CNT>
__device__ __forceinline__ void dotc(const float* __restrict__ wcol,
                                     const float* __restrict__ xbase,
                                     int xstride, int K, float* __restrict__ acc)
{
    #pragma unroll 2
    for (int c4 = 0; c4 < K; c4 += 4) {
        float4 w = *reinterpret_cast<const float4*>(wcol + c4);
        #pragma unroll
        for (int k = 0; k < CNT; k++) {
            float4 xv = *reinterpret_cast<const float4*>(xbase + k * xstride + c4);
            acc[k] = fmaf(w.x, xv.x, acc[k]);
            acc[k] = fmaf(w.y, xv.y, acc[k]);
            acc[k] = fmaf(w.z, xv.z, acc[k]);
            acc[k] = fmaf(w.w, xv.w, acc[k]);
        }
    }
}

__device__ __forceinline__ void dotc_dispatch(int cnt, const float* wcol,
                                              const float* xbase, int xstride,
                                              int K, float* acc)
{
    switch (cnt) {
        case 1:  dotc<1>(wcol, xbase, xstride, K, acc);  break;
        case 2:  dotc<2>(wcol, xbase, xstride, K, acc);  break;
        case 3:  dotc<3>(wcol, xbase, xstride, K, acc);  break;
        case 4:  dotc<4>(wcol, xbase, xstride, K, acc);  break;
        case 5:  dotc<5>(wcol, xbase, xstride, K, acc);  break;
        case 6:  dotc<6>(wcol, xbase, xstride, K, acc);  break;
        case 7:  dotc<7>(wcol, xbase, xstride, K, acc);  break;
        case 9:  dotc<9>(wcol, xbase, xstride, K, acc);  break;
        case 11: dotc<11>(wcol, xbase, xstride, K, acc); break;
        case 13: dotc<13>(wcol, xbase, xstride, K, acc); break;
        default: break;
    }
}

__global__ void __launch_bounds__(256, 1)
ffn_fused(const float* __restrict__ x,
          const float* __restrict__ ln0_w, const float* __restrict__ ln0_b,
          const float* __restrict__ aff_w,
          const float* __restrict__ w1, const float* __restrict__ b1,
          const float* __restrict__ gate_w, const float* __restrict__ gate_b,
          const float* __restrict__ w2, const float* __restrict__ b2,
          const float* __restrict__ to_grid, const float* __restrict__ from_grid,
          float* __restrict__ out)
{
    extern __shared__ float sm[];
    float* sgate = sm + O_SGATE;
    float* rbuf  = sm + O_RBUF;
    float* xn    = sm + O_XN;
    float* S     = sm + O_S;

    const int tid = threadIdx.x;
    const int n   = blockIdx.x;
    const int wid = tid >> 5;
    const int lid = tid & 31;

    // ---------------- Phase A: load + norms ----------------
    const float4* xin = reinterpret_cast<const float4*>(x + (size_t)n * (NSH * CC));
    float4* xns = reinterpret_cast<float4*>(xn);
    #pragma unroll 4
    for (int j4 = tid; j4 < NSH * CC / 4; j4 += 256) xns[j4] = xin[j4];
    // zero B1 hi+lo (incl. i-pads)
    {
        float4* bz = reinterpret_cast<float4*>(sm + O_B1HI);
        for (int j = tid; j < 2 * 9216 / 4; j += 256) bz[j] = make_float4(0.f, 0.f, 0.f, 0.f);
    }
    __syncthreads();

    float s0 = 0.f, q0 = 0.f, sw = 0.f;
    #pragma unroll 4
    for (int j4 = tid; j4 < NSH * CC / 4; j4 += 256) {
        float4 v = xns[j4];
        int m = j4 >> 5;
        float d = v.x * v.x + v.y * v.y + v.z * v.z + v.w * v.w;
        if (m == 0) { s0 += v.x + v.y + v.z + v.w; q0 += d; }
        else        sw += c_bal[m] * d;
    }
    #pragma unroll
    for (int o = 16; o > 0; o >>= 1) {
        s0 += __shfl_xor_sync(0xffffffffu, s0, o);
        q0 += __shfl_xor_sync(0xffffffffu, q0, o);
        sw += __shfl_xor_sync(0xffffffffu, sw, o);
    }
    if (lid == 0) { rbuf[wid] = s0; rbuf[8 + wid] = q0; rbuf[16 + wid] = sw; }
    __syncthreads();
    if (tid == 0) {
        float a = 0.f, b = 0.f, c = 0.f;
        #pragma unroll
        for (int k = 0; k < 8; k++) { a += rbuf[k]; b += rbuf[8 + k]; c += rbuf[16 + k]; }
        float muv  = a * (1.0f / CC);
        float varv = b * (1.0f / CC) - muv * muv;
        rbuf[24] = muv;
        rbuf[25] = rsqrtf(varv + EPSV);
        rbuf[26] = rsqrtf(c * (1.0f / CC) + EPSV);
    }
    __syncthreads();
    const float mu = rbuf[24], rstd = rbuf[25], inv = rbuf[26];

    #pragma unroll 4
    for (int j4 = tid; j4 < NSH * CC / 4; j4 += 256) {
        int m = j4 >> 5, c4 = (j4 & 31) << 2;
        float4 v = xns[j4];
        if (m == 0) {
            float4 w = *reinterpret_cast<const float4*>(ln0_w + c4);
            float4 b = *reinterpret_cast<const float4*>(ln0_b + c4);
            v.x = (v.x - mu) * rstd * w.x + b.x;
            v.y = (v.y - mu) * rstd * w.y + b.y;
            v.z = (v.z - mu) * rstd * w.z + b.z;
            v.w = (v.w - mu) * rstd * w.w + b.w;
        } else {
            float4 a = *reinterpret_cast<const float4*>(aff_w + (c_ltab[m] - 1) * CC + c4);
            v.x *= inv * a.x; v.y *= inv * a.y; v.z *= inv * a.z; v.w *= inv * a.w;
        }
        xns[j4] = v;
    }
    __syncthreads();

    // ---------------- Phase B: gate = silu(xn0 @ gate_w^T + gate_b) ----------------
    {
        const int c4 = lid << 2;
        float4 x0 = *reinterpret_cast<const float4*>(xn + c4);
        for (int ho = wid; ho < HH; ho += 8) {
            float4 g = *reinterpret_cast<const float4*>(gate_w + ho * CC + c4);
            float p = g.x * x0.x + g.y * x0.y + g.z * x0.z + g.w * x0.w;
            #pragma unroll
            for (int o = 16; o > 0; o >>= 1) p += __shfl_xor_sync(0xffffffffu, p, o);
            if (lid == 0) sgate[ho] = fast_silu(p + gate_b[ho]);
        }
    }

    // ---------------- Phase C: h = xn @ w1^T -> B1 = h^T bf16 hi/lo ----------------
    {
        char* b1h = reinterpret_cast<char*>(sm + O_B1HI);
        char* b1l = reinterpret_cast<char*>(sm + O_B1LO);
        const int och = tid;
        float* wstC = S;
        for (int l = 0; l <= 6; l++) {
            const int g = 2 * l + 1, mbase = l * l;
            float acc[13];
            #pragma unroll
            for (int k = 0; k < 13; k++) acc[k] = 0.f;
            for (int kh = 0; kh < 2; kh++) {
                __syncthreads();
                // stage w1[l][:, kh*64 .. +64] -> 256 x 68
                for (int j4 = tid; j4 < 4096; j4 += 256) {
                    int o = j4 >> 4, c4 = (j4 & 15) << 2;
                    *reinterpret_cast<float4*>(wstC + o * WCPAD + c4) =
                        *reinterpret_cast<const float4*>(w1 + (size_t)l * HH * CC + o * CC + kh * 64 + c4);
                }
                __syncthreads();
                dotc_dispatch(g, wstC + och * WCPAD, xn + mbase * CC + kh * 64, CC, 64, acc);
            }
            #pragma unroll
            for (int k = 0; k < 13; k++) {
                if (k < g) {
                    int i = mbase + k;
                    float v = acc[k];
                    if (l == 0) v += b1[och];
                    st_split(b1h, b1l, och * (BFS * 2) + i * 2, v);
                }
            }
        }
    }

    // ---------------- Phase D: grid transform via mma.sync bf16 split ----------------
    {
        char* a1h = reinterpret_cast<char*>(S);
        char* a1l = reinterpret_cast<char*>(S + 2304);
        char* a2h = reinterpret_cast<char*>(S + 4608);
        char* a2l = reinterpret_cast<char*>(S + 6912);
        char* b2h = reinterpret_cast<char*>(S + 9216);
        char* b2l = reinterpret_cast<char*>(S + 13824);
        char* b1h = reinterpret_cast<char*>(sm + O_B1HI);
        char* b1l = reinterpret_cast<char*>(sm + O_B1LO);

        const int mt  = wid & 3;     // m-tile (16 rows)
        const int nh  = wid >> 2;    // n-tile group (8 tiles of 8)
        const int r0  = lid >> 2;
        const int tig = lid & 3;

        for (int half = 0; half < 2; half++) {
            float acc2[8][4];
            #pragma unroll
            for (int j = 0; j < 8; j++)
                #pragma unroll
                for (int q = 0; q < 4; q++) acc2[j][q] = 0.f;

            for (int ch = 0; ch < 3; ch++) {
                const int pbase = ch * 64;
                __syncthreads();   // prev GEMM2 reads of S done (or phase C wstC)

                // build A1 = T chunk [p 0..63][i 0..63], A2 = F^T chunk [i][p]
                for (int t = tid; t < 4096; t += 256) {
                    int p = t >> 6, i = t & 63;
                    int pg = pbase + p;
                    float tv = (pg < 182 && i < 49) ? to_grid[pg * NSH + i] : 0.f;
                    st_split(a1h, a1l, p * (BFS * 2) + i * 2, tv);
                }
                for (int t = tid; t < 4096; t += 256) {
                    int i = t & 63, p = t >> 6;
                    int pg = pbase + p;
                    float fv = (pg < 182 && i < 49) ? from_grid[pg * NSH + i] : 0.f;
                    st_split(a2h, a2l, i * (BFS * 2) + p * 2, fv);
                }
                __syncthreads();

                // GEMM1: g[p, c] = sum_i T[p,i] h[i,c]  (M=64, N=128 half, K=64)
                float acc1[8][4];
                #pragma unroll
                for (int j = 0; j < 8; j++)
                    #pragma unroll
                    for (int q = 0; q < 4; q++) acc1[j][q] = 0.f;
                #pragma unroll
                for (int ks = 0; ks < 4; ks++) {
                    uint32_t ah[4], al[4];
                    ldfragA(ah, a1h, mt * 16, ks * 16, r0, tig);
                    ldfragA(al, a1l, mt * 16, ks * 16, r0, tig);
                    #pragma unroll
                    for (int j = 0; j < 8; j++) {
                        int nrow = half * 128 + (nh * 8 + j) * 8;
                        uint32_t bh[2], bl[2];
                        ldfragB(bh, b1h, nrow, ks * 16, r0, tig);
                        ldfragB(bl, b1l, nrow, ks * 16, r0, tig);
                        mma16816(acc1[j], ah, bh[0], bh[1]);
                        mma16816(acc1[j], ah, bl[0], bl[1]);
                        mma16816(acc1[j], al, bh[0], bh[1]);
                    }
                }
                // epilogue: silu -> B2 = g^T [c_local][p] bf16 hi/lo
                #pragma unroll
                for (int j = 0; j < 8; j++) {
                    int cl = (nh * 8 + j) * 8 + 2 * tig;
                    int p0 = mt * 16 + r0;
                    st_split(b2h, b2l, cl * (BFS * 2) + p0 * 2,       fast_silu(acc1[j][0]));
                    st_split(b2h, b2l, (cl + 1) * (BFS * 2) + p0 * 2, fast_silu(acc1[j][1]));
                    st_split(b2h, b2l, cl * (BFS * 2) + (p0 + 8) * 2,       fast_silu(acc1[j][2]));
                    st_split(b2h, b2l, (cl + 1) * (BFS * 2) + (p0 + 8) * 2, fast_silu(acc1[j][3]));
                }
                __syncthreads();

                // GEMM2: ht[i, c] += sum_p F[p,i] g[p,c]  (M=64, N=128, K=64)
                #pragma unroll
                for (int ks = 0; ks < 4; ks++) {
                    uint32_t ah[4], al[4];
                    ldfragA(ah, a2h, mt * 16, ks * 16, r0, tig);
                    ldfragA(al, a2l, mt * 16, ks * 16, r0, tig);
                    #pragma unroll
                    for (int j = 0; j < 8; j++) {
                        int nrow = (nh * 8 + j) * 8;
                        uint32_t bh[2], bl[2];
                        ldfragB(bh, b2h, nrow, ks * 16, r0, tig);
                        ldfragB(bl, b2l, nrow, ks * 16, r0, tig);
                        mma16816(acc2[j], ah, bh[0], bh[1]);
                        mma16816(acc2[j], ah, bl[0], bl[1]);
                        mma16816(acc2[j], al, bh[0], bh[1]);
                    }
                }
            }

            // store ht half: htA (half 0) -> xn region, htB (half 1) -> B1hi region
            float* htx = (half == 0) ? (sm + O_XN) : (sm + O_B1HI);
            #pragma unroll
            for (int j = 0; j < 8; j++) {
                int cl = (nh * 8 + j) * 8 + 2 * tig;
                int i0 = mt * 16 + r0;
                if (i0 < NSH) {
                    htx[i0 * 128 + cl]     = acc2[j][0];
                    htx[i0 * 128 + cl + 1] = acc2[j][1];
                }
                if (i0 + 8 < NSH) {
                    htx[(i0 + 8) * 128 + cl]     = acc2[j][2];
                    htx[(i0 + 8) * 128 + cl + 1] = acc2[j][3];
                }
            }
        }
    }

    // ---------------- Phase E: out[m,:] = h2[m,:] @ w2[l]^T (+b2 on m==0) ----------------
    {
        float* wstE = S;
        float* htA  = sm + O_XN;
        float* htB  = sm + O_B1HI;
        float* outn = out + (size_t)n * (NSH * CC);
        const int oc = tid & 127;
        const int rh = tid >> 7;
        for (int l = 0; l <= 6; l++) {
            const int g = 2 * l + 1, mbase = l * l;
            const int cnt = (g - rh + 1) >> 1;
            float acc[7];
            #pragma unroll
            for (int k = 0; k < 7; k++) acc[k] = 0.f;
            for (int kh = 0; kh < 2; kh++) {
                __syncthreads();   // protect wstE (D reads of S / prev stage)
                // stage w2[l][:, kh*128 .. +128] -> 128 x 132
                for (int j4 = tid; j4 < 4096; j4 += 256) {
                    int o = j4 >> 5, kk = (j4 & 31) << 2;
                    *reinterpret_cast<float4*>(wstE + o * WEPAD + kk) =
                        *reinterpret_cast<const float4*>(w2 + (size_t)l * CC * HH + o * HH + kh * 128 + kk);
                }
                __syncthreads();
                if (cnt > 0) {
                    const float* ht = (kh == 0) ? htA : htB;
                    const float* xr = (l == 0) ? (sgate + kh * 128)
                                               : (ht + (mbase + rh) * 128);
                    dotc_dispatch(cnt, wstE + oc * WEPAD, xr, 2 * 128, 128, acc);
                }
            }
            if (cnt > 0) {
                #pragma unroll
                for (int k = 0; k < 7; k++) {
                    if (k < cnt) {
                        int m = mbase + rh + 2 * k;
                        float v = acc[k];
                        if (m == 0) v += b2[oc];
                        outn[m * CC + oc] = v;
                    }
                }
            }
        }
    }
}

extern "C" void kernel_launch(void* const* d_in, const int* in_sizes, int n_in,
                              void* d_out, int out_size)
{
    const float* x      = (const float*)d_in[0];
    const float* ln0_w  = (const float*)d_in[1];
    const float* ln0_b  = (const float*)d_in[2];
    const float* aff_w  = (const float*)d_in[3];
    const float* w1     = (const float*)d_in[4];
    const float* b1     = (const float*)d_in[5];
    const float* gate_w = (const float*)d_in[6];
    const float* gate_b = (const float*)d_in[7];
    const float* w2     = (const float*)d_in[8];
    const float* b2     = (const float*)d_in[9];
    const float* tg     = (const float*)d_in[10];
    const float* fg     = (const float*)d_in[11];
    float* out = (float*)d_out;

    const int n_nodes = in_sizes[0] / (NSH * CC);
    const int smem_bytes = SMEM_FLOATS * (int)sizeof(float);
    cudaFuncSetAttribute(ffn_fused, cudaFuncAttributeMaxDynamicSharedMemorySize, smem_bytes);
    ffn_fused<<<n_nodes, 256, smem_bytes>>>(x, ln0_w, ln0_b, aff_w, w1, b1,
                                            gate_w, gate_b, w2, b2, tg, fg, out);
}

// round 8
// speedup vs baseline: 1.7322x; 1.7301x over previous
#include <cuda_runtime.h>
#include <cuda_bf16.h>
#include <math.h>
#include <cstdint>

#define NSH  49
#define CC   128
#define HH   256
#define EPSV 1e-5f

// ---------------- smem layout (floats) ----------------
// sgate 0..256 | rbuf 256..320
// B1 (h^T bf16 [256 n][68 i]) : hi 320..9024, lo 9024..17728
// B2 (g^T bf16 [256 c][68 p]) : hi 17728..26432, lo 26432..35136
//   xn fp32 (6272)  overlays B2hi region (dead before D)
//   xnbf hi/lo (8448) overlays B2lo region (dead after C)
// h2 (bf16 [64 i][260 c])     : hi 35136..43456, lo 43456..51776
#define O_SGATE 0
#define O_RBUF  256
#define O_B1HI  320
#define O_B1LO  9024
#define O_B2HI  17728
#define O_B2LO  26432
#define O_XN    17728
#define O_XNBFH 26432
#define O_XNBFL 30656
#define O_H2HI  35136
#define O_H2LO  43456
#define SMEM_FLOATS 51776

// fragment-linear global operand banks (filled by prep kernel)
#define W1F_IDX(h,l,nt,ks) (((((h)*7 + (l))*32 + (nt))*8 + (ks)))
#define W2F_IDX(h,l,nt,ks) (((((h)*7 + (l))*16 + (nt))*16 + (ks)))
#define A1F_IDX(h,ch,mt,ks) (((((h)*3 + (ch))*4 + (mt))*4 + (ks)))
__device__ uint2 g_w1f[2*7*32*8*32];    // [hi/lo][l][ntile N=256][ks K=128][lane]
__device__ uint2 g_w2f[2*7*16*16*32];   // [hi/lo][l][ntile N=128][ks K=256][lane]
__device__ uint4 g_a1f[2*3*4*4*32];     // to_grid A frags  [hi/lo][chunk][mt][ks][lane]
__device__ uint4 g_a2f[2*3*4*4*32];     // from_grid^T A frags

__constant__ int c_ltab[NSH] = {
    0,
    1,1,1,
    2,2,2,2,2,
    3,3,3,3,3,3,3,
    4,4,4,4,4,4,4,4,4,
    5,5,5,5,5,5,5,5,5,5,5,
    6,6,6,6,6,6,6,6,6,6,6,6,6};

__constant__ float c_bal[NSH] = {
    0.0f,
    0.05555555556f,0.05555555556f,0.05555555556f,
    0.03333333333f,0.03333333333f,0.03333333333f,0.03333333333f,0.03333333333f,
    0.02380952381f,0.02380952381f,0.02380952381f,0.02380952381f,0.02380952381f,0.02380952381f,0.02380952381f,
    0.01851851852f,0.01851851852f,0.01851851852f,0.01851851852f,0.01851851852f,0.01851851852f,0.01851851852f,0.01851851852f,0.01851851852f,
    0.01515151515f,0.01515151515f,0.01515151515f,0.01515151515f,0.01515151515f,0.01515151515f,0.01515151515f,0.01515151515f,0.01515151515f,0.01515151515f,0.01515151515f,
    0.01282051282f,0.01282051282f,0.01282051282f,0.01282051282f,0.01282051282f,0.01282051282f,0.01282051282f,0.01282051282f,0.01282051282f,0.01282051282f,0.01282051282f,0.01282051282f,0.01282051282f};

__device__ __forceinline__ float fast_silu(float v) {
    return __fdividef(v, 1.0f + __expf(-v));
}
__device__ __forceinline__ uint16_t bfh(float v) {
    return __bfloat16_as_ushort(__float2bfloat16(v));
}
__device__ __forceinline__ uint16_t bfl(float v) {
    __nv_bfloat16 h = __float2bfloat16(v);
    return __bfloat16_as_ushort(__float2bfloat16(v - __bfloat162float(h)));
}
__device__ __forceinline__ uint32_t pk(uint16_t a, uint16_t b) {
    return (uint32_t)a | ((uint32_t)b << 16);
}
__device__ __forceinline__ void st_split(char* hib, char* lob, int byteoff, float v) {
    __nv_bfloat16 h = __float2bfloat16(v);
    float vh = __bfloat162float(h);
    __nv_bfloat16 l = __float2bfloat16(v - vh);
    *reinterpret_cast<__nv_bfloat16*>(hib + byteoff) = h;
    *reinterpret_cast<__nv_bfloat16*>(lob + byteoff) = l;
}
__device__ __forceinline__ void mma16816(float* d, const uint32_t* a,
                                         uint32_t b0, uint32_t b1) {
    asm volatile(
        "mma.sync.aligned.m16n8k16.row.col.f32.bf16.bf16.f32 "
        "{%0,%1,%2,%3}, {%4,%5,%6,%7}, {%8,%9}, {%0,%1,%2,%3};\n"
        : "+f"(d[0]), "+f"(d[1]), "+f"(d[2]), "+f"(d[3])
        : "r"(a[0]), "r"(a[1]), "r"(a[2]), "r"(a[3]), "r"(b0), "r"(b1));
}
// A fragment (16x16) from row-major bf16 [row][k], byte stride strideB
__device__ __forceinline__ void ldA(uint32_t* f, const char* base, int row0, int k,
                                    int r0, int tig, int strideB) {
    const char* p = base + (row0 + r0) * strideB + (k + 2 * tig) * 2;
    f[0] = *reinterpret_cast<const uint32_t*>(p);
    f[1] = *reinterpret_cast<const uint32_t*>(p + 8 * strideB);
    f[2] = *reinterpret_cast<const uint32_t*>(p + 16);
    f[3] = *reinterpret_cast<const uint32_t*>(p + 8 * strideB + 16);
}
// B fragment (16k x 8n) from B^T row-major bf16 [n][k], byte stride strideB
__device__ __forceinline__ void ldB(uint32_t* f, const char* base, int nrow, int k,
                                    int r0, int tig, int strideB) {
    const char* p = base + (nrow + r0) * strideB + (k + 2 * tig) * 2;
    f[0] = *reinterpret_cast<const uint32_t*>(p);
    f[1] = *reinterpret_cast<const uint32_t*>(p + 16);
}

// ---------------- prep kernel: build fragment banks ----------------
__global__ void prep_frags(const float* __restrict__ w1, const float* __restrict__ w2,
                           const float* __restrict__ tg, const float* __restrict__ fg)
{
    int t = blockIdx.x * 256 + threadIdx.x;
    if (t >= 3680 * 32) return;
    int lane = t & 31;
    int r0 = lane >> 2, tig = lane & 3;
    int fi = t >> 5;

    if (fi < 1792) {                       // w1 frags: l x nt(32) x ks(8)
        int ks = fi & 7, nt = (fi >> 3) & 31, l = fi >> 8;
        int n = nt * 8 + r0, k = ks * 16 + 2 * tig;
        const float* s = w1 + ((size_t)l * HH + n) * CC + k;
        float v0 = s[0], v1 = s[1], v8 = s[8], v9 = s[9];
        g_w1f[(size_t)W1F_IDX(0, l, nt, ks) * 32 + lane] =
            make_uint2(pk(bfh(v0), bfh(v1)), pk(bfh(v8), bfh(v9)));
        g_w1f[(size_t)W1F_IDX(1, l, nt, ks) * 32 + lane] =
            make_uint2(pk(bfl(v0), bfl(v1)), pk(bfl(v8), bfl(v9)));
    } else if (fi < 3584) {                // w2 frags: l x nt(16) x ks(16)
        int fj = fi - 1792;
        int ks = fj & 15, nt = (fj >> 4) & 15, l = fj >> 8;
        int n = nt * 8 + r0, k = ks * 16 + 2 * tig;
        const float* s = w2 + ((size_t)l * CC + n) * HH + k;
        float v0 = s[0], v1 = s[1], v8 = s[8], v9 = s[9];
        g_w2f[(size_t)W2F_IDX(0, l, nt, ks) * 32 + lane] =
            make_uint2(pk(bfh(v0), bfh(v1)), pk(bfh(v8), bfh(v9)));
        g_w2f[(size_t)W2F_IDX(1, l, nt, ks) * 32 + lane] =
            make_uint2(pk(bfl(v0), bfl(v1)), pk(bfl(v8), bfl(v9)));
    } else if (fi < 3632) {                // a1: A = to_grid [p][i], ch x mt x ks
        int fk = fi - 3584;
        int ks = fk & 3, mt = (fk >> 2) & 3, ch = fk >> 4;
        int pa = ch * 64 + mt * 16 + r0, pb = pa + 8;
        int ia = ks * 16 + 2 * tig;
        auto val = [&](int p, int i) -> float {
            return (p < 182 && i < NSH) ? tg[p * NSH + i] : 0.f;
        };
        float xa0 = val(pa, ia), xa1 = val(pa, ia + 1);
        float ya0 = val(pb, ia), ya1 = val(pb, ia + 1);
        float za0 = val(pa, ia + 8), za1 = val(pa, ia + 9);
        float wa0 = val(pb, ia + 8), wa1 = val(pb, ia + 9);
        g_a1f[(size_t)A1F_IDX(0, ch, mt, ks) * 32 + lane] =
            make_uint4(pk(bfh(xa0), bfh(xa1)), pk(bfh(ya0), bfh(ya1)),
                       pk(bfh(za0), bfh(za1)), pk(bfh(wa0), bfh(wa1)));
        g_a1f[(size_t)A1F_IDX(1, ch, mt, ks) * 32 + lane] =
            make_uint4(pk(bfl(xa0), bfl(xa1)), pk(bfl(ya0), bfl(ya1)),
                       pk(bfl(za0), bfl(za1)), pk(bfl(wa0), bfl(wa1)));
    } else {                               // a2: A = from_grid^T [i][p]
        int fk = fi - 3632;
        int ks = fk & 3, mt = (fk >> 2) & 3, ch = fk >> 4;
        int ia = mt * 16 + r0, ib = ia + 8;
        int p0 = ch * 64 + ks * 16 + 2 * tig;
        auto val = [&](int i, int p) -> float {
            return (p < 182 && i < NSH) ? fg[p * NSH + i] : 0.f;
        };
        float xa0 = val(ia, p0), xa1 = val(ia, p0 + 1);
        float ya0 = val(ib, p0), ya1 = val(ib, p0 + 1);
        float za0 = val(ia, p0 + 8), za1 = val(ia, p0 + 9);
        float wa0 = val(ib, p0 + 8), wa1 = val(ib, p0 + 9);
        g_a2f[(size_t)A1F_IDX(0, ch, mt, ks) * 32 + lane] =
            make_uint4(pk(bfh(xa0), bfh(xa1)), pk(bfh(ya0), bfh(ya1)),
                       pk(bfh(za0), bfh(za1)), pk(bfh(wa0), bfh(wa1)));
        g_a2f[(size_t)A1F_IDX(1, ch, mt, ks) * 32 + lane] =
            make_uint4(pk(bfl(xa0), bfl(xa1)), pk(bfl(ya0), bfl(ya1)),
                       pk(bfl(za0), bfl(za1)), pk(bfl(wa0), bfl(wa1)));
    }
}

// ---------------- main kernel ----------------
__global__ void __launch_bounds__(512, 1)
ffn_fused(const float* __restrict__ x,
          const float* __restrict__ ln0_w, const float* __restrict__ ln0_b,
          const float* __restrict__ aff_w,
          const float* __restrict__ b1,
          const float* __restrict__ gate_w, const float* __restrict__ gate_b,
          const float* __restrict__ b2,
          float* __restrict__ out)
{
    extern __shared__ float sm[];
    float* sgate = sm + O_SGATE;
    float* rbuf  = sm + O_RBUF;
    float* xn    = sm + O_XN;

    char* b1h = reinterpret_cast<char*>(sm + O_B1HI);
    char* b1l = reinterpret_cast<char*>(sm + O_B1LO);
    char* b2h = reinterpret_cast<char*>(sm + O_B2HI);
    char* b2l = reinterpret_cast<char*>(sm + O_B2LO);
    char* xnh = reinterpret_cast<char*>(sm + O_XNBFH);
    char* xnl = reinterpret_cast<char*>(sm + O_XNBFL);
    char* h2h = reinterpret_cast<char*>(sm + O_H2HI);
    char* h2l = reinterpret_cast<char*>(sm + O_H2LO);

    const int tid = threadIdx.x;
    const int n   = blockIdx.x;
    const int wid = tid >> 5;
    const int lid = tid & 31;
    const int r0  = lid >> 2;
    const int tig = lid & 3;

    // ---- Phase A: load x, zero bf16 buffers ----
    const float4* xin = reinterpret_cast<const float4*>(x + (size_t)n * (NSH * CC));
    float4* xns = reinterpret_cast<float4*>(xn);
    for (int j4 = tid; j4 < NSH * CC / 4; j4 += 512) xns[j4] = xin[j4];
    {   // zero B1 (17408 fl), xnbf (8448 fl), h2 (16640 fl)
        float4* z = reinterpret_cast<float4*>(sm + O_B1HI);
        for (int j = tid; j < 17408 / 4; j += 512) z[j] = make_float4(0, 0, 0, 0);
        z = reinterpret_cast<float4*>(sm + O_XNBFH);
        for (int j = tid; j < 8448 / 4; j += 512) z[j] = make_float4(0, 0, 0, 0);
        z = reinterpret_cast<float4*>(sm + O_H2HI);
        for (int j = tid; j < 16640 / 4; j += 512) z[j] = make_float4(0, 0, 0, 0);
    }
    __syncthreads();

    // ---- norms ----
    float s0 = 0.f, q0 = 0.f, sw = 0.f;
    for (int j4 = tid; j4 < NSH * CC / 4; j4 += 512) {
        float4 v = xns[j4];
        int m = j4 >> 5;
        float d = v.x * v.x + v.y * v.y + v.z * v.z + v.w * v.w;
        if (m == 0) { s0 += v.x + v.y + v.z + v.w; q0 += d; }
        else        sw += c_bal[m] * d;
    }
    #pragma unroll
    for (int o = 16; o > 0; o >>= 1) {
        s0 += __shfl_xor_sync(0xffffffffu, s0, o);
        q0 += __shfl_xor_sync(0xffffffffu, q0, o);
        sw += __shfl_xor_sync(0xffffffffu, sw, o);
    }
    if (lid == 0) { rbuf[wid] = s0; rbuf[16 + wid] = q0; rbuf[32 + wid] = sw; }
    __syncthreads();
    if (tid == 0) {
        float a = 0.f, b = 0.f, c = 0.f;
        #pragma unroll
        for (int k = 0; k < 16; k++) { a += rbuf[k]; b += rbuf[16 + k]; c += rbuf[32 + k]; }
        float muv  = a * (1.0f / CC);
        float varv = b * (1.0f / CC) - muv * muv;
        rbuf[48] = muv;
        rbuf[49] = rsqrtf(varv + EPSV);
        rbuf[50] = rsqrtf(c * (1.0f / CC) + EPSV);
    }
    __syncthreads();
    const float mu = rbuf[48], rstd = rbuf[49], inv = rbuf[50];

    // normalize -> xnbf (bf16 hi/lo, stride 132); keep fp32 row 0 for gate
    for (int j = tid; j < NSH * CC; j += 512) {
        int m = j >> 7, c = j & 127;
        float v = xn[j];
        if (m == 0) {
            v = (v - mu) * rstd * ln0_w[c] + ln0_b[c];
            xn[j] = v;
        } else {
            v *= inv * aff_w[(c_ltab[m] - 1) * CC + c];
        }
        st_split(xnh, xnl, (m * 132 + c) * 2, v);
    }
    __syncthreads();

    // ---- Phase B: gate ----
    {
        const int c4 = lid << 2;
        float4 x0 = *reinterpret_cast<const float4*>(xn + c4);
        for (int ho = wid; ho < HH; ho += 16) {
            float4 g = *reinterpret_cast<const float4*>(gate_w + ho * CC + c4);
            float p = g.x * x0.x + g.y * x0.y + g.z * x0.z + g.w * x0.w;
            #pragma unroll
            for (int o = 16; o > 0; o >>= 1) p += __shfl_xor_sync(0xffffffffu, p, o);
            if (lid == 0) sgate[ho] = fast_silu(p + gate_b[ho]);
        }
    }

    // ---- Phase C: h = xn @ w1^T  (mma; per-l M-tile=16; writes B1 = h^T) ----
    for (int l = 0; l <= 6; l++) {
        const int g = 2 * l + 1, mbase = l * l;
        float acc[2][4] = {{0, 0, 0, 0}, {0, 0, 0, 0}};
        #pragma unroll
        for (int ks = 0; ks < 8; ks++) {
            uint32_t ah[4], al[4];
            ldA(ah, xnh, mbase, ks * 16, r0, tig, 264);
            ldA(al, xnl, mbase, ks * 16, r0, tig, 264);
            #pragma unroll
            for (int t = 0; t < 2; t++) {
                int nt = wid * 2 + t;
                uint2 bh = g_w1f[(size_t)W1F_IDX(0, l, nt, ks) * 32 + lid];
                uint2 bl = g_w1f[(size_t)W1F_IDX(1, l, nt, ks) * 32 + lid];
                mma16816(acc[t], ah, bh.x, bh.y);
                mma16816(acc[t], ah, bl.x, bl.y);
                mma16816(acc[t], al, bh.x, bh.y);
            }
        }
        #pragma unroll
        for (int t = 0; t < 2; t++) {
            int nt = wid * 2 + t;
            int n0 = nt * 8 + 2 * tig;
            float v0 = acc[t][0], v1 = acc[t][1], v2 = acc[t][2], v3 = acc[t][3];
            if (l == 0 && r0 == 0) { v0 += b1[n0]; v1 += b1[n0 + 1]; }
            if (r0 < g) {
                int i = mbase + r0;
                st_split(b1h, b1l, (n0 * 68 + i) * 2, v0);
                st_split(b1h, b1l, ((n0 + 1) * 68 + i) * 2, v1);
            }
            if (r0 + 8 < g) {
                int i = mbase + r0 + 8;
                st_split(b1h, b1l, (n0 * 68 + i) * 2, v2);
                st_split(b1h, b1l, ((n0 + 1) * 68 + i) * 2, v3);
            }
        }
    }

    // ---- Phase D: grid transform (3 chunks of 64 p) ----
    {
        const int mt = wid & 3, ng = wid >> 2;
        float acc2[8][4];
        #pragma unroll
        for (int j = 0; j < 8; j++)
            #pragma unroll
            for (int q = 0; q < 4; q++) acc2[j][q] = 0.f;

        for (int ch = 0; ch < 3; ch++) {
            __syncthreads();   // B1 complete (ch=0) / prev GEMM2 reads of B2 done
            // GEMM1: g[p][c] = T @ h ; epilogue silu -> B2 = g^T [c][p]
            #pragma unroll
            for (int jb = 0; jb < 2; jb++) {
                float acc1[4][4] = {{0,0,0,0},{0,0,0,0},{0,0,0,0},{0,0,0,0}};
                #pragma unroll
                for (int ks = 0; ks < 4; ks++) {
                    uint4 AH = g_a1f[(size_t)A1F_IDX(0, ch, mt, ks) * 32 + lid];
                    uint4 AL = g_a1f[(size_t)A1F_IDX(1, ch, mt, ks) * 32 + lid];
                    uint32_t ah[4] = {AH.x, AH.y, AH.z, AH.w};
                    uint32_t al[4] = {AL.x, AL.y, AL.z, AL.w};
                    #pragma unroll
                    for (int j2 = 0; j2 < 4; j2++) {
                        int nt = ng * 8 + jb * 4 + j2;
                        uint32_t bh[2], bl[2];
                        ldB(bh, b1h, nt * 8, ks * 16, r0, tig, 136);
                        ldB(bl, b1l, nt * 8, ks * 16, r0, tig, 136);
                        mma16816(acc1[j2], ah, bh[0], bh[1]);
                        mma16816(acc1[j2], ah, bl[0], bl[1]);
                        mma16816(acc1[j2], al, bh[0], bh[1]);
                    }
                }
                #pragma unroll
                for (int j2 = 0; j2 < 4; j2++) {
                    int nt = ng * 8 + jb * 4 + j2;
                    int c0 = nt * 8 + 2 * tig;
                    int p0 = mt * 16 + r0;
                    st_split(b2h, b2l, (c0 * 68 + p0) * 2,        fast_silu(acc1[j2][0]));
                    st_split(b2h, b2l, ((c0 + 1) * 68 + p0) * 2,  fast_silu(acc1[j2][1]));
                    st_split(b2h, b2l, (c0 * 68 + p0 + 8) * 2,       fast_silu(acc1[j2][2]));
                    st_split(b2h, b2l, ((c0 + 1) * 68 + p0 + 8) * 2, fast_silu(acc1[j2][3]));
                }
            }
            __syncthreads();   // B2 complete
            // GEMM2: ht[i][c] += F^T @ g
            #pragma unroll
            for (int ks = 0; ks < 4; ks++) {
                uint4 AH = g_a2f[(size_t)A1F_IDX(0, ch, mt, ks) * 32 + lid];
                uint4 AL = g_a2f[(size_t)A1F_IDX(1, ch, mt, ks) * 32 + lid];
                uint32_t ah[4] = {AH.x, AH.y, AH.z, AH.w};
                uint32_t al[4] = {AL.x, AL.y, AL.z, AL.w};
                #pragma unroll
                for (int j = 0; j < 8; j++) {
                    int nt = ng * 8 + j;
                    uint32_t bh[2], bl[2];
                    ldB(bh, b2h, nt * 8, ks * 16, r0, tig, 136);
                    ldB(bl, b2l, nt * 8, ks * 16, r0, tig, 136);
                    mma16816(acc2[j], ah, bh[0], bh[1]);
                    mma16816(acc2[j], ah, bl[0], bl[1]);
                    mma16816(acc2[j], al, bh[0], bh[1]);
                }
            }
        }
        // D epilogue: ht rows 1..48 -> h2 (bf16 hi/lo, stride 260)
        #pragma unroll
        for (int j = 0; j < 8; j++) {
            int nt = ng * 8 + j;
            int c0 = nt * 8 + 2 * tig;
            int i0 = mt * 16 + r0, i1 = i0 + 8;
            if (i0 >= 1 && i0 <= 48) {
                st_split(h2h, h2l, (i0 * 260 + c0) * 2, acc2[j][0]);
                st_split(h2h, h2l, (i0 * 260 + c0 + 1) * 2, acc2[j][1]);
            }
            if (i1 <= 48) {
                st_split(h2h, h2l, (i1 * 260 + c0) * 2, acc2[j][2]);
                st_split(h2h, h2l, (i1 * 260 + c0 + 1) * 2, acc2[j][3]);
            }
        }
        // h2 row 0 = silu(gate)
        for (int c = tid; c < HH; c += 512)
            st_split(h2h, h2l, c * 2, sgate[c]);
        __syncthreads();
    }

    // ---- Phase E: out = h2 @ w2^T (mma; per-l M-tile=16; direct STG) ----
    {
        float* outn = out + (size_t)n * (NSH * CC);
        const int nt = wid;   // 16 n-tiles over N=128
        for (int l = 0; l <= 6; l++) {
            const int g = 2 * l + 1, mbase = l * l;
            float acc[4] = {0, 0, 0, 0};
            #pragma unroll
            for (int ks = 0; ks < 16; ks++) {
                uint32_t ah[4], al[4];
                ldA(ah, h2h, mbase, ks * 16, r0, tig, 520);
                ldA(al, h2l, mbase, ks * 16, r0, tig, 520);
                uint2 bh = g_w2f[(size_t)W2F_IDX(0, l, nt, ks) * 32 + lid];
                uint2 bl = g_w2f[(size_t)W2F_IDX(1, l, nt, ks) * 32 + lid];
                mma16816(acc, ah, bh.x, bh.y);
                mma16816(acc, ah, bl.x, bl.y);
                mma16816(acc, al, bh.x, bh.y);
            }
            int n0 = nt * 8 + 2 * tig;
            float v0 = acc[0], v1 = acc[1];
            if (l == 0 && r0 == 0) { v0 += b2[n0]; v1 += b2[n0 + 1]; }
            if (r0 < g) {
                outn[(mbase + r0) * CC + n0]     = v0;
                outn[(mbase + r0) * CC + n0 + 1] = v1;
            }
            if (r0 + 8 < g) {
                outn[(mbase + r0 + 8) * CC + n0]     = acc[2];
                outn[(mbase + r0 + 8) * CC + n0 + 1] = acc[3];
            }
        }
    }
}

extern "C" void kernel_launch(void* const* d_in, const int* in_sizes, int n_in,
                              void* d_out, int out_size)
{
    const float* x      = (const float*)d_in[0];
    const float* ln0_w  = (const float*)d_in[1];
    const float* ln0_b  = (const float*)d_in[2];
    const float* aff_w  = (const float*)d_in[3];
    const float* w1     = (const float*)d_in[4];
    const float* b1     = (const float*)d_in[5];
    const float* gate_w = (const float*)d_in[6];
    const float* gate_b = (const float*)d_in[7];
    const float* w2     = (const float*)d_in[8];
    const float* b2     = (const float*)d_in[9];
    const float* tg     = (const float*)d_in[10];
    const float* fg     = (const float*)d_in[11];
    float* out = (float*)d_out;

    prep_frags<<<(3680 * 32 + 255) / 256, 256>>>(w1, w2, tg, fg);

    const int n_nodes = in_sizes[0] / (NSH * CC);
    const int smem_bytes = SMEM_FLOATS * (int)sizeof(float);
    cudaFuncSetAttribute(ffn_fused, cudaFuncAttributeMaxDynamicSharedMemorySize, smem_bytes);
    ffn_fused<<<n_nodes, 512, smem_bytes>>>(x, ln0_w, ln0_b, aff_w, b1,
                                            gate_w, gate_b, b2, out);
}

// round 9
// speedup vs baseline: 1.9596x; 1.1313x over previous
#include <cuda_runtime.h>
#include <cuda_bf16.h>
#include <math.h>
#include <cstdint>

#define NSH  49
#define CC   128
#define HH   256
#define EPSV 1e-5f
#define XNS  136     // xnbf row stride (elems) -> 272B, ldsm conflict-free
#define GS   264     // h1/g/h2 row stride (elems) -> 528B, ldsm conflict-free

// ---------------- smem layout (floats) ----------------
// sgate 0..256 | rbuf 256..320
// GREG @320 (16896): phase A-C: xn fp32 @320(6272) | xnbf hi @6592(4352) lo @10944(4352)
//                    phase D:   g [64 p][264 c] bf16 hi @320(8448) lo @8768(8448)
// h1 [64 i][264 c] bf16: hi @17216(8448) lo @25664(8448)
// h2 [64 i][264 c] bf16: hi @34112(8448) lo @42560(8448)
#define O_SGATE 0
#define O_RBUF  256
#define O_XN    320
#define O_XNBFH 6592
#define O_XNBFL 10944
#define O_GHI   320
#define O_GLO   8768
#define O_H1HI  17216
#define O_H1LO  25664
#define O_H2HI  34112
#define O_H2LO  42560
#define SMEM_FLOATS 51008

// fragment-linear global operand banks (filled by prep kernel)
#define W1F_IDX(h,l,nt,ks) (((((h)*7 + (l))*32 + (nt))*8 + (ks)))
#define W2F_IDX(h,l,nt,ks) (((((h)*7 + (l))*16 + (nt))*16 + (ks)))
#define A1F_IDX(h,ch,mt,ks) (((((h)*3 + (ch))*4 + (mt))*4 + (ks)))
__device__ uint2 g_w1f[2*7*32*8*32];
__device__ uint2 g_w2f[2*7*16*16*32];
__device__ uint4 g_a1f[2*3*4*4*32];
__device__ uint4 g_a2f[2*3*4*4*32];

__constant__ int c_ltab[NSH] = {
    0,
    1,1,1,
    2,2,2,2,2,
    3,3,3,3,3,3,3,
    4,4,4,4,4,4,4,4,4,
    5,5,5,5,5,5,5,5,5,5,5,
    6,6,6,6,6,6,6,6,6,6,6,6,6};

__constant__ float c_bal[NSH] = {
    0.0f,
    0.05555555556f,0.05555555556f,0.05555555556f,
    0.03333333333f,0.03333333333f,0.03333333333f,0.03333333333f,0.03333333333f,
    0.02380952381f,0.02380952381f,0.02380952381f,0.02380952381f,0.02380952381f,0.02380952381f,0.02380952381f,
    0.01851851852f,0.01851851852f,0.01851851852f,0.01851851852f,0.01851851852f,0.01851851852f,0.01851851852f,0.01851851852f,0.01851851852f,
    0.01515151515f,0.01515151515f,0.01515151515f,0.01515151515f,0.01515151515f,0.01515151515f,0.01515151515f,0.01515151515f,0.01515151515f,0.01515151515f,0.01515151515f,
    0.01282051282f,0.01282051282f,0.01282051282f,0.01282051282f,0.01282051282f,0.01282051282f,0.01282051282f,0.01282051282f,0.01282051282f,0.01282051282f,0.01282051282f,0.01282051282f,0.01282051282f};

__device__ __forceinline__ float fast_silu(float v) {
    return __fdividef(v, 1.0f + __expf(-v));
}
__device__ __forceinline__ uint16_t bfh(float v) {
    return __bfloat16_as_ushort(__float2bfloat16(v));
}
__device__ __forceinline__ uint16_t bfl(float v) {
    __nv_bfloat16 h = __float2bfloat16(v);
    return __bfloat16_as_ushort(__float2bfloat16(v - __bfloat162float(h)));
}
__device__ __forceinline__ uint32_t pk(uint16_t a, uint16_t b) {
    return (uint32_t)a | ((uint32_t)b << 16);
}
// paired bf16 store: (a,b) -> one STS.32 in hi buf + one in lo buf
__device__ __forceinline__ void st2(char* hi, char* lo, int elem_off, float a, float b) {
    *reinterpret_cast<uint32_t*>(hi + elem_off * 2) = pk(bfh(a), bfh(b));
    *reinterpret_cast<uint32_t*>(lo + elem_off * 2) = pk(bfl(a), bfl(b));
}
__device__ __forceinline__ uint32_t smem_u32(const void* p) {
    uint32_t a;
    asm("{ .reg .u64 t; cvta.to.shared.u64 t, %1; cvt.u32.u64 %0, t; }" : "=r"(a) : "l"(p));
    return a;
}
__device__ __forceinline__ void mma16816(float* d, const uint32_t* a,
                                         uint32_t b0, uint32_t b1) {
    asm volatile(
        "mma.sync.aligned.m16n8k16.row.col.f32.bf16.bf16.f32 "
        "{%0,%1,%2,%3}, {%4,%5,%6,%7}, {%8,%9}, {%0,%1,%2,%3};\n"
        : "+f"(d[0]), "+f"(d[1]), "+f"(d[2]), "+f"(d[3])
        : "r"(a[0]), "r"(a[1]), "r"(a[2]), "r"(a[3]), "r"(b0), "r"(b1));
}
__device__ __forceinline__ void ldsm4(uint32_t* f, uint32_t a) {
    asm volatile("ldmatrix.sync.aligned.m8n8.x4.shared.b16 {%0,%1,%2,%3}, [%4];"
        : "=r"(f[0]), "=r"(f[1]), "=r"(f[2]), "=r"(f[3]) : "r"(a));
}
__device__ __forceinline__ void ldsm4t(uint32_t* f, uint32_t a) {
    asm volatile("ldmatrix.sync.aligned.m8n8.x4.trans.shared.b16 {%0,%1,%2,%3}, [%4];"
        : "=r"(f[0]), "=r"(f[1]), "=r"(f[2]), "=r"(f[3]) : "r"(a));
}
// per-lane byte offset for a 16x16 frag at (r_base, c_base), row stride strideB bytes.
// A (non-trans): r=m, c=k -> {a0,a1,a2,a3}. B (trans): r=k, c=n -> {b0,b1} x 2 n-tiles.
__device__ __forceinline__ uint32_t frag_off(int r_base, int c_base, int strideB, int lane) {
    int q = lane >> 3;
    return (uint32_t)((r_base + (lane & 7) + ((q & 1) << 3)) * strideB
                      + ((c_base + ((q >> 1) << 3)) << 1));
}

// ---------------- prep kernel (identical format to R8) ----------------
__global__ void prep_frags(const float* __restrict__ w1, const float* __restrict__ w2,
                           const float* __restrict__ tg, const float* __restrict__ fg)
{
    int t = blockIdx.x * 256 + threadIdx.x;
    if (t >= 3680 * 32) return;
    int lane = t & 31;
    int r0 = lane >> 2, tig = lane & 3;
    int fi = t >> 5;

    if (fi < 1792) {
        int ks = fi & 7, nt = (fi >> 3) & 31, l = fi >> 8;
        int n = nt * 8 + r0, k = ks * 16 + 2 * tig;
        const float* s = w1 + ((size_t)l * HH + n) * CC + k;
        float v0 = s[0], v1 = s[1], v8 = s[8], v9 = s[9];
        g_w1f[(size_t)W1F_IDX(0, l, nt, ks) * 32 + lane] =
            make_uint2(pk(bfh(v0), bfh(v1)), pk(bfh(v8), bfh(v9)));
        g_w1f[(size_t)W1F_IDX(1, l, nt, ks) * 32 + lane] =
            make_uint2(pk(bfl(v0), bfl(v1)), pk(bfl(v8), bfl(v9)));
    } else if (fi < 3584) {
        int fj = fi - 1792;
        int ks = fj & 15, nt = (fj >> 4) & 15, l = fj >> 8;
        int n = nt * 8 + r0, k = ks * 16 + 2 * tig;
        const float* s = w2 + ((size_t)l * CC + n) * HH + k;
        float v0 = s[0], v1 = s[1], v8 = s[8], v9 = s[9];
        g_w2f[(size_t)W2F_IDX(0, l, nt, ks) * 32 + lane] =
            make_uint2(pk(bfh(v0), bfh(v1)), pk(bfh(v8), bfh(v9)));
        g_w2f[(size_t)W2F_IDX(1, l, nt, ks) * 32 + lane] =
            make_uint2(pk(bfl(v0), bfl(v1)), pk(bfl(v8), bfl(v9)));
    } else if (fi < 3632) {
        int fk = fi - 3584;
        int ks = fk & 3, mt = (fk >> 2) & 3, ch = fk >> 4;
        int pa = ch * 64 + mt * 16 + r0, pb = pa + 8;
        int ia = ks * 16 + 2 * tig;
        auto val = [&](int p, int i) -> float {
            return (p < 182 && i < NSH) ? tg[p * NSH + i] : 0.f;
        };
        float xa0 = val(pa, ia), xa1 = val(pa, ia + 1);
        float ya0 = val(pb, ia), ya1 = val(pb, ia + 1);
        float za0 = val(pa, ia + 8), za1 = val(pa, ia + 9);
        float wa0 = val(pb, ia + 8), wa1 = val(pb, ia + 9);
        g_a1f[(size_t)A1F_IDX(0, ch, mt, ks) * 32 + lane] =
            make_uint4(pk(bfh(xa0), bfh(xa1)), pk(bfh(ya0), bfh(ya1)),
                       pk(bfh(za0), bfh(za1)), pk(bfh(wa0), bfh(wa1)));
        g_a1f[(size_t)A1F_IDX(1, ch, mt, ks) * 32 + lane] =
            make_uint4(pk(bfl(xa0), bfl(xa1)), pk(bfl(ya0), bfl(ya1)),
                       pk(bfl(za0), bfl(za1)), pk(bfl(wa0), bfl(wa1)));
    } else {
        int fk = fi - 3632;
        int ks = fk & 3, mt = (fk >> 2) & 3, ch = fk >> 4;
        int ia = mt * 16 + r0, ib = ia + 8;
        int p0 = ch * 64 + ks * 16 + 2 * tig;
        auto val = [&](int i, int p) -> float {
            return (p < 182 && i < NSH) ? fg[p * NSH + i] : 0.f;
        };
        float xa0 = val(ia, p0), xa1 = val(ia, p0 + 1);
        float ya0 = val(ib, p0), ya1 = val(ib, p0 + 1);
        float za0 = val(ia, p0 + 8), za1 = val(ia, p0 + 9);
        float wa0 = val(ib, p0 + 8), wa1 = val(ib, p0 + 9);
        g_a2f[(size_t)A1F_IDX(0, ch, mt, ks) * 32 + lane] =
            make_uint4(pk(bfh(xa0), bfh(xa1)), pk(bfh(ya0), bfh(ya1)),
                       pk(bfh(za0), bfh(za1)), pk(bfh(wa0), bfh(wa1)));
        g_a2f[(size_t)A1F_IDX(1, ch, mt, ks) * 32 + lane] =
            make_uint4(pk(bfl(xa0), bfl(xa1)), pk(bfl(ya0), bfl(ya1)),
                       pk(bfl(za0), bfl(za1)), pk(bfl(wa0), bfl(wa1)));
    }
}

// ---------------- main kernel ----------------
__global__ void __launch_bounds__(512, 1)
ffn_fused(const float* __restrict__ x,
          const float* __restrict__ ln0_w, const float* __restrict__ ln0_b,
          const float* __restrict__ aff_w,
          const float* __restrict__ b1,
          const float* __restrict__ gate_w, const float* __restrict__ gate_b,
          const float* __restrict__ b2,
          float* __restrict__ out)
{
    extern __shared__ float sm[];
    float* sgate = sm + O_SGATE;
    float* rbuf  = sm + O_RBUF;
    float* xn    = sm + O_XN;

    char* xnh = reinterpret_cast<char*>(sm + O_XNBFH);
    char* xnl = reinterpret_cast<char*>(sm + O_XNBFL);
    char* ghi = reinterpret_cast<char*>(sm + O_GHI);
    char* glo = reinterpret_cast<char*>(sm + O_GLO);
    char* h1h = reinterpret_cast<char*>(sm + O_H1HI);
    char* h1l = reinterpret_cast<char*>(sm + O_H1LO);
    char* h2h = reinterpret_cast<char*>(sm + O_H2HI);
    char* h2l = reinterpret_cast<char*>(sm + O_H2LO);

    const uint32_t u0     = smem_u32(sm);
    const uint32_t u_xnh  = u0 + O_XNBFH * 4, u_xnl = u0 + O_XNBFL * 4;
    const uint32_t u_ghi  = u0 + O_GHI * 4,   u_glo = u0 + O_GLO * 4;
    const uint32_t u_h1h  = u0 + O_H1HI * 4,  u_h1l = u0 + O_H1LO * 4;
    const uint32_t u_h2h  = u0 + O_H2HI * 4,  u_h2l = u0 + O_H2LO * 4;

    const int tid = threadIdx.x;
    const int n   = blockIdx.x;
    const int wid = tid >> 5;
    const int lid = tid & 31;
    const int r0  = lid >> 2;
    const int tig = lid & 3;

    // ---- Phase A: load x; zero h1 (K-side of D-GEMM1 must be clean) ----
    const float4* xin = reinterpret_cast<const float4*>(x + (size_t)n * (NSH * CC));
    float4* xns = reinterpret_cast<float4*>(xn);
    for (int j4 = tid; j4 < NSH * CC / 4; j4 += 512) xns[j4] = xin[j4];
    {
        float4* z = reinterpret_cast<float4*>(sm + O_H1HI);
        for (int j = tid; j < 16896 / 4; j += 512) z[j] = make_float4(0, 0, 0, 0);
    }
    __syncthreads();

    // ---- norms ----
    float s0 = 0.f, q0 = 0.f, sw = 0.f;
    for (int j4 = tid; j4 < NSH * CC / 4; j4 += 512) {
        float4 v = xns[j4];
        int m = j4 >> 5;
        float d = v.x * v.x + v.y * v.y + v.z * v.z + v.w * v.w;
        if (m == 0) { s0 += v.x + v.y + v.z + v.w; q0 += d; }
        else        sw += c_bal[m] * d;
    }
    #pragma unroll
    for (int o = 16; o > 0; o >>= 1) {
        s0 += __shfl_xor_sync(0xffffffffu, s0, o);
        q0 += __shfl_xor_sync(0xffffffffu, q0, o);
        sw += __shfl_xor_sync(0xffffffffu, sw, o);
    }
    if (lid == 0) { rbuf[wid] = s0; rbuf[16 + wid] = q0; rbuf[32 + wid] = sw; }
    __syncthreads();
    if (tid == 0) {
        float a = 0.f, b = 0.f, c = 0.f;
        #pragma unroll
        for (int k = 0; k < 16; k++) { a += rbuf[k]; b += rbuf[16 + k]; c += rbuf[32 + k]; }
        float muv  = a * (1.0f / CC);
        float varv = b * (1.0f / CC) - muv * muv;
        rbuf[48] = muv;
        rbuf[49] = rsqrtf(varv + EPSV);
        rbuf[50] = rsqrtf(c * (1.0f / CC) + EPSV);
    }
    __syncthreads();
    const float mu = rbuf[48], rstd = rbuf[49], inv = rbuf[50];

    // normalize (paired) -> xnbf; keep fp32 row0 in xn for gate
    for (int j2 = tid; j2 < NSH * 64; j2 += 512) {
        int m = j2 >> 6, c2 = (j2 & 63) << 1;
        float v0 = xn[m * CC + c2], v1 = xn[m * CC + c2 + 1];
        if (m == 0) {
            v0 = (v0 - mu) * rstd * ln0_w[c2] + ln0_b[c2];
            v1 = (v1 - mu) * rstd * ln0_w[c2 + 1] + ln0_b[c2 + 1];
            xn[c2] = v0; xn[c2 + 1] = v1;
        } else {
            const float* aw = aff_w + (c_ltab[m] - 1) * CC;
            v0 *= inv * aw[c2]; v1 *= inv * aw[c2 + 1];
        }
        st2(xnh, xnl, m * XNS + c2, v0, v1);
    }
    __syncthreads();

    // ---- Phase C (warps 0-13) + gate (warps 14-15), concurrent ----
    if (wid < 14) {
        const int l = wid >> 1, nh = wid & 1;
        const int g = 2 * l + 1, mbase = l * l;
        for (int jb = 0; jb < 2; jb++) {
            float acc[8][4];
            #pragma unroll
            for (int j = 0; j < 8; j++)
                #pragma unroll
                for (int q = 0; q < 4; q++) acc[j][q] = 0.f;
            #pragma unroll
            for (int ks = 0; ks < 8; ks++) {
                uint32_t ah[4], al[4];
                uint32_t fo = frag_off(mbase, ks * 16, XNS * 2, lid);
                ldsm4(ah, u_xnh + fo);
                ldsm4(al, u_xnl + fo);
                #pragma unroll
                for (int j = 0; j < 8; j++) {
                    int nt = nh * 16 + jb * 8 + j;
                    uint2 bh = g_w1f[(size_t)W1F_IDX(0, l, nt, ks) * 32 + lid];
                    uint2 bl = g_w1f[(size_t)W1F_IDX(1, l, nt, ks) * 32 + lid];
                    mma16816(acc[j], ah, bh.x, bh.y);
                    mma16816(acc[j], ah, bl.x, bl.y);
                    mma16816(acc[j], al, bh.x, bh.y);
                }
            }
            #pragma unroll
            for (int j = 0; j < 8; j++) {
                int nt = nh * 16 + jb * 8 + j;
                int n0 = nt * 8 + 2 * tig;
                float v0 = acc[j][0], v1 = acc[j][1];
                if (l == 0 && r0 == 0) { v0 += b1[n0]; v1 += b1[n0 + 1]; }
                if (r0 < g)
                    st2(h1h, h1l, (mbase + r0) * GS + n0, v0, v1);
                if (r0 + 8 < g)
                    st2(h1h, h1l, (mbase + r0 + 8) * GS + n0, acc[j][2], acc[j][3]);
            }
        }
    } else {
        const int gw = wid - 14;
        const int c4 = lid << 2;
        float4 x0 = *reinterpret_cast<const float4*>(xn + c4);
        for (int ho = gw * 128; ho < gw * 128 + 128; ho++) {
            float4 g = *reinterpret_cast<const float4*>(gate_w + ho * CC + c4);
            float p = g.x * x0.x + g.y * x0.y + g.z * x0.z + g.w * x0.w;
            #pragma unroll
            for (int o = 16; o > 0; o >>= 1) p += __shfl_xor_sync(0xffffffffu, p, o);
            if (lid == 0) sgate[ho] = fast_silu(p + gate_b[ho]);
        }
    }

    // ---- Phase D: grid transform (16 warps = 4 mt x 4 ng) ----
    {
        const int mt = wid & 3, ng = wid >> 2;
        float acc2[8][4];
        #pragma unroll
        for (int j = 0; j < 8; j++)
            #pragma unroll
            for (int q = 0; q < 4; q++) acc2[j][q] = 0.f;

        for (int ch = 0; ch < 3; ch++) {
            __syncthreads();   // h1/sgate ready (ch=0); prev G2 reads of g done
            // GEMM1: g[p][c] = T @ h1
            float acc1[8][4];
            #pragma unroll
            for (int j = 0; j < 8; j++)
                #pragma unroll
                for (int q = 0; q < 4; q++) acc1[j][q] = 0.f;
            #pragma unroll
            for (int ks = 0; ks < 4; ks++) {
                uint4 AH = g_a1f[(size_t)A1F_IDX(0, ch, mt, ks) * 32 + lid];
                uint4 AL = g_a1f[(size_t)A1F_IDX(1, ch, mt, ks) * 32 + lid];
                uint32_t ah[4] = {AH.x, AH.y, AH.z, AH.w};
                uint32_t al[4] = {AL.x, AL.y, AL.z, AL.w};
                #pragma unroll
                for (int jp = 0; jp < 4; jp++) {
                    uint32_t bh[4], bl[4];
                    uint32_t fo = frag_off(ks * 16, ng * 64 + jp * 16, GS * 2, lid);
                    ldsm4t(bh, u_h1h + fo);
                    ldsm4t(bl, u_h1l + fo);
                    mma16816(acc1[2 * jp], ah, bh[0], bh[1]);
                    mma16816(acc1[2 * jp], ah, bl[0], bl[1]);
                    mma16816(acc1[2 * jp], al, bh[0], bh[1]);
                    mma16816(acc1[2 * jp + 1], ah, bh[2], bh[3]);
                    mma16816(acc1[2 * jp + 1], ah, bl[2], bl[3]);
                    mma16816(acc1[2 * jp + 1], al, bh[2], bh[3]);
                }
            }
            __syncthreads();   // all G1 reads of g-region predecessors done before overwrite
            // epilogue: silu -> g[p][c]
            #pragma unroll
            for (int j = 0; j < 8; j++) {
                int c0 = ng * 64 + j * 8 + 2 * tig;
                int p0 = mt * 16 + r0;
                st2(ghi, glo, p0 * GS + c0, fast_silu(acc1[j][0]), fast_silu(acc1[j][1]));
                st2(ghi, glo, (p0 + 8) * GS + c0, fast_silu(acc1[j][2]), fast_silu(acc1[j][3]));
            }
            __syncthreads();   // g complete
            // GEMM2: ht[i][c] += F^T @ g
            #pragma unroll
            for (int ks = 0; ks < 4; ks++) {
                uint4 AH = g_a2f[(size_t)A1F_IDX(0, ch, mt, ks) * 32 + lid];
                uint4 AL = g_a2f[(size_t)A1F_IDX(1, ch, mt, ks) * 32 + lid];
                uint32_t ah[4] = {AH.x, AH.y, AH.z, AH.w};
                uint32_t al[4] = {AL.x, AL.y, AL.z, AL.w};
                #pragma unroll
                for (int jp = 0; jp < 4; jp++) {
                    uint32_t bh[4], bl[4];
                    uint32_t fo = frag_off(ks * 16, ng * 64 + jp * 16, GS * 2, lid);
                    ldsm4t(bh, u_ghi + fo);
                    ldsm4t(bl, u_glo + fo);
                    mma16816(acc2[2 * jp], ah, bh[0], bh[1]);
                    mma16816(acc2[2 * jp], ah, bl[0], bl[1]);
                    mma16816(acc2[2 * jp], al, bh[0], bh[1]);
                    mma16816(acc2[2 * jp + 1], ah, bh[2], bh[3]);
                    mma16816(acc2[2 * jp + 1], ah, bl[2], bl[3]);
                    mma16816(acc2[2 * jp + 1], al, bh[2], bh[3]);
                }
            }
        }
        // D epilogue: ht rows 1..48 -> h2; row 0 = silu(gate)
        #pragma unroll
        for (int j = 0; j < 8; j++) {
            int c0 = ng * 64 + j * 8 + 2 * tig;
            int i0 = mt * 16 + r0, i1 = i0 + 8;
            if (i0 >= 1 && i0 <= 48)
                st2(h2h, h2l, i0 * GS + c0, acc2[j][0], acc2[j][1]);
            if (i1 <= 48)
                st2(h2h, h2l, i1 * GS + c0, acc2[j][2], acc2[j][3]);
        }
        for (int c2 = tid; c2 < 128; c2 += 512)
            st2(h2h, h2l, 2 * c2, sgate[2 * c2], sgate[2 * c2 + 1]);
        __syncthreads();
    }

    // ---- Phase E: out = h2 @ w2^T (warps 0-13, 2 per l) ----
    if (wid < 14) {
        float* outn = out + (size_t)n * (NSH * CC);
        const int l = wid >> 1, nh = wid & 1;
        const int g = 2 * l + 1, mbase = l * l;
        float acc[8][4];
        #pragma unroll
        for (int j = 0; j < 8; j++)
            #pragma unroll
            for (int q = 0; q < 4; q++) acc[j][q] = 0.f;
        #pragma unroll 4
        for (int ks = 0; ks < 16; ks++) {
            uint32_t ah[4], al[4];
            uint32_t fo = frag_off(mbase, ks * 16, GS * 2, lid);
            ldsm4(ah, u_h2h + fo);
            ldsm4(al, u_h2l + fo);
            #pragma unroll
            for (int j = 0; j < 8; j++) {
                int nt = nh * 8 + j;
                uint2 bh = g_w2f[(size_t)W2F_IDX(0, l, nt, ks) * 32 + lid];
                uint2 bl = g_w2f[(size_t)W2F_IDX(1, l, nt, ks) * 32 + lid];
                mma16816(acc[j], ah, bh.x, bh.y);
                mma16816(acc[j], ah, bl.x, bl.y);
                mma16816(acc[j], al, bh.x, bh.y);
            }
        }
        #pragma unroll
        for (int j = 0; j < 8; j++) {
            int nt = nh * 8 + j;
            int n0 = nt * 8 + 2 * tig;
            float v0 = acc[j][0], v1 = acc[j][1];
            if (l == 0 && r0 == 0) { v0 += b2[n0]; v1 += b2[n0 + 1]; }
            if (r0 < g)
                *reinterpret_cast<float2*>(outn + (mbase + r0) * CC + n0) =
                    make_float2(v0, v1);
            if (r0 + 8 < g)
                *reinterpret_cast<float2*>(outn + (mbase + r0 + 8) * CC + n0) =
                    make_float2(acc[j][2], acc[j][3]);
        }
    }
}

extern "C" void kernel_launch(void* const* d_in, const int* in_sizes, int n_in,
                              void* d_out, int out_size)
{
    const float* x      = (const float*)d_in[0];
    const float* ln0_w  = (const float*)d_in[1];
    const float* ln0_b  = (const float*)d_in[2];
    const float* aff_w  = (const float*)d_in[3];
    const float* w1     = (const float*)d_in[4];
    const float* b1     = (const float*)d_in[5];
    const float* gate_w = (const float*)d_in[6];
    const float* gate_b = (const float*)d_in[7];
    const float* w2     = (const float*)d_in[8];
    const float* b2     = (const float*)d_in[9];
    const float* tg     = (const float*)d_in[10];
    const float* fg     = (const float*)d_in[11];
    float* out = (float*)d_out;

    prep_frags<<<(3680 * 32 + 255) / 256, 256>>>(w1, w2, tg, fg);

    const int n_nodes = in_sizes[0] / (NSH * CC);
    const int smem_bytes = SMEM_FLOATS * (int)sizeof(float);
    cudaFuncSetAttribute(ffn_fused, cudaFuncAttributeMaxDynamicSharedMemorySize, smem_bytes);
    ffn_fused<<<n_nodes, 512, smem_bytes>>>(x, ln0_w, ln0_b, aff_w, b1,
                                            gate_w, gate_b, b2, out);
}

// round 10
// speedup vs baseline: 2.5309x; 1.2915x over previous
#include <cuda_runtime.h>
#include <cuda_bf16.h>
#include <math.h>
#include <cstdint>

#define NSH  49
#define CC   128
#define HH   256
#define EPSV 1e-5f
#define XNS  136     // xnbf row stride (elems) -> 272B, ldsm conflict-free
#define GS   264     // h1/g/h2 row stride (elems) -> 528B, ldsm conflict-free

// ---------------- smem layout (floats) ----------------
// rbuf 0..64
// GREG @64 (16896): phase A-C: xn fp32 @64(6272) | xnbf hi @6336(4352) lo @10688(4352)
//                   phase D:   g [64 p][264 c] bf16 hi @64(8448) lo @8512(8448)
// h1 [64 i][264 c] bf16: hi @16960(8448) lo @25408(8448)
// h2 [64 i][264 c] bf16: hi @33856(8448) lo @42304(8448)
#define O_RBUF  0
#define O_XN    64
#define O_XNBFH 6336
#define O_XNBFL 10688
#define O_GHI   64
#define O_GLO   8512
#define O_H1HI  16960
#define O_H1LO  25408
#define O_H2HI  33856
#define O_H2LO  42304
#define SMEM_FLOATS 50752

// fragment-linear global operand banks. w1/w2: hi/lo merged in one uint4
// {bh.x, bh.y, bl.x, bl.y}. l=7 of w1 bank is gate_w.
#define W1F_IDX(l,nt,ks)  (((l)*32 + (nt))*8 + (ks))
#define W2F_IDX(l,nt,ks)  (((l)*16 + (nt))*16 + (ks))
#define A1F_IDX(h,ch,mt,ks) (((((h)*3 + (ch))*4 + (mt))*4 + (ks)))
__device__ uint4 g_w1f[2048*32];
__device__ uint4 g_w2f[1792*32];
__device__ uint4 g_a1f[2*48*32];
__device__ uint4 g_a2f[2*48*32];

__constant__ int c_ltab[NSH] = {
    0,
    1,1,1,
    2,2,2,2,2,
    3,3,3,3,3,3,3,
    4,4,4,4,4,4,4,4,4,
    5,5,5,5,5,5,5,5,5,5,5,
    6,6,6,6,6,6,6,6,6,6,6,6,6};

__constant__ float c_bal[NSH] = {
    0.0f,
    0.05555555556f,0.05555555556f,0.05555555556f,
    0.03333333333f,0.03333333333f,0.03333333333f,0.03333333333f,0.03333333333f,
    0.02380952381f,0.02380952381f,0.02380952381f,0.02380952381f,0.02380952381f,0.02380952381f,0.02380952381f,
    0.01851851852f,0.01851851852f,0.01851851852f,0.01851851852f,0.01851851852f,0.01851851852f,0.01851851852f,0.01851851852f,0.01851851852f,
    0.01515151515f,0.01515151515f,0.01515151515f,0.01515151515f,0.01515151515f,0.01515151515f,0.01515151515f,0.01515151515f,0.01515151515f,0.01515151515f,0.01515151515f,
    0.01282051282f,0.01282051282f,0.01282051282f,0.01282051282f,0.01282051282f,0.01282051282f,0.01282051282f,0.01282051282f,0.01282051282f,0.01282051282f,0.01282051282f,0.01282051282f,0.01282051282f};

__device__ __forceinline__ float fast_silu(float v) {
    return __fdividef(v, 1.0f + __expf(-v));
}
__device__ __forceinline__ uint16_t bfh(float v) {
    return __bfloat16_as_ushort(__float2bfloat16(v));
}
__device__ __forceinline__ uint16_t bfl(float v) {
    __nv_bfloat16 h = __float2bfloat16(v);
    return __bfloat16_as_ushort(__float2bfloat16(v - __bfloat162float(h)));
}
__device__ __forceinline__ uint32_t pk(uint16_t a, uint16_t b) {
    return (uint32_t)a | ((uint32_t)b << 16);
}
__device__ __forceinline__ void st2(char* hi, char* lo, int elem_off, float a, float b) {
    *reinterpret_cast<uint32_t*>(hi + elem_off * 2) = pk(bfh(a), bfh(b));
    *reinterpret_cast<uint32_t*>(lo + elem_off * 2) = pk(bfl(a), bfl(b));
}
__device__ __forceinline__ uint32_t smem_u32(const void* p) {
    uint32_t a;
    asm("{ .reg .u64 t; cvta.to.shared.u64 t, %1; cvt.u32.u64 %0, t; }" : "=r"(a) : "l"(p));
    return a;
}
__device__ __forceinline__ void mma16816(float* d, const uint32_t* a,
                                         uint32_t b0, uint32_t b1) {
    asm volatile(
        "mma.sync.aligned.m16n8k16.row.col.f32.bf16.bf16.f32 "
        "{%0,%1,%2,%3}, {%4,%5,%6,%7}, {%8,%9}, {%0,%1,%2,%3};\n"
        : "+f"(d[0]), "+f"(d[1]), "+f"(d[2]), "+f"(d[3])
        : "r"(a[0]), "r"(a[1]), "r"(a[2]), "r"(a[3]), "r"(b0), "r"(b1));
}
__device__ __forceinline__ void ldsm4(uint32_t* f, uint32_t a) {
    asm volatile("ldmatrix.sync.aligned.m8n8.x4.shared.b16 {%0,%1,%2,%3}, [%4];"
        : "=r"(f[0]), "=r"(f[1]), "=r"(f[2]), "=r"(f[3]) : "r"(a));
}
__device__ __forceinline__ void ldsm4t(uint32_t* f, uint32_t a) {
    asm volatile("ldmatrix.sync.aligned.m8n8.x4.trans.shared.b16 {%0,%1,%2,%3}, [%4];"
        : "=r"(f[0]), "=r"(f[1]), "=r"(f[2]), "=r"(f[3]) : "r"(a));
}
__device__ __forceinline__ uint32_t frag_off(int r_base, int c_base, int strideB, int lane) {
    int q = lane >> 3;
    return (uint32_t)((r_base + (lane & 7) + ((q & 1) << 3)) * strideB
                      + ((c_base + ((q >> 1) << 3)) << 1));
}

// ---------------- prep kernel ----------------
__global__ void prep_frags(const float* __restrict__ w1, const float* __restrict__ w2,
                           const float* __restrict__ tg, const float* __restrict__ fg,
                           const float* __restrict__ gate_w)
{
    int t = blockIdx.x * 256 + threadIdx.x;
    if (t >= 3936 * 32) return;
    int lane = t & 31;
    int r0 = lane >> 2, tig = lane & 3;
    int fi = t >> 5;

    if (fi < 2048) {                       // w1 (l 0..6) + gate_w (l=7)
        int ks = fi & 7, nt = (fi >> 3) & 31, l = fi >> 8;
        int n = nt * 8 + r0, k = ks * 16 + 2 * tig;
        const float* s = (l < 7) ? (w1 + ((size_t)l * HH + n) * CC + k)
                                 : (gate_w + (size_t)n * CC + k);
        float v0 = s[0], v1 = s[1], v8 = s[8], v9 = s[9];
        g_w1f[(size_t)W1F_IDX(l, nt, ks) * 32 + lane] =
            make_uint4(pk(bfh(v0), bfh(v1)), pk(bfh(v8), bfh(v9)),
                       pk(bfl(v0), bfl(v1)), pk(bfl(v8), bfl(v9)));
    } else if (fi < 3840) {                // w2
        int fj = fi - 2048;
        int ks = fj & 15, nt = (fj >> 4) & 15, l = fj >> 8;
        int n = nt * 8 + r0, k = ks * 16 + 2 * tig;
        const float* s = w2 + ((size_t)l * CC + n) * HH + k;
        float v0 = s[0], v1 = s[1], v8 = s[8], v9 = s[9];
        g_w2f[(size_t)W2F_IDX(l, nt, ks) * 32 + lane] =
            make_uint4(pk(bfh(v0), bfh(v1)), pk(bfh(v8), bfh(v9)),
                       pk(bfl(v0), bfl(v1)), pk(bfl(v8), bfl(v9)));
    } else if (fi < 3888) {                // a1 = to_grid [p][i]
        int fk = fi - 3840;
        int ks = fk & 3, mt = (fk >> 2) & 3, ch = fk >> 4;
        int pa = ch * 64 + mt * 16 + r0, pb = pa + 8;
        int ia = ks * 16 + 2 * tig;
        auto val = [&](int p, int i) -> float {
            return (p < 182 && i < NSH) ? tg[p * NSH + i] : 0.f;
        };
        float xa0 = val(pa, ia), xa1 = val(pa, ia + 1);
        float ya0 = val(pb, ia), ya1 = val(pb, ia + 1);
        float za0 = val(pa, ia + 8), za1 = val(pa, ia + 9);
        float wa0 = val(pb, ia + 8), wa1 = val(pb, ia + 9);
        g_a1f[(size_t)A1F_IDX(0, ch, mt, ks) * 32 + lane] =
            make_uint4(pk(bfh(xa0), bfh(xa1)), pk(bfh(ya0), bfh(ya1)),
                       pk(bfh(za0), bfh(za1)), pk(bfh(wa0), bfh(wa1)));
        g_a1f[(size_t)A1F_IDX(1, ch, mt, ks) * 32 + lane] =
            make_uint4(pk(bfl(xa0), bfl(xa1)), pk(bfl(ya0), bfl(ya1)),
                       pk(bfl(za0), bfl(za1)), pk(bfl(wa0), bfl(wa1)));
    } else {                               // a2 = from_grid^T [i][p]
        int fk = fi - 3888;
        int ks = fk & 3, mt = (fk >> 2) & 3, ch = fk >> 4;
        int ia = mt * 16 + r0, ib = ia + 8;
        int p0 = ch * 64 + ks * 16 + 2 * tig;
        auto val = [&](int i, int p) -> float {
            return (p < 182 && i < NSH) ? fg[p * NSH + i] : 0.f;
        };
        float xa0 = val(ia, p0), xa1 = val(ia, p0 + 1);
        float ya0 = val(ib, p0), ya1 = val(ib, p0 + 1);
        float za0 = val(ia, p0 + 8), za1 = val(ia, p0 + 9);
        float wa0 = val(ib, p0 + 8), wa1 = val(ib, p0 + 9);
        g_a2f[(size_t)A1F_IDX(0, ch, mt, ks) * 32 + lane] =
            make_uint4(pk(bfh(xa0), bfh(xa1)), pk(bfh(ya0), bfh(ya1)),
                       pk(bfh(za0), bfh(za1)), pk(bfh(wa0), bfh(wa1)));
        g_a2f[(size_t)A1F_IDX(1, ch, mt, ks) * 32 + lane] =
            make_uint4(pk(bfl(xa0), bfl(xa1)), pk(bfl(ya0), bfl(ya1)),
                       pk(bfl(za0), bfl(za1)), pk(bfl(wa0), bfl(wa1)));
    }
}

// ---------------- main kernel ----------------
__global__ void __launch_bounds__(512, 1)
ffn_fused(const float* __restrict__ x,
          const float* __restrict__ ln0_w, const float* __restrict__ ln0_b,
          const float* __restrict__ aff_w,
          const float* __restrict__ b1,
          const float* __restrict__ gate_b,
          const float* __restrict__ b2,
          float* __restrict__ out)
{
    extern __shared__ float sm[];
    float* rbuf = sm + O_RBUF;
    float* xn   = sm + O_XN;

    char* xnh = reinterpret_cast<char*>(sm + O_XNBFH);
    char* xnl = reinterpret_cast<char*>(sm + O_XNBFL);
    char* ghi = reinterpret_cast<char*>(sm + O_GHI);
    char* glo = reinterpret_cast<char*>(sm + O_GLO);
    char* h1h = reinterpret_cast<char*>(sm + O_H1HI);
    char* h1l = reinterpret_cast<char*>(sm + O_H1LO);
    char* h2h = reinterpret_cast<char*>(sm + O_H2HI);
    char* h2l = reinterpret_cast<char*>(sm + O_H2LO);

    const uint32_t u0    = smem_u32(sm);
    const uint32_t u_xnh = u0 + O_XNBFH * 4, u_xnl = u0 + O_XNBFL * 4;
    const uint32_t u_ghi = u0 + O_GHI * 4,   u_glo = u0 + O_GLO * 4;
    const uint32_t u_h1h = u0 + O_H1HI * 4,  u_h1l = u0 + O_H1LO * 4;
    const uint32_t u_h2h = u0 + O_H2HI * 4,  u_h2l = u0 + O_H2LO * 4;

    const int tid = threadIdx.x;
    const int n   = blockIdx.x;
    const int wid = tid >> 5;
    const int lid = tid & 31;
    const int r0  = lid >> 2;
    const int tig = lid & 3;

    // ---- Phase A: load x; zero h1 (K-side of D-GEMM1 must be clean) ----
    const float4* xin = reinterpret_cast<const float4*>(x + (size_t)n * (NSH * CC));
    float4* xns = reinterpret_cast<float4*>(xn);
    for (int j4 = tid; j4 < NSH * CC / 4; j4 += 512) xns[j4] = xin[j4];
    {
        float4* z = reinterpret_cast<float4*>(sm + O_H1HI);
        for (int j = tid; j < 16896 / 4; j += 512) z[j] = make_float4(0, 0, 0, 0);
    }
    __syncthreads();

    // ---- norms ----
    float s0 = 0.f, q0 = 0.f, sw = 0.f;
    for (int j4 = tid; j4 < NSH * CC / 4; j4 += 512) {
        float4 v = xns[j4];
        int m = j4 >> 5;
        float d = v.x * v.x + v.y * v.y + v.z * v.z + v.w * v.w;
        if (m == 0) { s0 += v.x + v.y + v.z + v.w; q0 += d; }
        else        sw += c_bal[m] * d;
    }
    #pragma unroll
    for (int o = 16; o > 0; o >>= 1) {
        s0 += __shfl_xor_sync(0xffffffffu, s0, o);
        q0 += __shfl_xor_sync(0xffffffffu, q0, o);
        sw += __shfl_xor_sync(0xffffffffu, sw, o);
    }
    if (lid == 0) { rbuf[wid] = s0; rbuf[16 + wid] = q0; rbuf[32 + wid] = sw; }
    __syncthreads();
    if (tid == 0) {
        float a = 0.f, b = 0.f, c = 0.f;
        #pragma unroll
        for (int k = 0; k < 16; k++) { a += rbuf[k]; b += rbuf[16 + k]; c += rbuf[32 + k]; }
        float muv  = a * (1.0f / CC);
        float varv = b * (1.0f / CC) - muv * muv;
        rbuf[48] = muv;
        rbuf[49] = rsqrtf(varv + EPSV);
        rbuf[50] = rsqrtf(c * (1.0f / CC) + EPSV);
    }
    __syncthreads();
    const float mu = rbuf[48], rstd = rbuf[49], inv = rbuf[50];

    // normalize (paired) -> xnbf
    for (int j2 = tid; j2 < NSH * 64; j2 += 512) {
        int m = j2 >> 6, c2 = (j2 & 63) << 1;
        float v0 = xn[m * CC + c2], v1 = xn[m * CC + c2 + 1];
        if (m == 0) {
            v0 = (v0 - mu) * rstd * ln0_w[c2] + ln0_b[c2];
            v1 = (v1 - mu) * rstd * ln0_w[c2 + 1] + ln0_b[c2 + 1];
        } else {
            const float* aw = aff_w + (c_ltab[m] - 1) * CC;
            v0 *= inv * aw[c2]; v1 *= inv * aw[c2 + 1];
        }
        st2(xnh, xnl, m * XNS + c2, v0, v1);
    }
    __syncthreads();

    // ---- Phase C: 16 warps, l = wid>>1 (l=7 is the gate row) ----
    {
        const int l = wid >> 1, nh = wid & 1;
        const bool isg = (l == 7);
        const int geff  = isg ? 1 : 2 * l + 1;
        const int mbase = isg ? 0 : l * l;
        for (int jb = 0; jb < 2; jb++) {
            float acc[8][4];
            #pragma unroll
            for (int j = 0; j < 8; j++)
                #pragma unroll
                for (int q = 0; q < 4; q++) acc[j][q] = 0.f;
            #pragma unroll
            for (int ks = 0; ks < 8; ks++) {
                uint32_t ah[4], al[4];
                uint32_t fo = frag_off(mbase, ks * 16, XNS * 2, lid);
                ldsm4(ah, u_xnh + fo);
                ldsm4(al, u_xnl + fo);
                #pragma unroll
                for (int j = 0; j < 8; j++) {
                    int nt = nh * 16 + jb * 8 + j;
                    uint4 B = g_w1f[(size_t)W1F_IDX(l, nt, ks) * 32 + lid];
                    mma16816(acc[j], ah, B.x, B.y);
                    mma16816(acc[j], ah, B.z, B.w);
                    mma16816(acc[j], al, B.x, B.y);
                }
            }
            #pragma unroll
            for (int j = 0; j < 8; j++) {
                int nt = nh * 16 + jb * 8 + j;
                int n0 = nt * 8 + 2 * tig;
                float v0 = acc[j][0], v1 = acc[j][1];
                if (isg) {
                    if (r0 == 0) {
                        v0 = fast_silu(v0 + gate_b[n0]);
                        v1 = fast_silu(v1 + gate_b[n0 + 1]);
                        st2(h2h, h2l, n0, v0, v1);   // h2 row 0
                    }
                } else {
                    if (l == 0 && r0 == 0) { v0 += b1[n0]; v1 += b1[n0 + 1]; }
                    if (r0 < geff)
                        st2(h1h, h1l, (mbase + r0) * GS + n0, v0, v1);
                    if (r0 + 8 < geff)
                        st2(h1h, h1l, (mbase + r0 + 8) * GS + n0, acc[j][2], acc[j][3]);
                }
            }
        }
    }

    // ---- Phase D: grid transform (16 warps = 4 mt x 4 ng) ----
    {
        const int mt = wid & 3, ng = wid >> 2;
        float acc2[8][4];
        #pragma unroll
        for (int j = 0; j < 8; j++)
            #pragma unroll
            for (int q = 0; q < 4; q++) acc2[j][q] = 0.f;

        for (int ch = 0; ch < 3; ch++) {
            __syncthreads();   // h1 ready (ch=0); prev G2 reads of g done
            // GEMM1: g[p][c] = T @ h1
            float acc1[8][4];
            #pragma unroll
            for (int j = 0; j < 8; j++)
                #pragma unroll
                for (int q = 0; q < 4; q++) acc1[j][q] = 0.f;
            #pragma unroll
            for (int ks = 0; ks < 4; ks++) {
                uint4 AH = g_a1f[(size_t)A1F_IDX(0, ch, mt, ks) * 32 + lid];
                uint4 AL = g_a1f[(size_t)A1F_IDX(1, ch, mt, ks) * 32 + lid];
                uint32_t ah[4] = {AH.x, AH.y, AH.z, AH.w};
                uint32_t al[4] = {AL.x, AL.y, AL.z, AL.w};
                #pragma unroll
                for (int jp = 0; jp < 4; jp++) {
                    uint32_t bh[4], bl[4];
                    uint32_t fo = frag_off(ks * 16, ng * 64 + jp * 16, GS * 2, lid);
                    ldsm4t(bh, u_h1h + fo);
                    ldsm4t(bl, u_h1l + fo);
                    mma16816(acc1[2 * jp], ah, bh[0], bh[1]);
                    mma16816(acc1[2 * jp], ah, bl[0], bl[1]);
                    mma16816(acc1[2 * jp], al, bh[0], bh[1]);
                    mma16816(acc1[2 * jp + 1], ah, bh[2], bh[3]);
                    mma16816(acc1[2 * jp + 1], ah, bl[2], bl[3]);
                    mma16816(acc1[2 * jp + 1], al, bh[2], bh[3]);
                }
            }
            __syncthreads();   // all reads of g-region predecessors done before overwrite
            // epilogue: silu -> g[p][c]
            #pragma unroll
            for (int j = 0; j < 8; j++) {
                int c0 = ng * 64 + j * 8 + 2 * tig;
                int p0 = mt * 16 + r0;
                st2(ghi, glo, p0 * GS + c0, fast_silu(acc1[j][0]), fast_silu(acc1[j][1]));
                st2(ghi, glo, (p0 + 8) * GS + c0, fast_silu(acc1[j][2]), fast_silu(acc1[j][3]));
            }
            __syncthreads();   // g complete
            // GEMM2: ht[i][c] += F^T @ g
            #pragma unroll
            for (int ks = 0; ks < 4; ks++) {
                uint4 AH = g_a2f[(size_t)A1F_IDX(0, ch, mt, ks) * 32 + lid];
                uint4 AL = g_a2f[(size_t)A1F_IDX(1, ch, mt, ks) * 32 + lid];
                uint32_t ah[4] = {AH.x, AH.y, AH.z, AH.w};
                uint32_t al[4] = {AL.x, AL.y, AL.z, AL.w};
                #pragma unroll
                for (int jp = 0; jp < 4; jp++) {
                    uint32_t bh[4], bl[4];
                    uint32_t fo = frag_off(ks * 16, ng * 64 + jp * 16, GS * 2, lid);
                    ldsm4t(bh, u_ghi + fo);
                    ldsm4t(bl, u_glo + fo);
                    mma16816(acc2[2 * jp], ah, bh[0], bh[1]);
                    mma16816(acc2[2 * jp], ah, bl[0], bl[1]);
                    mma16816(acc2[2 * jp], al, bh[0], bh[1]);
                    mma16816(acc2[2 * jp + 1], ah, bh[2], bh[3]);
                    mma16816(acc2[2 * jp + 1], ah, bl[2], bl[3]);
                    mma16816(acc2[2 * jp + 1], al, bh[2], bh[3]);
                }
            }
        }
        // D epilogue: ht rows 1..48 -> h2 (row 0 already written by gate in C)
        #pragma unroll
        for (int j = 0; j < 8; j++) {
            int c0 = ng * 64 + j * 8 + 2 * tig;
            int i0 = mt * 16 + r0, i1 = i0 + 8;
            if (i0 >= 1 && i0 <= 48)
                st2(h2h, h2l, i0 * GS + c0, acc2[j][0], acc2[j][1]);
            if (i1 <= 48)
                st2(h2h, h2l, i1 * GS + c0, acc2[j][2], acc2[j][3]);
        }
        __syncthreads();
    }

    // ---- Phase E: out = h2 @ w2^T (warps 0-13, 2 per l) ----
    if (wid < 14) {
        float* outn = out + (size_t)n * (NSH * CC);
        const int l = wid >> 1, nh = wid & 1;
        const int g = 2 * l + 1, mbase = l * l;
        float acc[8][4];
        #pragma unroll
        for (int j = 0; j < 8; j++)
            #pragma unroll
            for (int q = 0; q < 4; q++) acc[j][q] = 0.f;
        #pragma unroll 4
        for (int ks = 0; ks < 16; ks++) {
            uint32_t ah[4], al[4];
            uint32_t fo = frag_off(mbase, ks * 16, GS * 2, lid);
            ldsm4(ah, u_h2h + fo);
            ldsm4(al, u_h2l + fo);
            #pragma unroll
            for (int j = 0; j < 8; j++) {
                int nt = nh * 8 + j;
                uint4 B = g_w2f[(size_t)W2F_IDX(l, nt, ks) * 32 + lid];
                mma16816(acc[j], ah, B.x, B.y);
                mma16816(acc[j], ah, B.z, B.w);
                mma16816(acc[j], al, B.x, B.y);
            }
        }
        #pragma unroll
        for (int j = 0; j < 8; j++) {
            int nt = nh * 8 + j;
            int n0 = nt * 8 + 2 * tig;
            float v0 = acc[j][0], v1 = acc[j][1];
            if (l == 0 && r0 == 0) { v0 += b2[n0]; v1 += b2[n0 + 1]; }
            if (r0 < g)
                *reinterpret_cast<float2*>(outn + (mbase + r0) * CC + n0) =
                    make_float2(v0, v1);
            if (r0 + 8 < g)
                *reinterpret_cast<float2*>(outn + (mbase + r0 + 8) * CC + n0) =
                    make_float2(acc[j][2], acc[j][3]);
        }
    }
}

extern "C" void kernel_launch(void* const* d_in, const int* in_sizes, int n_in,
                              void* d_out, int out_size)
{
    const float* x      = (const float*)d_in[0];
    const float* ln0_w  = (const float*)d_in[1];
    const float* ln0_b  = (const float*)d_in[2];
    const float* aff_w  = (const float*)d_in[3];
    const float* w1     = (const float*)d_in[4];
    const float* b1     = (const float*)d_in[5];
    const float* gate_w = (const float*)d_in[6];
    const float* gate_b = (const float*)d_in[7];
    const float* w2     = (const float*)d_in[8];
    const float* b2     = (const float*)d_in[9];
    const float* tg     = (const float*)d_in[10];
    const float* fg     = (const float*)d_in[11];
    float* out = (float*)d_out;

    prep_frags<<<(3936 * 32 + 255) / 256, 256>>>(w1, w2, tg, fg, gate_w);

    const int n_nodes = in_sizes[0] / (NSH * CC);
    const int smem_bytes = SMEM_FLOATS * (int)sizeof(float);
    cudaFuncSetAttribute(ffn_fused, cudaFuncAttributeMaxDynamicSharedMemorySize, smem_bytes);
    ffn_fused<<<n_nodes, 512, smem_bytes>>>(x, ln0_w, ln0_b, aff_w, b1,
                                            gate_b, b2, out);
}

// round 11
// speedup vs baseline: 2.8208x; 1.1145x over previous
#include <cuda_runtime.h>
#include <cuda_fp16.h>
#include <math.h>
#include <cstdint>

#define NSH  49
#define CC   128
#define HH   256
#define EPSV 1e-5f
#define XNS  136     // xnbf row stride (elems) -> 272B, ldsm conflict-free
#define GS   264     // h1/g/h2 row stride (elems) -> 528B, ldsm conflict-free

// ---------------- smem layout (floats) ----------------
// rbuf 0..64
// GREG @64 (16896): phase A-C: xn fp32 @64(6272) | xnbf hi @6336(4352) lo @10688(4352)
//                   phase D:   g [64 p][264 c] fp16 hi @64(8448) lo @8512(8448)
// h1 [64 i][264 c] fp16: hi @16960(8448) lo @25408(8448)
// h2 [64 i][264 c] fp16: hi @33856(8448) lo @42304(8448)
#define O_RBUF  0
#define O_XN    64
#define O_XNBFH 6336
#define O_XNBFL 10688
#define O_GHI   64
#define O_GLO   8512
#define O_H1HI  16960
#define O_H1LO  25408
#define O_H2HI  33856
#define O_H2LO  42304
#define SMEM_FLOATS 50752

// fragment-linear global operand banks.
// w1 (l 0..6) + gate (l=7), w2: SINGLE fp16 -> uint2 per lane.
// a1/a2 (grid matrices): fp16 hi/lo split -> uint4 x2.
#define W1F_IDX(l,nt,ks)  (((l)*32 + (nt))*8 + (ks))
#define W2F_IDX(l,nt,ks)  (((l)*16 + (nt))*16 + (ks))
#define A1F_IDX(h,ch,mt,ks) (((((h)*3 + (ch))*4 + (mt))*4 + (ks)))
__device__ uint2 g_w1f[2048*32];
__device__ uint2 g_w2f[1792*32];
__device__ uint4 g_a1f[2*48*32];
__device__ uint4 g_a2f[2*48*32];

__constant__ int c_ltab[NSH] = {
    0,
    1,1,1,
    2,2,2,2,2,
    3,3,3,3,3,3,3,
    4,4,4,4,4,4,4,4,4,
    5,5,5,5,5,5,5,5,5,5,5,
    6,6,6,6,6,6,6,6,6,6,6,6,6};

__constant__ float c_bal[NSH] = {
    0.0f,
    0.05555555556f,0.05555555556f,0.05555555556f,
    0.03333333333f,0.03333333333f,0.03333333333f,0.03333333333f,0.03333333333f,
    0.02380952381f,0.02380952381f,0.02380952381f,0.02380952381f,0.02380952381f,0.02380952381f,0.02380952381f,
    0.01851851852f,0.01851851852f,0.01851851852f,0.01851851852f,0.01851851852f,0.01851851852f,0.01851851852f,0.01851851852f,0.01851851852f,
    0.01515151515f,0.01515151515f,0.01515151515f,0.01515151515f,0.01515151515f,0.01515151515f,0.01515151515f,0.01515151515f,0.01515151515f,0.01515151515f,0.01515151515f,
    0.01282051282f,0.01282051282f,0.01282051282f,0.01282051282f,0.01282051282f,0.01282051282f,0.01282051282f,0.01282051282f,0.01282051282f,0.01282051282f,0.01282051282f,0.01282051282f,0.01282051282f};

__device__ __forceinline__ float fast_silu(float v) {
    return __fdividef(v, 1.0f + __expf(-v));
}
__device__ __forceinline__ uint16_t f16h(float v) {
    return __half_as_ushort(__float2half(v));
}
__device__ __forceinline__ uint16_t f16l(float v) {
    __half h = __float2half(v);
    return __half_as_ushort(__float2half(v - __half2float(h)));
}
__device__ __forceinline__ uint32_t pk(uint16_t a, uint16_t b) {
    return (uint32_t)a | ((uint32_t)b << 16);
}
// paired fp16 hi/lo store: (a,b) -> one STS.32 each in hi/lo bufs
__device__ __forceinline__ void st2(char* hi, char* lo, int elem_off, float a, float b) {
    *reinterpret_cast<uint32_t*>(hi + elem_off * 2) = pk(f16h(a), f16h(b));
    *reinterpret_cast<uint32_t*>(lo + elem_off * 2) = pk(f16l(a), f16l(b));
}
__device__ __forceinline__ uint32_t smem_u32(const void* p) {
    uint32_t a;
    asm("{ .reg .u64 t; cvta.to.shared.u64 t, %1; cvt.u32.u64 %0, t; }" : "=r"(a) : "l"(p));
    return a;
}
__device__ __forceinline__ void mma16816(float* d, const uint32_t* a,
                                         uint32_t b0, uint32_t b1) {
    asm volatile(
        "mma.sync.aligned.m16n8k16.row.col.f32.f16.f16.f32 "
        "{%0,%1,%2,%3}, {%4,%5,%6,%7}, {%8,%9}, {%0,%1,%2,%3};\n"
        : "+f"(d[0]), "+f"(d[1]), "+f"(d[2]), "+f"(d[3])
        : "r"(a[0]), "r"(a[1]), "r"(a[2]), "r"(a[3]), "r"(b0), "r"(b1));
}
__device__ __forceinline__ void ldsm4(uint32_t* f, uint32_t a) {
    asm volatile("ldmatrix.sync.aligned.m8n8.x4.shared.b16 {%0,%1,%2,%3}, [%4];"
        : "=r"(f[0]), "=r"(f[1]), "=r"(f[2]), "=r"(f[3]) : "r"(a));
}
__device__ __forceinline__ void ldsm4t(uint32_t* f, uint32_t a) {
    asm volatile("ldmatrix.sync.aligned.m8n8.x4.trans.shared.b16 {%0,%1,%2,%3}, [%4];"
        : "=r"(f[0]), "=r"(f[1]), "=r"(f[2]), "=r"(f[3]) : "r"(a));
}
__device__ __forceinline__ uint32_t frag_off(int r_base, int c_base, int strideB, int lane) {
    int q = lane >> 3;
    return (uint32_t)((r_base + (lane & 7) + ((q & 1) << 3)) * strideB
                      + ((c_base + ((q >> 1) << 3)) << 1));
}

// ---------------- prep kernel ----------------
__global__ void prep_frags(const float* __restrict__ w1, const float* __restrict__ w2,
                           const float* __restrict__ tg, const float* __restrict__ fg,
                           const float* __restrict__ gate_w)
{
    int t = blockIdx.x * 256 + threadIdx.x;
    if (t >= 3936 * 32) return;
    int lane = t & 31;
    int r0 = lane >> 2, tig = lane & 3;
    int fi = t >> 5;

    if (fi < 2048) {                       // w1 (l 0..6) + gate_w (l=7): single fp16
        int ks = fi & 7, nt = (fi >> 3) & 31, l = fi >> 8;
        int n = nt * 8 + r0, k = ks * 16 + 2 * tig;
        const float* s = (l < 7) ? (w1 + ((size_t)l * HH + n) * CC + k)
                                 : (gate_w + (size_t)n * CC + k);
        float v0 = s[0], v1 = s[1], v8 = s[8], v9 = s[9];
        g_w1f[(size_t)W1F_IDX(l, nt, ks) * 32 + lane] =
            make_uint2(pk(f16h(v0), f16h(v1)), pk(f16h(v8), f16h(v9)));
    } else if (fi < 3840) {                // w2: single fp16
        int fj = fi - 2048;
        int ks = fj & 15, nt = (fj >> 4) & 15, l = fj >> 8;
        int n = nt * 8 + r0, k = ks * 16 + 2 * tig;
        const float* s = w2 + ((size_t)l * CC + n) * HH + k;
        float v0 = s[0], v1 = s[1], v8 = s[8], v9 = s[9];
        g_w2f[(size_t)W2F_IDX(l, nt, ks) * 32 + lane] =
            make_uint2(pk(f16h(v0), f16h(v1)), pk(f16h(v8), f16h(v9)));
    } else if (fi < 3888) {                // a1 = to_grid [p][i]: fp16 hi/lo
        int fk = fi - 3840;
        int ks = fk & 3, mt = (fk >> 2) & 3, ch = fk >> 4;
        int pa = ch * 64 + mt * 16 + r0, pb = pa + 8;
        int ia = ks * 16 + 2 * tig;
        auto val = [&](int p, int i) -> float {
            return (p < 182 && i < NSH) ? tg[p * NSH + i] : 0.f;
        };
        float xa0 = val(pa, ia), xa1 = val(pa, ia + 1);
        float ya0 = val(pb, ia), ya1 = val(pb, ia + 1);
        float za0 = val(pa, ia + 8), za1 = val(pa, ia + 9);
        float wa0 = val(pb, ia + 8), wa1 = val(pb, ia + 9);
        g_a1f[(size_t)A1F_IDX(0, ch, mt, ks) * 32 + lane] =
            make_uint4(pk(f16h(xa0), f16h(xa1)), pk(f16h(ya0), f16h(ya1)),
                       pk(f16h(za0), f16h(za1)), pk(f16h(wa0), f16h(wa1)));
        g_a1f[(size_t)A1F_IDX(1, ch, mt, ks) * 32 + lane] =
            make_uint4(pk(f16l(xa0), f16l(xa1)), pk(f16l(ya0), f16l(ya1)),
                       pk(f16l(za0), f16l(za1)), pk(f16l(wa0), f16l(wa1)));
    } else {                               // a2 = from_grid^T [i][p]: fp16 hi/lo
        int fk = fi - 3888;
        int ks = fk & 3, mt = (fk >> 2) & 3, ch = fk >> 4;
        int ia = mt * 16 + r0, ib = ia + 8;
        int p0 = ch * 64 + ks * 16 + 2 * tig;
        auto val = [&](int i, int p) -> float {
            return (p < 182 && i < NSH) ? fg[p * NSH + i] : 0.f;
        };
        float xa0 = val(ia, p0), xa1 = val(ia, p0 + 1);
        float ya0 = val(ib, p0), ya1 = val(ib, p0 + 1);
        float za0 = val(ia, p0 + 8), za1 = val(ia, p0 + 9);
        float wa0 = val(ib, p0 + 8), wa1 = val(ib, p0 + 9);
        g_a2f[(size_t)A1F_IDX(0, ch, mt, ks) * 32 + lane] =
            make_uint4(pk(f16h(xa0), f16h(xa1)), pk(f16h(ya0), f16h(ya1)),
                       pk(f16h(za0), f16h(za1)), pk(f16h(wa0), f16h(wa1)));
        g_a2f[(size_t)A1F_IDX(1, ch, mt, ks) * 32 + lane] =
            make_uint4(pk(f16l(xa0), f16l(xa1)), pk(f16l(ya0), f16l(ya1)),
                       pk(f16l(za0), f16l(za1)), pk(f16l(wa0), f16l(wa1)));
    }
}

// ---------------- main kernel ----------------
__global__ void __launch_bounds__(512, 1)
ffn_fused(const float* __restrict__ x,
          const float* __restrict__ ln0_w, const float* __restrict__ ln0_b,
          const float* __restrict__ aff_w,
          const float* __restrict__ b1,
          const float* __restrict__ gate_b,
          const float* __restrict__ b2,
          float* __restrict__ out)
{
    extern __shared__ float sm[];
    float* rbuf = sm + O_RBUF;
    float* xn   = sm + O_XN;

    char* xnh = reinterpret_cast<char*>(sm + O_XNBFH);
    char* xnl = reinterpret_cast<char*>(sm + O_XNBFL);
    char* ghi = reinterpret_cast<char*>(sm + O_GHI);
    char* glo = reinterpret_cast<char*>(sm + O_GLO);
    char* h1h = reinterpret_cast<char*>(sm + O_H1HI);
    char* h1l = reinterpret_cast<char*>(sm + O_H1LO);
    char* h2h = reinterpret_cast<char*>(sm + O_H2HI);
    char* h2l = reinterpret_cast<char*>(sm + O_H2LO);

    const uint32_t u0    = smem_u32(sm);
    const uint32_t u_xnh = u0 + O_XNBFH * 4, u_xnl = u0 + O_XNBFL * 4;
    const uint32_t u_ghi = u0 + O_GHI * 4,   u_glo = u0 + O_GLO * 4;
    const uint32_t u_h1h = u0 + O_H1HI * 4,  u_h1l = u0 + O_H1LO * 4;
    const uint32_t u_h2h = u0 + O_H2HI * 4,  u_h2l = u0 + O_H2LO * 4;

    const int tid = threadIdx.x;
    const int n   = blockIdx.x;
    const int wid = tid >> 5;
    const int lid = tid & 31;
    const int r0  = lid >> 2;
    const int tig = lid & 3;

    // ---- Phase A: load x; zero h1 (K-side of D-GEMM1 must be clean) ----
    const float4* xin = reinterpret_cast<const float4*>(x + (size_t)n * (NSH * CC));
    float4* xns = reinterpret_cast<float4*>(xn);
    for (int j4 = tid; j4 < NSH * CC / 4; j4 += 512) xns[j4] = xin[j4];
    {
        float4* z = reinterpret_cast<float4*>(sm + O_H1HI);
        for (int j = tid; j < 16896 / 4; j += 512) z[j] = make_float4(0, 0, 0, 0);
    }
    __syncthreads();

    // ---- norms ----
    float s0 = 0.f, q0 = 0.f, sw = 0.f;
    for (int j4 = tid; j4 < NSH * CC / 4; j4 += 512) {
        float4 v = xns[j4];
        int m = j4 >> 5;
        float d = v.x * v.x + v.y * v.y + v.z * v.z + v.w * v.w;
        if (m == 0) { s0 += v.x + v.y + v.z + v.w; q0 += d; }
        else        sw += c_bal[m] * d;
    }
    #pragma unroll
    for (int o = 16; o > 0; o >>= 1) {
        s0 += __shfl_xor_sync(0xffffffffu, s0, o);
        q0 += __shfl_xor_sync(0xffffffffu, q0, o);
        sw += __shfl_xor_sync(0xffffffffu, sw, o);
    }
    if (lid == 0) { rbuf[wid] = s0; rbuf[16 + wid] = q0; rbuf[32 + wid] = sw; }
    __syncthreads();
    if (tid == 0) {
        float a = 0.f, b = 0.f, c = 0.f;
        #pragma unroll
        for (int k = 0; k < 16; k++) { a += rbuf[k]; b += rbuf[16 + k]; c += rbuf[32 + k]; }
        float muv  = a * (1.0f / CC);
        float varv = b * (1.0f / CC) - muv * muv;
        rbuf[48] = muv;
        rbuf[49] = rsqrtf(varv + EPSV);
        rbuf[50] = rsqrtf(c * (1.0f / CC) + EPSV);
    }
    __syncthreads();
    const float mu = rbuf[48], rstd = rbuf[49], inv = rbuf[50];

    // normalize (paired) -> xnbf fp16 hi/lo
    for (int j2 = tid; j2 < NSH * 64; j2 += 512) {
        int m = j2 >> 6, c2 = (j2 & 63) << 1;
        float v0 = xn[m * CC + c2], v1 = xn[m * CC + c2 + 1];
        if (m == 0) {
            v0 = (v0 - mu) * rstd * ln0_w[c2] + ln0_b[c2];
            v1 = (v1 - mu) * rstd * ln0_w[c2 + 1] + ln0_b[c2 + 1];
        } else {
            const float* aw = aff_w + (c_ltab[m] - 1) * CC;
            v0 *= inv * aw[c2]; v1 *= inv * aw[c2 + 1];
        }
        st2(xnh, xnl, m * XNS + c2, v0, v1);
    }
    __syncthreads();

    // ---- Phase C: 16 warps, l = wid>>1 (l=7 is the gate row); 2-product fp16 ----
    {
        const int l = wid >> 1, nh = wid & 1;
        const bool isg = (l == 7);
        const int geff  = isg ? 1 : 2 * l + 1;
        const int mbase = isg ? 0 : l * l;
        for (int jb = 0; jb < 2; jb++) {
            float acc[8][4];
            #pragma unroll
            for (int j = 0; j < 8; j++)
                #pragma unroll
                for (int q = 0; q < 4; q++) acc[j][q] = 0.f;
            #pragma unroll
            for (int ks = 0; ks < 8; ks++) {
                uint32_t ah[4], al[4];
                uint32_t fo = frag_off(mbase, ks * 16, XNS * 2, lid);
                ldsm4(ah, u_xnh + fo);
                ldsm4(al, u_xnl + fo);
                #pragma unroll
                for (int j = 0; j < 8; j++) {
                    int nt = nh * 16 + jb * 8 + j;
                    uint2 B = g_w1f[(size_t)W1F_IDX(l, nt, ks) * 32 + lid];
                    mma16816(acc[j], ah, B.x, B.y);
                    mma16816(acc[j], al, B.x, B.y);
                }
            }
            #pragma unroll
            for (int j = 0; j < 8; j++) {
                int nt = nh * 16 + jb * 8 + j;
                int n0 = nt * 8 + 2 * tig;
                float v0 = acc[j][0], v1 = acc[j][1];
                if (isg) {
                    if (r0 == 0) {
                        v0 = fast_silu(v0 + gate_b[n0]);
                        v1 = fast_silu(v1 + gate_b[n0 + 1]);
                        st2(h2h, h2l, n0, v0, v1);   // h2 row 0
                    }
                } else {
                    if (l == 0 && r0 == 0) { v0 += b1[n0]; v1 += b1[n0 + 1]; }
                    if (r0 < geff)
                        st2(h1h, h1l, (mbase + r0) * GS + n0, v0, v1);
                    if (r0 + 8 < geff)
                        st2(h1h, h1l, (mbase + r0 + 8) * GS + n0, acc[j][2], acc[j][3]);
                }
            }
        }
    }

    // ---- Phase D: grid transform (16 warps = 4 mt x 4 ng); 3-product fp16 ----
    {
        const int mt = wid & 3, ng = wid >> 2;
        float acc2[8][4];
        #pragma unroll
        for (int j = 0; j < 8; j++)
            #pragma unroll
            for (int q = 0; q < 4; q++) acc2[j][q] = 0.f;

        for (int ch = 0; ch < 3; ch++) {
            __syncthreads();   // h1 ready (ch=0); prev G2 reads of g done
            // GEMM1: g[p][c] = T @ h1
            float acc1[8][4];
            #pragma unroll
            for (int j = 0; j < 8; j++)
                #pragma unroll
                for (int q = 0; q < 4; q++) acc1[j][q] = 0.f;
            #pragma unroll
            for (int ks = 0; ks < 4; ks++) {
                uint4 AH = g_a1f[(size_t)A1F_IDX(0, ch, mt, ks) * 32 + lid];
                uint4 AL = g_a1f[(size_t)A1F_IDX(1, ch, mt, ks) * 32 + lid];
                uint32_t ah[4] = {AH.x, AH.y, AH.z, AH.w};
                uint32_t al[4] = {AL.x, AL.y, AL.z, AL.w};
                #pragma unroll
                for (int jp = 0; jp < 4; jp++) {
                    uint32_t bh[4], bl[4];
                    uint32_t fo = frag_off(ks * 16, ng * 64 + jp * 16, GS * 2, lid);
                    ldsm4t(bh, u_h1h + fo);
                    ldsm4t(bl, u_h1l + fo);
                    mma16816(acc1[2 * jp], ah, bh[0], bh[1]);
                    mma16816(acc1[2 * jp], ah, bl[0], bl[1]);
                    mma16816(acc1[2 * jp], al, bh[0], bh[1]);
                    mma16816(acc1[2 * jp + 1], ah, bh[2], bh[3]);
                    mma16816(acc1[2 * jp + 1], ah, bl[2], bl[3]);
                    mma16816(acc1[2 * jp + 1], al, bh[2], bh[3]);
                }
            }
            __syncthreads();   // all reads of g-region predecessors done before overwrite
            // epilogue: silu -> g[p][c]
            #pragma unroll
            for (int j = 0; j < 8; j++) {
                int c0 = ng * 64 + j * 8 + 2 * tig;
                int p0 = mt * 16 + r0;
                st2(ghi, glo, p0 * GS + c0, fast_silu(acc1[j][0]), fast_silu(acc1[j][1]));
                st2(ghi, glo, (p0 + 8) * GS + c0, fast_silu(acc1[j][2]), fast_silu(acc1[j][3]));
            }
            __syncthreads();   // g complete
            // GEMM2: ht[i][c] += F^T @ g
            #pragma unroll
            for (int ks = 0; ks < 4; ks++) {
                uint4 AH = g_a2f[(size_t)A1F_IDX(0, ch, mt, ks) * 32 + lid];
                uint4 AL = g_a2f[(size_t)A1F_IDX(1, ch, mt, ks) * 32 + lid];
                uint32_t ah[4] = {AH.x, AH.y, AH.z, AH.w};
                uint32_t al[4] = {AL.x, AL.y, AL.z, AL.w};
                #pragma unroll
                for (int jp = 0; jp < 4; jp++) {
                    uint32_t bh[4], bl[4];
                    uint32_t fo = frag_off(ks * 16, ng * 64 + jp * 16, GS * 2, lid);
                    ldsm4t(bh, u_ghi + fo);
                    ldsm4t(bl, u_glo + fo);
                    mma16816(acc2[2 * jp], ah, bh[0], bh[1]);
                    mma16816(acc2[2 * jp], ah, bl[0], bl[1]);
                    mma16816(acc2[2 * jp], al, bh[0], bh[1]);
                    mma16816(acc2[2 * jp + 1], ah, bh[2], bh[3]);
                    mma16816(acc2[2 * jp + 1], ah, bl[2], bl[3]);
                    mma16816(acc2[2 * jp + 1], al, bh[2], bh[3]);
                }
            }
        }
        // D epilogue: ht rows 1..48 -> h2 (row 0 already written by gate in C)
        #pragma unroll
        for (int j = 0; j < 8; j++) {
            int c0 = ng * 64 + j * 8 + 2 * tig;
            int i0 = mt * 16 + r0, i1 = i0 + 8;
            if (i0 >= 1 && i0 <= 48)
                st2(h2h, h2l, i0 * GS + c0, acc2[j][0], acc2[j][1]);
            if (i1 <= 48)
                st2(h2h, h2l, i1 * GS + c0, acc2[j][2], acc2[j][3]);
        }
        __syncthreads();
    }

    // ---- Phase E: out = h2 @ w2^T (warps 0-13, 2 per l); 2-product fp16 ----
    if (wid < 14) {
        float* outn = out + (size_t)n * (NSH * CC);
        const int l = wid >> 1, nh = wid & 1;
        const int g = 2 * l + 1, mbase = l * l;
        float acc[8][4];
        #pragma unroll
        for (int j = 0; j < 8; j++)
            #pragma unroll
            for (int q = 0; q < 4; q++) acc[j][q] = 0.f;
        #pragma unroll 4
        for (int ks = 0; ks < 16; ks++) {
            uint32_t ah[4], al[4];
            uint32_t fo = frag_off(mbase, ks * 16, GS * 2, lid);
            ldsm4(ah, u_h2h + fo);
            ldsm4(al, u_h2l + fo);
            #pragma unroll
            for (int j = 0; j < 8; j++) {
                int nt = nh * 8 + j;
                uint2 B = g_w2f[(size_t)W2F_IDX(l, nt, ks) * 32 + lid];
                mma16816(acc[j], ah, B.x, B.y);
                mma16816(acc[j], al, B.x, B.y);
            }
        }
        #pragma unroll
        for (int j = 0; j < 8; j++) {
            int nt = nh * 8 + j;
            int n0 = nt * 8 + 2 * tig;
            float v0 = acc[j][0], v1 = acc[j][1];
            if (l == 0 && r0 == 0) { v0 += b2[n0]; v1 += b2[n0 + 1]; }
            if (r0 < g)
                *reinterpret_cast<float2*>(outn + (mbase + r0) * CC + n0) =
                    make_float2(v0, v1);
            if (r0 + 8 < g)
                *reinterpret_cast<float2*>(outn + (mbase + r0 + 8) * CC + n0) =
                    make_float2(acc[j][2], acc[j][3]);
        }
    }
}

extern "C" void kernel_launch(void* const* d_in, const int* in_sizes, int n_in,
                              void* d_out, int out_size)
{
    const float* x      = (const float*)d_in[0];
    const float* ln0_w  = (const float*)d_in[1];
    const float* ln0_b  = (const float*)d_in[2];
    const float* aff_w  = (const float*)d_in[3];
    const float* w1     = (const float*)d_in[4];
    const float* b1     = (const float*)d_in[5];
    const float* gate_w = (const float*)d_in[6];
    const float* gate_b = (const float*)d_in[7];
    const float* w2     = (const float*)d_in[8];
    const float* b2     = (const float*)d_in[9];
    const float* tg     = (const float*)d_in[10];
    const float* fg     = (const float*)d_in[11];
    float* out = (float*)d_out;

    prep_frags<<<(3936 * 32 + 255) / 256, 256>>>(w1, w2, tg, fg, gate_w);

    const int n_nodes = in_sizes[0] / (NSH * CC);
    const int smem_bytes = SMEM_FLOATS * (int)sizeof(float);
    cudaFuncSetAttribute(ffn_fused, cudaFuncAttributeMaxDynamicSharedMemorySize, smem_bytes);
    ffn_fused<<<n_nodes, 512, smem_bytes>>>(x, ln0_w, ln0_b, aff_w, b1,
                                            gate_b, b2, out);
}

// round 12
// speedup vs baseline: 3.0366x; 1.0765x over previous
#include <cuda_runtime.h>
#include <cuda_fp16.h>
#include <math.h>
#include <cstdint>

#define NSH  49
#define CC   128
#define HH   256
#define EPSV 1e-5f
#define XNS  136     // xnbf row stride (elems) -> 272B, ldsm conflict-free
#define GS   264     // h1/g/h2 row stride (elems) -> 528B, ldsm conflict-free

// ---------------- smem layout (floats) ----------------
// rbuf 0..64
// GREG @64 (16896): phase A-C: xn fp32 @64(6272) | xnbf hi @6336(4352) lo @10688(4352)
//                   phase D:   g [64 p][264 c] fp16 hi @64(8448) lo @8512(8448)
// h1 [64 i][264 c] fp16: hi @16960(8448) lo @25408(8448)
// h2 [64 i][264 c] fp16: hi @33856(8448) lo @42304(8448)
#define O_RBUF  0
#define O_XN    64
#define O_XNBFH 6336
#define O_XNBFL 10688
#define O_GHI   64
#define O_GLO   8512
#define O_H1HI  16960
#define O_H1LO  25408
#define O_H2HI  33856
#define O_H2LO  42304
#define SMEM_FLOATS 50752

// fragment-linear global operand banks, all SINGLE fp16:
// w1 (l 0..6) + gate (l=7), w2: uint2 per lane (B-frags).
// a1/a2 (grid A-frags): uint4 per lane.
#define W1F_IDX(l,nt,ks)  (((l)*32 + (nt))*8 + (ks))
#define W2F_IDX(l,nt,ks)  (((l)*16 + (nt))*16 + (ks))
#define A1F_IDX(ch,mt,ks) ((((ch)*4 + (mt))*4 + (ks)))
__device__ uint2 g_w1f[2048*32];
__device__ uint2 g_w2f[1792*32];
__device__ uint4 g_a1f[48*32];
__device__ uint4 g_a2f[48*32];

__constant__ int c_ltab[NSH] = {
    0,
    1,1,1,
    2,2,2,2,2,
    3,3,3,3,3,3,3,
    4,4,4,4,4,4,4,4,4,
    5,5,5,5,5,5,5,5,5,5,5,
    6,6,6,6,6,6,6,6,6,6,6,6,6};

__constant__ float c_bal[NSH] = {
    0.0f,
    0.05555555556f,0.05555555556f,0.05555555556f,
    0.03333333333f,0.03333333333f,0.03333333333f,0.03333333333f,0.03333333333f,
    0.02380952381f,0.02380952381f,0.02380952381f,0.02380952381f,0.02380952381f,0.02380952381f,0.02380952381f,
    0.01851851852f,0.01851851852f,0.01851851852f,0.01851851852f,0.01851851852f,0.01851851852f,0.01851851852f,0.01851851852f,0.01851851852f,
    0.01515151515f,0.01515151515f,0.01515151515f,0.01515151515f,0.01515151515f,0.01515151515f,0.01515151515f,0.01515151515f,0.01515151515f,0.01515151515f,0.01515151515f,
    0.01282051282f,0.01282051282f,0.01282051282f,0.01282051282f,0.01282051282f,0.01282051282f,0.01282051282f,0.01282051282f,0.01282051282f,0.01282051282f,0.01282051282f,0.01282051282f,0.01282051282f};

__device__ __forceinline__ float fast_silu(float v) {
    return __fdividef(v, 1.0f + __expf(-v));
}
__device__ __forceinline__ uint16_t f16h(float v) {
    return __half_as_ushort(__float2half(v));
}
__device__ __forceinline__ uint16_t f16l(float v) {
    __half h = __float2half(v);
    return __half_as_ushort(__float2half(v - __half2float(h)));
}
__device__ __forceinline__ uint32_t pk(uint16_t a, uint16_t b) {
    return (uint32_t)a | ((uint32_t)b << 16);
}
__device__ __forceinline__ void st2(char* hi, char* lo, int elem_off, float a, float b) {
    *reinterpret_cast<uint32_t*>(hi + elem_off * 2) = pk(f16h(a), f16h(b));
    *reinterpret_cast<uint32_t*>(lo + elem_off * 2) = pk(f16l(a), f16l(b));
}
__device__ __forceinline__ uint32_t smem_u32(const void* p) {
    uint32_t a;
    asm("{ .reg .u64 t; cvta.to.shared.u64 t, %1; cvt.u32.u64 %0, t; }" : "=r"(a) : "l"(p));
    return a;
}
__device__ __forceinline__ void mma16816(float* d, const uint32_t* a,
                                         uint32_t b0, uint32_t b1) {
    asm volatile(
        "mma.sync.aligned.m16n8k16.row.col.f32.f16.f16.f32 "
        "{%0,%1,%2,%3}, {%4,%5,%6,%7}, {%8,%9}, {%0,%1,%2,%3};\n"
        : "+f"(d[0]), "+f"(d[1]), "+f"(d[2]), "+f"(d[3])
        : "r"(a[0]), "r"(a[1]), "r"(a[2]), "r"(a[3]), "r"(b0), "r"(b1));
}
__device__ __forceinline__ void ldsm4(uint32_t* f, uint32_t a) {
    asm volatile("ldmatrix.sync.aligned.m8n8.x4.shared.b16 {%0,%1,%2,%3}, [%4];"
        : "=r"(f[0]), "=r"(f[1]), "=r"(f[2]), "=r"(f[3]) : "r"(a));
}
__device__ __forceinline__ void ldsm4t(uint32_t* f, uint32_t a) {
    asm volatile("ldmatrix.sync.aligned.m8n8.x4.trans.shared.b16 {%0,%1,%2,%3}, [%4];"
        : "=r"(f[0]), "=r"(f[1]), "=r"(f[2]), "=r"(f[3]) : "r"(a));
}
__device__ __forceinline__ uint32_t frag_off(int r_base, int c_base, int strideB, int lane) {
    int q = lane >> 3;
    return (uint32_t)((r_base + (lane & 7) + ((q & 1) << 3)) * strideB
                      + ((c_base + ((q >> 1) << 3)) << 1));
}

// ---------------- prep kernel ----------------
__global__ void prep_frags(const float* __restrict__ w1, const float* __restrict__ w2,
                           const float* __restrict__ tg, const float* __restrict__ fg,
                           const float* __restrict__ gate_w)
{
    int t = blockIdx.x * 256 + threadIdx.x;
    if (t >= 3936 * 32) return;
    int lane = t & 31;
    int r0 = lane >> 2, tig = lane & 3;
    int fi = t >> 5;

    if (fi < 2048) {                       // w1 (l 0..6) + gate_w (l=7): single fp16
        int ks = fi & 7, nt = (fi >> 3) & 31, l = fi >> 8;
        int n = nt * 8 + r0, k = ks * 16 + 2 * tig;
        const float* s = (l < 7) ? (w1 + ((size_t)l * HH + n) * CC + k)
                                 : (gate_w + (size_t)n * CC + k);
        float v0 = s[0], v1 = s[1], v8 = s[8], v9 = s[9];
        g_w1f[(size_t)W1F_IDX(l, nt, ks) * 32 + lane] =
            make_uint2(pk(f16h(v0), f16h(v1)), pk(f16h(v8), f16h(v9)));
    } else if (fi < 3840) {                // w2: single fp16
        int fj = fi - 2048;
        int ks = fj & 15, nt = (fj >> 4) & 15, l = fj >> 8;
        int n = nt * 8 + r0, k = ks * 16 + 2 * tig;
        const float* s = w2 + ((size_t)l * CC + n) * HH + k;
        float v0 = s[0], v1 = s[1], v8 = s[8], v9 = s[9];
        g_w2f[(size_t)W2F_IDX(l, nt, ks) * 32 + lane] =
            make_uint2(pk(f16h(v0), f16h(v1)), pk(f16h(v8), f16h(v9)));
    } else if (fi < 3888) {                // a1 = to_grid [p][i]: single fp16
        int fk = fi - 3840;
        int ks = fk & 3, mt = (fk >> 2) & 3, ch = fk >> 4;
        int pa = ch * 64 + mt * 16 + r0, pb = pa + 8;
        int ia = ks * 16 + 2 * tig;
        auto val = [&](int p, int i) -> float {
            return (p < 182 && i < NSH) ? tg[p * NSH + i] : 0.f;
        };
        g_a1f[(size_t)A1F_IDX(ch, mt, ks) * 32 + lane] =
            make_uint4(pk(f16h(val(pa, ia)),     f16h(val(pa, ia + 1))),
                       pk(f16h(val(pb, ia)),     f16h(val(pb, ia + 1))),
                       pk(f16h(val(pa, ia + 8)), f16h(val(pa, ia + 9))),
                       pk(f16h(val(pb, ia + 8)), f16h(val(pb, ia + 9))));
    } else {                               // a2 = from_grid^T [i][p]: single fp16
        int fk = fi - 3888;
        int ks = fk & 3, mt = (fk >> 2) & 3, ch = fk >> 4;
        int ia = mt * 16 + r0, ib = ia + 8;
        int p0 = ch * 64 + ks * 16 + 2 * tig;
        auto val = [&](int i, int p) -> float {
            return (p < 182 && i < NSH) ? fg[p * NSH + i] : 0.f;
        };
        g_a2f[(size_t)A1F_IDX(ch, mt, ks) * 32 + lane] =
            make_uint4(pk(f16h(val(ia, p0)),     f16h(val(ia, p0 + 1))),
                       pk(f16h(val(ib, p0)),     f16h(val(ib, p0 + 1))),
                       pk(f16h(val(ia, p0 + 8)), f16h(val(ia, p0 + 9))),
                       pk(f16h(val(ib, p0 + 8)), f16h(val(ib, p0 + 9))));
    }
}

// ---------------- main kernel ----------------
__global__ void __launch_bounds__(512, 1)
ffn_fused(const float* __restrict__ x,
          const float* __restrict__ ln0_w, const float* __restrict__ ln0_b,
          const float* __restrict__ aff_w,
          const float* __restrict__ b1,
          const float* __restrict__ gate_b,
          const float* __restrict__ b2,
          float* __restrict__ out)
{
    extern __shared__ float sm[];
    float* rbuf = sm + O_RBUF;
    float* xn   = sm + O_XN;

    char* xnh = reinterpret_cast<char*>(sm + O_XNBFH);
    char* xnl = reinterpret_cast<char*>(sm + O_XNBFL);
    char* ghi = reinterpret_cast<char*>(sm + O_GHI);
    char* glo = reinterpret_cast<char*>(sm + O_GLO);
    char* h1h = reinterpret_cast<char*>(sm + O_H1HI);
    char* h1l = reinterpret_cast<char*>(sm + O_H1LO);
    char* h2h = reinterpret_cast<char*>(sm + O_H2HI);
    char* h2l = reinterpret_cast<char*>(sm + O_H2LO);

    const uint32_t u0    = smem_u32(sm);
    const uint32_t u_xnh = u0 + O_XNBFH * 4, u_xnl = u0 + O_XNBFL * 4;
    const uint32_t u_ghi = u0 + O_GHI * 4,   u_glo = u0 + O_GLO * 4;
    const uint32_t u_h1h = u0 + O_H1HI * 4,  u_h1l = u0 + O_H1LO * 4;
    const uint32_t u_h2h = u0 + O_H2HI * 4,  u_h2l = u0 + O_H2LO * 4;

    const int tid = threadIdx.x;
    const int n   = blockIdx.x;
    const int wid = tid >> 5;
    const int lid = tid & 31;
    const int r0  = lid >> 2;
    const int tig = lid & 3;

    // ---- Phase A: load x; zero h1 pad rows 49..63 only (rows 0..48 fully written by C) ----
    const float4* xin = reinterpret_cast<const float4*>(x + (size_t)n * (NSH * CC));
    float4* xns = reinterpret_cast<float4*>(xn);
    for (int j4 = tid; j4 < NSH * CC / 4; j4 += 512) xns[j4] = xin[j4];
    {
        // rows 49..63 = float offsets [49*132, 8448) in each of h1hi/h1lo
        float4* zh = reinterpret_cast<float4*>(sm + O_H1HI + 49 * 132);
        float4* zl = reinterpret_cast<float4*>(sm + O_H1LO + 49 * 132);
        const int cnt = (8448 - 49 * 132) / 4;   // 495
        for (int j = tid; j < cnt; j += 512) {
            zh[j] = make_float4(0, 0, 0, 0);
            zl[j] = make_float4(0, 0, 0, 0);
        }
    }
    __syncthreads();

    // ---- norms ----
    float s0 = 0.f, q0 = 0.f, sw = 0.f;
    for (int j4 = tid; j4 < NSH * CC / 4; j4 += 512) {
        float4 v = xns[j4];
        int m = j4 >> 5;
        float d = v.x * v.x + v.y * v.y + v.z * v.z + v.w * v.w;
        if (m == 0) { s0 += v.x + v.y + v.z + v.w; q0 += d; }
        else        sw += c_bal[m] * d;
    }
    #pragma unroll
    for (int o = 16; o > 0; o >>= 1) {
        s0 += __shfl_xor_sync(0xffffffffu, s0, o);
        q0 += __shfl_xor_sync(0xffffffffu, q0, o);
        sw += __shfl_xor_sync(0xffffffffu, sw, o);
    }
    if (lid == 0) { rbuf[wid] = s0; rbuf[16 + wid] = q0; rbuf[32 + wid] = sw; }
    __syncthreads();
    if (tid == 0) {
        float a = 0.f, b = 0.f, c = 0.f;
        #pragma unroll
        for (int k = 0; k < 16; k++) { a += rbuf[k]; b += rbuf[16 + k]; c += rbuf[32 + k]; }
        float muv  = a * (1.0f / CC);
        float varv = b * (1.0f / CC) - muv * muv;
        rbuf[48] = muv;
        rbuf[49] = rsqrtf(varv + EPSV);
        rbuf[50] = rsqrtf(c * (1.0f / CC) + EPSV);
    }
    __syncthreads();
    const float mu = rbuf[48], rstd = rbuf[49], inv = rbuf[50];

    // normalize (paired) -> xnbf fp16 hi/lo
    for (int j2 = tid; j2 < NSH * 64; j2 += 512) {
        int m = j2 >> 6, c2 = (j2 & 63) << 1;
        float v0 = xn[m * CC + c2], v1 = xn[m * CC + c2 + 1];
        if (m == 0) {
            v0 = (v0 - mu) * rstd * ln0_w[c2] + ln0_b[c2];
            v1 = (v1 - mu) * rstd * ln0_w[c2 + 1] + ln0_b[c2 + 1];
        } else {
            const float* aw = aff_w + (c_ltab[m] - 1) * CC;
            v0 *= inv * aw[c2]; v1 *= inv * aw[c2 + 1];
        }
        st2(xnh, xnl, m * XNS + c2, v0, v1);
    }
    __syncthreads();

    // ---- Phase C: 16 warps, l = wid>>1 (l=7 is the gate row); 2-product fp16 ----
    {
        const int l = wid >> 1, nh = wid & 1;
        const bool isg = (l == 7);
        const int geff  = isg ? 1 : 2 * l + 1;
        const int mbase = isg ? 0 : l * l;
        for (int jb = 0; jb < 2; jb++) {
            float acc[8][4];
            #pragma unroll
            for (int j = 0; j < 8; j++)
                #pragma unroll
                for (int q = 0; q < 4; q++) acc[j][q] = 0.f;
            #pragma unroll
            for (int ks = 0; ks < 8; ks++) {
                uint32_t ah[4], al[4];
                uint32_t fo = frag_off(mbase, ks * 16, XNS * 2, lid);
                ldsm4(ah, u_xnh + fo);
                ldsm4(al, u_xnl + fo);
                #pragma unroll
                for (int j = 0; j < 8; j++) {
                    int nt = nh * 16 + jb * 8 + j;
                    uint2 B = g_w1f[(size_t)W1F_IDX(l, nt, ks) * 32 + lid];
                    mma16816(acc[j], ah, B.x, B.y);
                    mma16816(acc[j], al, B.x, B.y);
                }
            }
            #pragma unroll
            for (int j = 0; j < 8; j++) {
                int nt = nh * 16 + jb * 8 + j;
                int n0 = nt * 8 + 2 * tig;
                float v0 = acc[j][0], v1 = acc[j][1];
                if (isg) {
                    if (r0 == 0) {
                        v0 = fast_silu(v0 + gate_b[n0]);
                        v1 = fast_silu(v1 + gate_b[n0 + 1]);
                        st2(h2h, h2l, n0, v0, v1);   // h2 row 0
                    }
                } else {
                    if (l == 0 && r0 == 0) { v0 += b1[n0]; v1 += b1[n0 + 1]; }
                    if (r0 < geff)
                        st2(h1h, h1l, (mbase + r0) * GS + n0, v0, v1);
                    if (r0 + 8 < geff)
                        st2(h1h, h1l, (mbase + r0 + 8) * GS + n0, acc[j][2], acc[j][3]);
                }
            }
        }
    }

    // ---- Phase D: grid transform (16 warps = 4 mt x 4 ng); 2-product, single-fp16 A ----
    {
        const int mt = wid & 3, ng = wid >> 2;
        float acc2[8][4];
        #pragma unroll
        for (int j = 0; j < 8; j++)
            #pragma unroll
            for (int q = 0; q < 4; q++) acc2[j][q] = 0.f;

        for (int ch = 0; ch < 3; ch++) {
            __syncthreads();   // h1 ready (ch=0); prev G2 reads of g done
            // GEMM1: g[p][c] = T @ h1
            float acc1[8][4];
            #pragma unroll
            for (int j = 0; j < 8; j++)
                #pragma unroll
                for (int q = 0; q < 4; q++) acc1[j][q] = 0.f;
            #pragma unroll
            for (int ks = 0; ks < 4; ks++) {
                uint4 AH = g_a1f[(size_t)A1F_IDX(ch, mt, ks) * 32 + lid];
                uint32_t ah[4] = {AH.x, AH.y, AH.z, AH.w};
                #pragma unroll
                for (int jp = 0; jp < 4; jp++) {
                    uint32_t bh[4], bl[4];
                    uint32_t fo = frag_off(ks * 16, ng * 64 + jp * 16, GS * 2, lid);
                    ldsm4t(bh, u_h1h + fo);
                    ldsm4t(bl, u_h1l + fo);
                    mma16816(acc1[2 * jp], ah, bh[0], bh[1]);
                    mma16816(acc1[2 * jp], ah, bl[0], bl[1]);
                    mma16816(acc1[2 * jp + 1], ah, bh[2], bh[3]);
                    mma16816(acc1[2 * jp + 1], ah, bl[2], bl[3]);
                }
            }
            __syncthreads();   // all reads of g-region predecessors done before overwrite
            // epilogue: silu -> g[p][c]
            #pragma unroll
            for (int j = 0; j < 8; j++) {
                int c0 = ng * 64 + j * 8 + 2 * tig;
                int p0 = mt * 16 + r0;
                st2(ghi, glo, p0 * GS + c0, fast_silu(acc1[j][0]), fast_silu(acc1[j][1]));
                st2(ghi, glo, (p0 + 8) * GS + c0, fast_silu(acc1[j][2]), fast_silu(acc1[j][3]));
            }
            __syncthreads();   // g complete
            // GEMM2: ht[i][c] += F^T @ g
            #pragma unroll
            for (int ks = 0; ks < 4; ks++) {
                uint4 AH = g_a2f[(size_t)A1F_IDX(ch, mt, ks) * 32 + lid];
                uint32_t ah[4] = {AH.x, AH.y, AH.z, AH.w};
                #pragma unroll
                for (int jp = 0; jp < 4; jp++) {
                    uint32_t bh[4], bl[4];
                    uint32_t fo = frag_off(ks * 16, ng * 64 + jp * 16, GS * 2, lid);
                    ldsm4t(bh, u_ghi + fo);
                    ldsm4t(bl, u_glo + fo);
                    mma16816(acc2[2 * jp], ah, bh[0], bh[1]);
                    mma16816(acc2[2 * jp], ah, bl[0], bl[1]);
                    mma16816(acc2[2 * jp + 1], ah, bh[2], bh[3]);
                    mma16816(acc2[2 * jp + 1], ah, bl[2], bl[3]);
                }
            }
        }
        // D epilogue: ht rows 1..48 -> h2 (row 0 already written by gate in C)
        #pragma unroll
        for (int j = 0; j < 8; j++) {
            int c0 = ng * 64 + j * 8 + 2 * tig;
            int i0 = mt * 16 + r0, i1 = i0 + 8;
            if (i0 >= 1 && i0 <= 48)
                st2(h2h, h2l, i0 * GS + c0, acc2[j][0], acc2[j][1]);
            if (i1 <= 48)
                st2(h2h, h2l, i1 * GS + c0, acc2[j][2], acc2[j][3]);
        }
        __syncthreads();
    }

    // ---- Phase E: out = h2 @ w2^T (warps 0-13, 2 per l); 2-product fp16 ----
    if (wid < 14) {
        float* outn = out + (size_t)n * (NSH * CC);
        const int l = wid >> 1, nh = wid & 1;
        const int g = 2 * l + 1, mbase = l * l;
        float acc[8][4];
        #pragma unroll
        for (int j = 0; j < 8; j++)
            #pragma unroll
            for (int q = 0; q < 4; q++) acc[j][q] = 0.f;
        #pragma unroll 4
        for (int ks = 0; ks < 16; ks++) {
            uint32_t ah[4], al[4];
            uint32_t fo = frag_off(mbase, ks * 16, GS * 2, lid);
            ldsm4(ah, u_h2h + fo);
            ldsm4(al, u_h2l + fo);
            #pragma unroll
            for (int j = 0; j < 8; j++) {
                int nt = nh * 8 + j;
                uint2 B = g_w2f[(size_t)W2F_IDX(l, nt, ks) * 32 + lid];
                mma16816(acc[j], ah, B.x, B.y);
                mma16816(acc[j], al, B.x, B.y);
            }
        }
        #pragma unroll
        for (int j = 0; j < 8; j++) {
            int nt = nh * 8 + j;
            int n0 = nt * 8 + 2 * tig;
            float v0 = acc[j][0], v1 = acc[j][1];
            if (l == 0 && r0 == 0) { v0 += b2[n0]; v1 += b2[n0 + 1]; }
            if (r0 < g)
                *reinterpret_cast<float2*>(outn + (mbase + r0) * CC + n0) =
                    make_float2(v0, v1);
            if (r0 + 8 < g)
                *reinterpret_cast<float2*>(outn + (mbase + r0 + 8) * CC + n0) =
                    make_float2(acc[j][2], acc[j][3]);
        }
    }
}

extern "C" void kernel_launch(void* const* d_in, const int* in_sizes, int n_in,
                              void* d_out, int out_size)
{
    const float* x      = (const float*)d_in[0];
    const float* ln0_w  = (const float*)d_in[1];
    const float* ln0_b  = (const float*)d_in[2];
    const float* aff_w  = (const float*)d_in[3];
    const float* w1     = (const float*)d_in[4];
    const float* b1     = (const float*)d_in[5];
    const float* gate_w = (const float*)d_in[6];
    const float* gate_b = (const float*)d_in[7];
    const float* w2     = (const float*)d_in[8];
    const float* b2     = (const float*)d_in[9];
    const float* tg     = (const float*)d_in[10];
    const float* fg     = (const float*)d_in[11];
    float* out = (float*)d_out;

    prep_frags<<<(3936 * 32 + 255) / 256, 256>>>(w1, w2, tg, fg, gate_w);

    const int n_nodes = in_sizes[0] / (NSH * CC);
    const int smem_bytes = SMEM_FLOATS * (int)sizeof(float);
    cudaFuncSetAttribute(ffn_fused, cudaFuncAttributeMaxDynamicSharedMemorySize, smem_bytes);
    ffn_fused<<<n_nodes, 512, smem_bytes>>>(x, ln0_w, ln0_b, aff_w, b1,
                                            gate_b, b2, out);
}

// round 13
// speedup vs baseline: 3.4328x; 1.1305x over previous
#include <cuda_runtime.h>
#include <cuda_fp16.h>
#include <math.h>
#include <cstdint>

#define NSH  49
#define CC   128
#define HH   256
#define EPSV 1e-5f
#define XNS  136     // xnbf row stride (elems) -> 272B, ldsm conflict-free
#define GS   264     // h1/g/h2 row stride (elems) -> 528B, ldsm conflict-free

// ---------------- smem layout (floats) ----------------
// rbuf 0..64
// GREG @64 (16896): phase A-C: xn fp32 @64(6272) | xnbf hi @6336(4352) lo @10688(4352)
//                   phase D:   g [64 p][264 c] fp16 (hi only) @64(8448)
// h1 [64 i][264 c] fp16: hi @16960(8448) lo @25408(8448)
// h2 [64 i][264 c] fp16: hi @33856(8448) lo @42304(8448)
#define O_RBUF  0
#define O_XN    64
#define O_XNBFH 6336
#define O_XNBFL 10688
#define O_GHI   64
#define O_H1HI  16960
#define O_H1LO  25408
#define O_H2HI  33856
#define O_H2LO  42304
#define SMEM_FLOATS 50752

// fragment-linear global operand banks, all SINGLE fp16:
// w1 (l 0..6) + gate (l=7), w2: uint2 per lane (B-frags).
// a1/a2 (grid A-frags): uint4 per lane.
#define W1F_IDX(l,nt,ks)  (((l)*32 + (nt))*8 + (ks))
#define W2F_IDX(l,nt,ks)  (((l)*16 + (nt))*16 + (ks))
#define A1F_IDX(ch,mt,ks) ((((ch)*4 + (mt))*4 + (ks)))
__device__ uint2 g_w1f[2048*32];
__device__ uint2 g_w2f[1792*32];
__device__ uint4 g_a1f[48*32];
__device__ uint4 g_a2f[48*32];

__constant__ int c_ltab[NSH] = {
    0,
    1,1,1,
    2,2,2,2,2,
    3,3,3,3,3,3,3,
    4,4,4,4,4,4,4,4,4,
    5,5,5,5,5,5,5,5,5,5,5,
    6,6,6,6,6,6,6,6,6,6,6,6,6};

__constant__ float c_bal[NSH] = {
    0.0f,
    0.05555555556f,0.05555555556f,0.05555555556f,
    0.03333333333f,0.03333333333f,0.03333333333f,0.03333333333f,0.03333333333f,
    0.02380952381f,0.02380952381f,0.02380952381f,0.02380952381f,0.02380952381f,0.02380952381f,0.02380952381f,
    0.01851851852f,0.01851851852f,0.01851851852f,0.01851851852f,0.01851851852f,0.01851851852f,0.01851851852f,0.01851851852f,0.01851851852f,
    0.01515151515f,0.01515151515f,0.01515151515f,0.01515151515f,0.01515151515f,0.01515151515f,0.01515151515f,0.01515151515f,0.01515151515f,0.01515151515f,0.01515151515f,
    0.01282051282f,0.01282051282f,0.01282051282f,0.01282051282f,0.01282051282f,0.01282051282f,0.01282051282f,0.01282051282f,0.01282051282f,0.01282051282f,0.01282051282f,0.01282051282f,0.01282051282f};

__device__ __forceinline__ float fast_silu(float v) {
    return __fdividef(v, 1.0f + __expf(-v));
}
__device__ __forceinline__ uint16_t f16h(float v) {
    return __half_as_ushort(__float2half(v));
}
__device__ __forceinline__ uint16_t f16l(float v) {
    __half h = __float2half(v);
    return __half_as_ushort(__float2half(v - __half2float(h)));
}
__device__ __forceinline__ uint32_t pk(uint16_t a, uint16_t b) {
    return (uint32_t)a | ((uint32_t)b << 16);
}
__device__ __forceinline__ void st2(char* hi, char* lo, int elem_off, float a, float b) {
    *reinterpret_cast<uint32_t*>(hi + elem_off * 2) = pk(f16h(a), f16h(b));
    *reinterpret_cast<uint32_t*>(lo + elem_off * 2) = pk(f16l(a), f16l(b));
}
__device__ __forceinline__ void st1(char* hi, int elem_off, float a, float b) {
    *reinterpret_cast<uint32_t*>(hi + elem_off * 2) = pk(f16h(a), f16h(b));
}
__device__ __forceinline__ uint32_t smem_u32(const void* p) {
    uint32_t a;
    asm("{ .reg .u64 t; cvta.to.shared.u64 t, %1; cvt.u32.u64 %0, t; }" : "=r"(a) : "l"(p));
    return a;
}
__device__ __forceinline__ void mma16816(float* d, const uint32_t* a,
                                         uint32_t b0, uint32_t b1) {
    asm volatile(
        "mma.sync.aligned.m16n8k16.row.col.f32.f16.f16.f32 "
        "{%0,%1,%2,%3}, {%4,%5,%6,%7}, {%8,%9}, {%0,%1,%2,%3};\n"
        : "+f"(d[0]), "+f"(d[1]), "+f"(d[2]), "+f"(d[3])
        : "r"(a[0]), "r"(a[1]), "r"(a[2]), "r"(a[3]), "r"(b0), "r"(b1));
}
__device__ __forceinline__ void ldsm4(uint32_t* f, uint32_t a) {
    asm volatile("ldmatrix.sync.aligned.m8n8.x4.shared.b16 {%0,%1,%2,%3}, [%4];"
        : "=r"(f[0]), "=r"(f[1]), "=r"(f[2]), "=r"(f[3]) : "r"(a));
}
__device__ __forceinline__ void ldsm4t(uint32_t* f, uint32_t a) {
    asm volatile("ldmatrix.sync.aligned.m8n8.x4.trans.shared.b16 {%0,%1,%2,%3}, [%4];"
        : "=r"(f[0]), "=r"(f[1]), "=r"(f[2]), "=r"(f[3]) : "r"(a));
}
__device__ __forceinline__ uint32_t frag_off(int r_base, int c_base, int strideB, int lane) {
    int q = lane >> 3;
    return (uint32_t)((r_base + (lane & 7) + ((q & 1) << 3)) * strideB
                      + ((c_base + ((q >> 1) << 3)) << 1));
}

// ---------------- prep kernel (unchanged from R12) ----------------
__global__ void prep_frags(const float* __restrict__ w1, const float* __restrict__ w2,
                           const float* __restrict__ tg, const float* __restrict__ fg,
                           const float* __restrict__ gate_w)
{
    int t = blockIdx.x * 256 + threadIdx.x;
    if (t >= 3936 * 32) return;
    int lane = t & 31;
    int r0 = lane >> 2, tig = lane & 3;
    int fi = t >> 5;

    if (fi < 2048) {                       // w1 (l 0..6) + gate_w (l=7): single fp16
        int ks = fi & 7, nt = (fi >> 3) & 31, l = fi >> 8;
        int n = nt * 8 + r0, k = ks * 16 + 2 * tig;
        const float* s = (l < 7) ? (w1 + ((size_t)l * HH + n) * CC + k)
                                 : (gate_w + (size_t)n * CC + k);
        float v0 = s[0], v1 = s[1], v8 = s[8], v9 = s[9];
        g_w1f[(size_t)W1F_IDX(l, nt, ks) * 32 + lane] =
            make_uint2(pk(f16h(v0), f16h(v1)), pk(f16h(v8), f16h(v9)));
    } else if (fi < 3840) {                // w2: single fp16
        int fj = fi - 2048;
        int ks = fj & 15, nt = (fj >> 4) & 15, l = fj >> 8;
        int n = nt * 8 + r0, k = ks * 16 + 2 * tig;
        const float* s = w2 + ((size_t)l * CC + n) * HH + k;
        float v0 = s[0], v1 = s[1], v8 = s[8], v9 = s[9];
        g_w2f[(size_t)W2F_IDX(l, nt, ks) * 32 + lane] =
            make_uint2(pk(f16h(v0), f16h(v1)), pk(f16h(v8), f16h(v9)));
    } else if (fi < 3888) {                // a1 = to_grid [p][i]: single fp16
        int fk = fi - 3840;
        int ks = fk & 3, mt = (fk >> 2) & 3, ch = fk >> 4;
        int pa = ch * 64 + mt * 16 + r0, pb = pa + 8;
        int ia = ks * 16 + 2 * tig;
        auto val = [&](int p, int i) -> float {
            return (p < 182 && i < NSH) ? tg[p * NSH + i] : 0.f;
        };
        g_a1f[(size_t)A1F_IDX(ch, mt, ks) * 32 + lane] =
            make_uint4(pk(f16h(val(pa, ia)),     f16h(val(pa, ia + 1))),
                       pk(f16h(val(pb, ia)),     f16h(val(pb, ia + 1))),
                       pk(f16h(val(pa, ia + 8)), f16h(val(pa, ia + 9))),
                       pk(f16h(val(pb, ia + 8)), f16h(val(pb, ia + 9))));
    } else {                               // a2 = from_grid^T [i][p]: single fp16
        int fk = fi - 3888;
        int ks = fk & 3, mt = (fk >> 2) & 3, ch = fk >> 4;
        int ia = mt * 16 + r0, ib = ia + 8;
        int p0 = ch * 64 + ks * 16 + 2 * tig;
        auto val = [&](int i, int p) -> float {
            return (p < 182 && i < NSH) ? fg[p * NSH + i] : 0.f;
        };
        g_a2f[(size_t)A1F_IDX(ch, mt, ks) * 32 + lane] =
            make_uint4(pk(f16h(val(ia, p0)),     f16h(val(ia, p0 + 1))),
                       pk(f16h(val(ib, p0)),     f16h(val(ib, p0 + 1))),
                       pk(f16h(val(ia, p0 + 8)), f16h(val(ia, p0 + 9))),
                       pk(f16h(val(ib, p0 + 8)), f16h(val(ib, p0 + 9))));
    }
}

// ---------------- main kernel ----------------
__global__ void __launch_bounds__(512, 1)
ffn_fused(const float* __restrict__ x,
          const float* __restrict__ ln0_w, const float* __restrict__ ln0_b,
          const float* __restrict__ aff_w,
          const float* __restrict__ b1,
          const float* __restrict__ gate_b,
          const float* __restrict__ b2,
          float* __restrict__ out)
{
    extern __shared__ float sm[];
    float* rbuf = sm + O_RBUF;
    float* xn   = sm + O_XN;

    char* xnh = reinterpret_cast<char*>(sm + O_XNBFH);
    char* xnl = reinterpret_cast<char*>(sm + O_XNBFL);
    char* ghi = reinterpret_cast<char*>(sm + O_GHI);
    char* h1h = reinterpret_cast<char*>(sm + O_H1HI);
    char* h1l = reinterpret_cast<char*>(sm + O_H1LO);
    char* h2h = reinterpret_cast<char*>(sm + O_H2HI);
    char* h2l = reinterpret_cast<char*>(sm + O_H2LO);

    const uint32_t u0    = smem_u32(sm);
    const uint32_t u_xnh = u0 + O_XNBFH * 4, u_xnl = u0 + O_XNBFL * 4;
    const uint32_t u_ghi = u0 + O_GHI * 4;
    const uint32_t u_h1h = u0 + O_H1HI * 4,  u_h1l = u0 + O_H1LO * 4;
    const uint32_t u_h2h = u0 + O_H2HI * 4,  u_h2l = u0 + O_H2LO * 4;

    const int tid = threadIdx.x;
    const int n   = blockIdx.x;
    const int wid = tid >> 5;
    const int lid = tid & 31;
    const int r0  = lid >> 2;
    const int tig = lid & 3;

    // ---- Phase A: load x; zero h1 pad rows 49..63 only ----
    const float4* xin = reinterpret_cast<const float4*>(x + (size_t)n * (NSH * CC));
    float4* xns = reinterpret_cast<float4*>(xn);
    for (int j4 = tid; j4 < NSH * CC / 4; j4 += 512) xns[j4] = xin[j4];
    {
        float4* zh = reinterpret_cast<float4*>(sm + O_H1HI + 49 * 132);
        float4* zl = reinterpret_cast<float4*>(sm + O_H1LO + 49 * 132);
        const int cnt = (8448 - 49 * 132) / 4;
        for (int j = tid; j < cnt; j += 512) {
            zh[j] = make_float4(0, 0, 0, 0);
            zl[j] = make_float4(0, 0, 0, 0);
        }
    }
    __syncthreads();

    // ---- norms ----
    float s0 = 0.f, q0 = 0.f, sw = 0.f;
    for (int j4 = tid; j4 < NSH * CC / 4; j4 += 512) {
        float4 v = xns[j4];
        int m = j4 >> 5;
        float d = v.x * v.x + v.y * v.y + v.z * v.z + v.w * v.w;
        if (m == 0) { s0 += v.x + v.y + v.z + v.w; q0 += d; }
        else        sw += c_bal[m] * d;
    }
    #pragma unroll
    for (int o = 16; o > 0; o >>= 1) {
        s0 += __shfl_xor_sync(0xffffffffu, s0, o);
        q0 += __shfl_xor_sync(0xffffffffu, q0, o);
        sw += __shfl_xor_sync(0xffffffffu, sw, o);
    }
    if (lid == 0) { rbuf[wid] = s0; rbuf[16 + wid] = q0; rbuf[32 + wid] = sw; }
    __syncthreads();
    if (tid == 0) {
        float a = 0.f, b = 0.f, c = 0.f;
        #pragma unroll
        for (int k = 0; k < 16; k++) { a += rbuf[k]; b += rbuf[16 + k]; c += rbuf[32 + k]; }
        float muv  = a * (1.0f / CC);
        float varv = b * (1.0f / CC) - muv * muv;
        rbuf[48] = muv;
        rbuf[49] = rsqrtf(varv + EPSV);
        rbuf[50] = rsqrtf(c * (1.0f / CC) + EPSV);
    }
    __syncthreads();
    const float mu = rbuf[48], rstd = rbuf[49], inv = rbuf[50];

    // normalize (paired) -> xnbf fp16 hi/lo
    for (int j2 = tid; j2 < NSH * 64; j2 += 512) {
        int m = j2 >> 6, c2 = (j2 & 63) << 1;
        float v0 = xn[m * CC + c2], v1 = xn[m * CC + c2 + 1];
        if (m == 0) {
            v0 = (v0 - mu) * rstd * ln0_w[c2] + ln0_b[c2];
            v1 = (v1 - mu) * rstd * ln0_w[c2 + 1] + ln0_b[c2 + 1];
        } else {
            const float* aw = aff_w + (c_ltab[m] - 1) * CC;
            v0 *= inv * aw[c2]; v1 *= inv * aw[c2 + 1];
        }
        st2(xnh, xnl, m * XNS + c2, v0, v1);
    }
    __syncthreads();

    // ---- Phase C: 16 warps, l = wid>>1 (l=7 is the gate row); 2-product fp16 ----
    {
        const int l = wid >> 1, nh = wid & 1;
        const bool isg = (l == 7);
        const int geff  = isg ? 1 : 2 * l + 1;
        const int mbase = isg ? 0 : l * l;
        for (int jb = 0; jb < 2; jb++) {
            float acc[8][4];
            #pragma unroll
            for (int j = 0; j < 8; j++)
                #pragma unroll
                for (int q = 0; q < 4; q++) acc[j][q] = 0.f;
            #pragma unroll
            for (int ks = 0; ks < 8; ks++) {
                uint32_t ah[4], al[4];
                uint32_t fo = frag_off(mbase, ks * 16, XNS * 2, lid);
                ldsm4(ah, u_xnh + fo);
                ldsm4(al, u_xnl + fo);
                #pragma unroll
                for (int j = 0; j < 8; j++) {
                    int nt = nh * 16 + jb * 8 + j;
                    uint2 B = g_w1f[(size_t)W1F_IDX(l, nt, ks) * 32 + lid];
                    mma16816(acc[j], ah, B.x, B.y);
                    mma16816(acc[j], al, B.x, B.y);
                }
            }
            #pragma unroll
            for (int j = 0; j < 8; j++) {
                int nt = nh * 16 + jb * 8 + j;
                int n0 = nt * 8 + 2 * tig;
                float v0 = acc[j][0], v1 = acc[j][1];
                if (isg) {
                    if (r0 == 0) {
                        v0 = fast_silu(v0 + gate_b[n0]);
                        v1 = fast_silu(v1 + gate_b[n0 + 1]);
                        st2(h2h, h2l, n0, v0, v1);   // h2 row 0
                    }
                } else {
                    if (l == 0 && r0 == 0) { v0 += b1[n0]; v1 += b1[n0 + 1]; }
                    if (r0 < geff)
                        st2(h1h, h1l, (mbase + r0) * GS + n0, v0, v1);
                    if (r0 + 8 < geff)
                        st2(h1h, h1l, (mbase + r0 + 8) * GS + n0, acc[j][2], acc[j][3]);
                }
            }
        }
    }

    // ---- Phase D: 16 warps = 2 M-halves x 8 N-slices of 32 cols ----
    // G1 (g = T @ h1): 2-product on h1 hi/lo, single-fp16 A.
    // G2 (ht += F^T @ g): single product, g single fp16.
    {
        const int mth  = wid & 1;     // M-half: mt = 2*mth + mtl
        const int ng32 = wid >> 1;    // 32-col slice
        const int cbase = ng32 * 32;
        float acc2[2][4][4];
        #pragma unroll
        for (int m2 = 0; m2 < 2; m2++)
            #pragma unroll
            for (int j = 0; j < 4; j++)
                #pragma unroll
                for (int q = 0; q < 4; q++) acc2[m2][j][q] = 0.f;

        for (int ch = 0; ch < 3; ch++) {
            __syncthreads();   // h1 ready (ch=0); prev G2 reads of g done
            // GEMM1
            float acc1[2][4][4];
            #pragma unroll
            for (int m2 = 0; m2 < 2; m2++)
                #pragma unroll
                for (int j = 0; j < 4; j++)
                    #pragma unroll
                    for (int q = 0; q < 4; q++) acc1[m2][j][q] = 0.f;
            #pragma unroll
            for (int ks = 0; ks < 4; ks++) {
                uint32_t bh0[4], bh1[4], bl0[4], bl1[4];
                uint32_t fo0 = frag_off(ks * 16, cbase, GS * 2, lid);
                uint32_t fo1 = frag_off(ks * 16, cbase + 16, GS * 2, lid);
                ldsm4t(bh0, u_h1h + fo0);
                ldsm4t(bh1, u_h1h + fo1);
                ldsm4t(bl0, u_h1l + fo0);
                ldsm4t(bl1, u_h1l + fo1);
                #pragma unroll
                for (int m2 = 0; m2 < 2; m2++) {
                    uint4 A = g_a1f[(size_t)A1F_IDX(ch, 2 * mth + m2, ks) * 32 + lid];
                    uint32_t ah[4] = {A.x, A.y, A.z, A.w};
                    mma16816(acc1[m2][0], ah, bh0[0], bh0[1]);
                    mma16816(acc1[m2][0], ah, bl0[0], bl0[1]);
                    mma16816(acc1[m2][1], ah, bh0[2], bh0[3]);
                    mma16816(acc1[m2][1], ah, bl0[2], bl0[3]);
                    mma16816(acc1[m2][2], ah, bh1[0], bh1[1]);
                    mma16816(acc1[m2][2], ah, bl1[0], bl1[1]);
                    mma16816(acc1[m2][3], ah, bh1[2], bh1[3]);
                    mma16816(acc1[m2][3], ah, bl1[2], bl1[3]);
                }
            }
            __syncthreads();   // all G1 reads done before g overwrite
            // epilogue: silu -> g (single fp16, hi only)
            #pragma unroll
            for (int m2 = 0; m2 < 2; m2++) {
                int p0 = (2 * mth + m2) * 16 + r0;
                #pragma unroll
                for (int j = 0; j < 4; j++) {
                    int c0 = cbase + j * 8 + 2 * tig;
                    st1(ghi, p0 * GS + c0, fast_silu(acc1[m2][j][0]), fast_silu(acc1[m2][j][1]));
                    st1(ghi, (p0 + 8) * GS + c0, fast_silu(acc1[m2][j][2]), fast_silu(acc1[m2][j][3]));
                }
            }
            __syncthreads();   // g complete
            // GEMM2
            #pragma unroll
            for (int ks = 0; ks < 4; ks++) {
                uint32_t bg0[4], bg1[4];
                ldsm4t(bg0, u_ghi + frag_off(ks * 16, cbase, GS * 2, lid));
                ldsm4t(bg1, u_ghi + frag_off(ks * 16, cbase + 16, GS * 2, lid));
                #pragma unroll
                for (int m2 = 0; m2 < 2; m2++) {
                    uint4 A = g_a2f[(size_t)A1F_IDX(ch, 2 * mth + m2, ks) * 32 + lid];
                    uint32_t ah[4] = {A.x, A.y, A.z, A.w};
                    mma16816(acc2[m2][0], ah, bg0[0], bg0[1]);
                    mma16816(acc2[m2][1], ah, bg0[2], bg0[3]);
                    mma16816(acc2[m2][2], ah, bg1[0], bg1[1]);
                    mma16816(acc2[m2][3], ah, bg1[2], bg1[3]);
                }
            }
        }
        // D epilogue: ht rows 1..48 -> h2 (row 0 already written by gate in C)
        #pragma unroll
        for (int m2 = 0; m2 < 2; m2++) {
            int i0 = (2 * mth + m2) * 16 + r0, i1 = i0 + 8;
            #pragma unroll
            for (int j = 0; j < 4; j++) {
                int c0 = cbase + j * 8 + 2 * tig;
                if (i0 >= 1 && i0 <= 48)
                    st2(h2h, h2l, i0 * GS + c0, acc2[m2][j][0], acc2[m2][j][1]);
                if (i1 <= 48)
                    st2(h2h, h2l, i1 * GS + c0, acc2[m2][j][2], acc2[m2][j][3]);
            }
        }
        __syncthreads();
    }

    // ---- Phase E: out = h2 @ w2^T (warps 0-13, 2 per l); 2-product fp16 ----
    if (wid < 14) {
        float* outn = out + (size_t)n * (NSH * CC);
        const int l = wid >> 1, nh = wid & 1;
        const int g = 2 * l + 1, mbase = l * l;
        float acc[8][4];
        #pragma unroll
        for (int j = 0; j < 8; j++)
            #pragma unroll
            for (int q = 0; q < 4; q++) acc[j][q] = 0.f;
        #pragma unroll 4
        for (int ks = 0; ks < 16; ks++) {
            uint32_t ah[4], al[4];
            uint32_t fo = frag_off(mbase, ks * 16, GS * 2, lid);
            ldsm4(ah, u_h2h + fo);
            ldsm4(al, u_h2l + fo);
            #pragma unroll
            for (int j = 0; j < 8; j++) {
                int nt = nh * 8 + j;
                uint2 B = g_w2f[(size_t)W2F_IDX(l, nt, ks) * 32 + lid];
                mma16816(acc[j], ah, B.x, B.y);
                mma16816(acc[j], al, B.x, B.y);
            }
        }
        #pragma unroll
        for (int j = 0; j < 8; j++) {
            int nt = nh * 8 + j;
            int n0 = nt * 8 + 2 * tig;
            float v0 = acc[j][0], v1 = acc[j][1];
            if (l == 0 && r0 == 0) { v0 += b2[n0]; v1 += b2[n0 + 1]; }
            if (r0 < g)
                *reinterpret_cast<float2*>(outn + (mbase + r0) * CC + n0) =
                    make_float2(v0, v1);
            if (r0 + 8 < g)
                *reinterpret_cast<float2*>(outn + (mbase + r0 + 8) * CC + n0) =
                    make_float2(acc[j][2], acc[j][3]);
        }
    }
}

extern "C" void kernel_launch(void* const* d_in, const int* in_sizes, int n_in,
                              void* d_out, int out_size)
{
    const float* x      = (const float*)d_in[0];
    const float* ln0_w  = (const float*)d_in[1];
    const float* ln0_b  = (const float*)d_in[2];
    const float* aff_w  = (const float*)d_in[3];
    const float* w1     = (const float*)d_in[4];
    const float* b1     = (const float*)d_in[5];
    const float* gate_w = (const float*)d_in[6];
    const float* gate_b = (const float*)d_in[7];
    const float* w2     = (const float*)d_in[8];
    const float* b2     = (const float*)d_in[9];
    const float* tg     = (const float*)d_in[10];
    const float* fg     = (const float*)d_in[11];
    float* out = (float*)d_out;

    prep_frags<<<(3936 * 32 + 255) / 256, 256>>>(w1, w2, tg, fg, gate_w);

    const int n_nodes = in_sizes[0] / (NSH * CC);
    const int smem_bytes = SMEM_FLOATS * (int)sizeof(float);
    cudaFuncSetAttribute(ffn_fused, cudaFuncAttributeMaxDynamicSharedMemorySize, smem_bytes);
    ffn_fused<<<n_nodes, 512, smem_bytes>>>(x, ln0_w, ln0_b, aff_w, b1,
                                            gate_b, b2, out);
}

// round 14
// speedup vs baseline: 4.2120x; 1.2270x over previous
#include <cuda_runtime.h>
#include <cuda_fp16.h>
#include <math.h>
#include <cstdint>

#define NSH  49
#define CC   128
#define HH   256
#define EPSV 1e-5f
#define XNS  136     // xnbf row stride (elems) -> 272B, ldsm conflict-free
#define GS   264     // h1/g/h2 row stride (elems) -> 528B, ldsm conflict-free

// ---------------- smem layout (floats) ----------------
// rbuf 0..64
// GREG @64 (16896): phase A-C: xn fp32 @64(6272) | xnbf hi @6336(4352) lo @10688(4352)
//                   phase D:   g double-buffered fp16 [64][264]: g0 @64(8448), g1 @8512(8448)
// h1 [64 i][264 c] fp16 single: @16960 (8448)
// h2 [64 i][264 c] fp16 single: @25408 (8448)
#define O_RBUF  0
#define O_XN    64
#define O_XNBFH 6336
#define O_XNBFL 10688
#define O_G0    64
#define O_G1B   8512
#define O_H1    16960
#define O_H2    25408
#define SMEM_FLOATS 33856

// fragment-linear global operand banks, all SINGLE fp16 (unchanged from R12/R13):
#define W1F_IDX(l,nt,ks)  (((l)*32 + (nt))*8 + (ks))
#define W2F_IDX(l,nt,ks)  (((l)*16 + (nt))*16 + (ks))
#define A1F_IDX(ch,mt,ks) ((((ch)*4 + (mt))*4 + (ks)))
__device__ uint2 g_w1f[2048*32];
__device__ uint2 g_w2f[1792*32];
__device__ uint4 g_a1f[48*32];
__device__ uint4 g_a2f[48*32];

__constant__ int c_ltab[NSH] = {
    0,
    1,1,1,
    2,2,2,2,2,
    3,3,3,3,3,3,3,
    4,4,4,4,4,4,4,4,4,
    5,5,5,5,5,5,5,5,5,5,5,
    6,6,6,6,6,6,6,6,6,6,6,6,6};

__constant__ float c_bal[NSH] = {
    0.0f,
    0.05555555556f,0.05555555556f,0.05555555556f,
    0.03333333333f,0.03333333333f,0.03333333333f,0.03333333333f,0.03333333333f,
    0.02380952381f,0.02380952381f,0.02380952381f,0.02380952381f,0.02380952381f,0.02380952381f,0.02380952381f,
    0.01851851852f,0.01851851852f,0.01851851852f,0.01851851852f,0.01851851852f,0.01851851852f,0.01851851852f,0.01851851852f,0.01851851852f,
    0.01515151515f,0.01515151515f,0.01515151515f,0.01515151515f,0.01515151515f,0.01515151515f,0.01515151515f,0.01515151515f,0.01515151515f,0.01515151515f,0.01515151515f,
    0.01282051282f,0.01282051282f,0.01282051282f,0.01282051282f,0.01282051282f,0.01282051282f,0.01282051282f,0.01282051282f,0.01282051282f,0.01282051282f,0.01282051282f,0.01282051282f,0.01282051282f};

__device__ __forceinline__ float fast_silu(float v) {
    return __fdividef(v, 1.0f + __expf(-v));
}
__device__ __forceinline__ uint16_t f16h(float v) {
    return __half_as_ushort(__float2half(v));
}
__device__ __forceinline__ uint16_t f16l(float v) {
    __half h = __float2half(v);
    return __half_as_ushort(__float2half(v - __half2float(h)));
}
__device__ __forceinline__ uint32_t pk(uint16_t a, uint16_t b) {
    return (uint32_t)a | ((uint32_t)b << 16);
}
__device__ __forceinline__ void st2(char* hi, char* lo, int elem_off, float a, float b) {
    *reinterpret_cast<uint32_t*>(hi + elem_off * 2) = pk(f16h(a), f16h(b));
    *reinterpret_cast<uint32_t*>(lo + elem_off * 2) = pk(f16l(a), f16l(b));
}
__device__ __forceinline__ void st1(char* hi, int elem_off, float a, float b) {
    *reinterpret_cast<uint32_t*>(hi + elem_off * 2) = pk(f16h(a), f16h(b));
}
__device__ __forceinline__ uint32_t smem_u32(const void* p) {
    uint32_t a;
    asm("{ .reg .u64 t; cvta.to.shared.u64 t, %1; cvt.u32.u64 %0, t; }" : "=r"(a) : "l"(p));
    return a;
}
__device__ __forceinline__ void mma16816(float* d, const uint32_t* a,
                                         uint32_t b0, uint32_t b1) {
    asm volatile(
        "mma.sync.aligned.m16n8k16.row.col.f32.f16.f16.f32 "
        "{%0,%1,%2,%3}, {%4,%5,%6,%7}, {%8,%9}, {%0,%1,%2,%3};\n"
        : "+f"(d[0]), "+f"(d[1]), "+f"(d[2]), "+f"(d[3])
        : "r"(a[0]), "r"(a[1]), "r"(a[2]), "r"(a[3]), "r"(b0), "r"(b1));
}
__device__ __forceinline__ void ldsm4(uint32_t* f, uint32_t a) {
    asm volatile("ldmatrix.sync.aligned.m8n8.x4.shared.b16 {%0,%1,%2,%3}, [%4];"
        : "=r"(f[0]), "=r"(f[1]), "=r"(f[2]), "=r"(f[3]) : "r"(a));
}
__device__ __forceinline__ void ldsm4t(uint32_t* f, uint32_t a) {
    asm volatile("ldmatrix.sync.aligned.m8n8.x4.trans.shared.b16 {%0,%1,%2,%3}, [%4];"
        : "=r"(f[0]), "=r"(f[1]), "=r"(f[2]), "=r"(f[3]) : "r"(a));
}
__device__ __forceinline__ uint32_t frag_off(int r_base, int c_base, int strideB, int lane) {
    int q = lane >> 3;
    return (uint32_t)((r_base + (lane & 7) + ((q & 1) << 3)) * strideB
                      + ((c_base + ((q >> 1) << 3)) << 1));
}

// ---------------- prep kernel (unchanged from R13) ----------------
__global__ void prep_frags(const float* __restrict__ w1, const float* __restrict__ w2,
                           const float* __restrict__ tg, const float* __restrict__ fg,
                           const float* __restrict__ gate_w)
{
    int t = blockIdx.x * 256 + threadIdx.x;
    if (t >= 3936 * 32) return;
    int lane = t & 31;
    int r0 = lane >> 2, tig = lane & 3;
    int fi = t >> 5;

    if (fi < 2048) {                       // w1 (l 0..6) + gate_w (l=7): single fp16
        int ks = fi & 7, nt = (fi >> 3) & 31, l = fi >> 8;
        int n = nt * 8 + r0, k = ks * 16 + 2 * tig;
        const float* s = (l < 7) ? (w1 + ((size_t)l * HH + n) * CC + k)
                                 : (gate_w + (size_t)n * CC + k);
        float v0 = s[0], v1 = s[1], v8 = s[8], v9 = s[9];
        g_w1f[(size_t)W1F_IDX(l, nt, ks) * 32 + lane] =
            make_uint2(pk(f16h(v0), f16h(v1)), pk(f16h(v8), f16h(v9)));
    } else if (fi < 3840) {                // w2: single fp16
        int fj = fi - 2048;
        int ks = fj & 15, nt = (fj >> 4) & 15, l = fj >> 8;
        int n = nt * 8 + r0, k = ks * 16 + 2 * tig;
        const float* s = w2 + ((size_t)l * CC + n) * HH + k;
        float v0 = s[0], v1 = s[1], v8 = s[8], v9 = s[9];
        g_w2f[(size_t)W2F_IDX(l, nt, ks) * 32 + lane] =
            make_uint2(pk(f16h(v0), f16h(v1)), pk(f16h(v8), f16h(v9)));
    } else if (fi < 3888) {                // a1 = to_grid [p][i]: single fp16
        int fk = fi - 3840;
        int ks = fk & 3, mt = (fk >> 2) & 3, ch = fk >> 4;
        int pa = ch * 64 + mt * 16 + r0, pb = pa + 8;
        int ia = ks * 16 + 2 * tig;
        auto val = [&](int p, int i) -> float {
            return (p < 182 && i < NSH) ? tg[p * NSH + i] : 0.f;
        };
        g_a1f[(size_t)A1F_IDX(ch, mt, ks) * 32 + lane] =
            make_uint4(pk(f16h(val(pa, ia)),     f16h(val(pa, ia + 1))),
                       pk(f16h(val(pb, ia)),     f16h(val(pb, ia + 1))),
                       pk(f16h(val(pa, ia + 8)), f16h(val(pa, ia + 9))),
                       pk(f16h(val(pb, ia + 8)), f16h(val(pb, ia + 9))));
    } else {                               // a2 = from_grid^T [i][p]: single fp16
        int fk = fi - 3888;
        int ks = fk & 3, mt = (fk >> 2) & 3, ch = fk >> 4;
        int ia = mt * 16 + r0, ib = ia + 8;
        int p0 = ch * 64 + ks * 16 + 2 * tig;
        auto val = [&](int i, int p) -> float {
            return (p < 182 && i < NSH) ? fg[p * NSH + i] : 0.f;
        };
        g_a2f[(size_t)A1F_IDX(ch, mt, ks) * 32 + lane] =
            make_uint4(pk(f16h(val(ia, p0)),     f16h(val(ia, p0 + 1))),
                       pk(f16h(val(ib, p0)),     f16h(val(ib, p0 + 1))),
                       pk(f16h(val(ia, p0 + 8)), f16h(val(ia, p0 + 9))),
                       pk(f16h(val(ib, p0 + 8)), f16h(val(ib, p0 + 9))));
    }
}

// ---------------- main kernel ----------------
__global__ void __launch_bounds__(512, 1)
ffn_fused(const float* __restrict__ x,
          const float* __restrict__ ln0_w, const float* __restrict__ ln0_b,
          const float* __restrict__ aff_w,
          const float* __restrict__ b1,
          const float* __restrict__ gate_b,
          const float* __restrict__ b2,
          float* __restrict__ out)
{
    extern __shared__ float sm[];
    float* rbuf = sm + O_RBUF;
    float* xn   = sm + O_XN;

    char* xnh = reinterpret_cast<char*>(sm + O_XNBFH);
    char* xnl = reinterpret_cast<char*>(sm + O_XNBFL);
    char* h1b = reinterpret_cast<char*>(sm + O_H1);
    char* h2b = reinterpret_cast<char*>(sm + O_H2);

    const uint32_t u0    = smem_u32(sm);
    const uint32_t u_xnh = u0 + O_XNBFH * 4, u_xnl = u0 + O_XNBFL * 4;
    const uint32_t u_h1  = u0 + O_H1 * 4,    u_h2  = u0 + O_H2 * 4;
    const uint32_t u_g[2] = { u0 + O_G0 * 4, u0 + O_G1B * 4 };
    char* gb[2] = { reinterpret_cast<char*>(sm + O_G0),
                    reinterpret_cast<char*>(sm + O_G1B) };

    const int tid = threadIdx.x;
    const int n   = blockIdx.x;
    const int wid = tid >> 5;
    const int lid = tid & 31;
    const int r0  = lid >> 2;
    const int tig = lid & 3;

    // ---- Phase A: load x; zero h1 pad rows 49..63 ----
    const float4* xin = reinterpret_cast<const float4*>(x + (size_t)n * (NSH * CC));
    float4* xns = reinterpret_cast<float4*>(xn);
    for (int j4 = tid; j4 < NSH * CC / 4; j4 += 512) xns[j4] = xin[j4];
    {
        float4* zh = reinterpret_cast<float4*>(sm + O_H1 + 49 * 132);
        const int cnt = (8448 - 49 * 132) / 4;
        for (int j = tid; j < cnt; j += 512) zh[j] = make_float4(0, 0, 0, 0);
    }
    __syncthreads();

    // ---- norms ----
    float s0 = 0.f, q0 = 0.f, sw = 0.f;
    for (int j4 = tid; j4 < NSH * CC / 4; j4 += 512) {
        float4 v = xns[j4];
        int m = j4 >> 5;
        float d = v.x * v.x + v.y * v.y + v.z * v.z + v.w * v.w;
        if (m == 0) { s0 += v.x + v.y + v.z + v.w; q0 += d; }
        else        sw += c_bal[m] * d;
    }
    #pragma unroll
    for (int o = 16; o > 0; o >>= 1) {
        s0 += __shfl_xor_sync(0xffffffffu, s0, o);
        q0 += __shfl_xor_sync(0xffffffffu, q0, o);
        sw += __shfl_xor_sync(0xffffffffu, sw, o);
    }
    if (lid == 0) { rbuf[wid] = s0; rbuf[16 + wid] = q0; rbuf[32 + wid] = sw; }
    __syncthreads();
    if (tid == 0) {
        float a = 0.f, b = 0.f, c = 0.f;
        #pragma unroll
        for (int k = 0; k < 16; k++) { a += rbuf[k]; b += rbuf[16 + k]; c += rbuf[32 + k]; }
        float muv  = a * (1.0f / CC);
        float varv = b * (1.0f / CC) - muv * muv;
        rbuf[48] = muv;
        rbuf[49] = rsqrtf(varv + EPSV);
        rbuf[50] = rsqrtf(c * (1.0f / CC) + EPSV);
    }
    __syncthreads();
    const float mu = rbuf[48], rstd = rbuf[49], inv = rbuf[50];

    // normalize (paired) -> xnbf fp16 hi/lo
    for (int j2 = tid; j2 < NSH * 64; j2 += 512) {
        int m = j2 >> 6, c2 = (j2 & 63) << 1;
        float v0 = xn[m * CC + c2], v1 = xn[m * CC + c2 + 1];
        if (m == 0) {
            v0 = (v0 - mu) * rstd * ln0_w[c2] + ln0_b[c2];
            v1 = (v1 - mu) * rstd * ln0_w[c2 + 1] + ln0_b[c2 + 1];
        } else {
            const float* aw = aff_w + (c_ltab[m] - 1) * CC;
            v0 *= inv * aw[c2]; v1 *= inv * aw[c2 + 1];
        }
        st2(xnh, xnl, m * XNS + c2, v0, v1);
    }
    __syncthreads();

    // ---- Phase C: 16 warps, l = wid>>1 (l=7 is the gate row); 2-product fp16 A ----
    {
        const int l = wid >> 1, nh = wid & 1;
        const bool isg = (l == 7);
        const int geff  = isg ? 1 : 2 * l + 1;
        const int mbase = isg ? 0 : l * l;
        for (int jb = 0; jb < 2; jb++) {
            float acc[8][4];
            #pragma unroll
            for (int j = 0; j < 8; j++)
                #pragma unroll
                for (int q = 0; q < 4; q++) acc[j][q] = 0.f;
            #pragma unroll
            for (int ks = 0; ks < 8; ks++) {
                uint32_t ah[4], al[4];
                uint32_t fo = frag_off(mbase, ks * 16, XNS * 2, lid);
                ldsm4(ah, u_xnh + fo);
                ldsm4(al, u_xnl + fo);
                #pragma unroll
                for (int j = 0; j < 8; j++) {
                    int nt = nh * 16 + jb * 8 + j;
                    uint2 B = g_w1f[(size_t)W1F_IDX(l, nt, ks) * 32 + lid];
                    mma16816(acc[j], ah, B.x, B.y);
                    mma16816(acc[j], al, B.x, B.y);
                }
            }
            #pragma unroll
            for (int j = 0; j < 8; j++) {
                int nt = nh * 16 + jb * 8 + j;
                int n0 = nt * 8 + 2 * tig;
                float v0 = acc[j][0], v1 = acc[j][1];
                if (isg) {
                    if (r0 == 0) {
                        v0 = fast_silu(v0 + gate_b[n0]);
                        v1 = fast_silu(v1 + gate_b[n0 + 1]);
                        st1(h2b, n0, v0, v1);        // h2 row 0
                    }
                } else {
                    if (l == 0 && r0 == 0) { v0 += b1[n0]; v1 += b1[n0 + 1]; }
                    if (r0 < geff)
                        st1(h1b, (mbase + r0) * GS + n0, v0, v1);
                    if (r0 + 8 < geff)
                        st1(h1b, (mbase + r0 + 8) * GS + n0, acc[j][2], acc[j][3]);
                }
            }
        }
    }
    __syncthreads();   // h1 + h2 row 0 complete; xnbf reads done (g may overwrite)

    // ---- Phase D: 16 warps = 2 M-halves x 8 N-slices; single-fp16 everywhere;
    //      g double-buffered -> 1 sync per chunk ----
    {
        const int mth  = wid & 1;
        const int ng32 = wid >> 1;
        const int cbase = ng32 * 32;
        float acc2[2][4][4];
        #pragma unroll
        for (int m2 = 0; m2 < 2; m2++)
            #pragma unroll
            for (int j = 0; j < 4; j++)
                #pragma unroll
                for (int q = 0; q < 4; q++) acc2[m2][j][q] = 0.f;

        for (int ch = 0; ch < 3; ch++) {
            const int b = ch & 1;
            // GEMM1: g[p][c] = T @ h1 (single product)
            float acc1[2][4][4];
            #pragma unroll
            for (int m2 = 0; m2 < 2; m2++)
                #pragma unroll
                for (int j = 0; j < 4; j++)
                    #pragma unroll
                    for (int q = 0; q < 4; q++) acc1[m2][j][q] = 0.f;
            #pragma unroll
            for (int ks = 0; ks < 4; ks++) {
                uint32_t bh0[4], bh1[4];
                ldsm4t(bh0, u_h1 + frag_off(ks * 16, cbase, GS * 2, lid));
                ldsm4t(bh1, u_h1 + frag_off(ks * 16, cbase + 16, GS * 2, lid));
                #pragma unroll
                for (int m2 = 0; m2 < 2; m2++) {
                    uint4 A = g_a1f[(size_t)A1F_IDX(ch, 2 * mth + m2, ks) * 32 + lid];
                    uint32_t ah[4] = {A.x, A.y, A.z, A.w};
                    mma16816(acc1[m2][0], ah, bh0[0], bh0[1]);
                    mma16816(acc1[m2][1], ah, bh0[2], bh0[3]);
                    mma16816(acc1[m2][2], ah, bh1[0], bh1[1]);
                    mma16816(acc1[m2][3], ah, bh1[2], bh1[3]);
                }
            }
            // epilogue: silu -> g[b] (buffer last read 2 chunks + 2 barriers ago)
            #pragma unroll
            for (int m2 = 0; m2 < 2; m2++) {
                int p0 = (2 * mth + m2) * 16 + r0;
                #pragma unroll
                for (int j = 0; j < 4; j++) {
                    int c0 = cbase + j * 8 + 2 * tig;
                    st1(gb[b], p0 * GS + c0, fast_silu(acc1[m2][j][0]), fast_silu(acc1[m2][j][1]));
                    st1(gb[b], (p0 + 8) * GS + c0, fast_silu(acc1[m2][j][2]), fast_silu(acc1[m2][j][3]));
                }
            }
            __syncthreads();   // g[b] complete
            // GEMM2: ht[i][c] += F^T @ g[b] (single product)
            #pragma unroll
            for (int ks = 0; ks < 4; ks++) {
                uint32_t bg0[4], bg1[4];
                ldsm4t(bg0, u_g[b] + frag_off(ks * 16, cbase, GS * 2, lid));
                ldsm4t(bg1, u_g[b] + frag_off(ks * 16, cbase + 16, GS * 2, lid));
                #pragma unroll
                for (int m2 = 0; m2 < 2; m2++) {
                    uint4 A = g_a2f[(size_t)A1F_IDX(ch, 2 * mth + m2, ks) * 32 + lid];
                    uint32_t ah[4] = {A.x, A.y, A.z, A.w};
                    mma16816(acc2[m2][0], ah, bg0[0], bg0[1]);
                    mma16816(acc2[m2][1], ah, bg0[2], bg0[3]);
                    mma16816(acc2[m2][2], ah, bg1[0], bg1[1]);
                    mma16816(acc2[m2][3], ah, bg1[2], bg1[3]);
                }
            }
        }
        // D epilogue: ht rows 1..48 -> h2 (row 0 written by gate in C)
        #pragma unroll
        for (int m2 = 0; m2 < 2; m2++) {
            int i0 = (2 * mth + m2) * 16 + r0, i1 = i0 + 8;
            #pragma unroll
            for (int j = 0; j < 4; j++) {
                int c0 = cbase + j * 8 + 2 * tig;
                if (i0 >= 1 && i0 <= 48)
                    st1(h2b, i0 * GS + c0, acc2[m2][j][0], acc2[m2][j][1]);
                if (i1 <= 48)
                    st1(h2b, i1 * GS + c0, acc2[m2][j][2], acc2[m2][j][3]);
            }
        }
        __syncthreads();
    }

    // ---- Phase E: out = h2 @ w2^T (warps 0-13, 2 per l); single-product fp16 ----
    if (wid < 14) {
        float* outn = out + (size_t)n * (NSH * CC);
        const int l = wid >> 1, nh = wid & 1;
        const int g = 2 * l + 1, mbase = l * l;
        float acc[8][4];
        #pragma unroll
        for (int j = 0; j < 8; j++)
            #pragma unroll
            for (int q = 0; q < 4; q++) acc[j][q] = 0.f;
        #pragma unroll 4
        for (int ks = 0; ks < 16; ks++) {
            uint32_t ah[4];
            ldsm4(ah, u_h2 + frag_off(mbase, ks * 16, GS * 2, lid));
            #pragma unroll
            for (int j = 0; j < 8; j++) {
                int nt = nh * 8 + j;
                uint2 B = g_w2f[(size_t)W2F_IDX(l, nt, ks) * 32 + lid];
                mma16816(acc[j], ah, B.x, B.y);
            }
        }
        #pragma unroll
        for (int j = 0; j < 8; j++) {
            int nt = nh * 8 + j;
            int n0 = nt * 8 + 2 * tig;
            float v0 = acc[j][0], v1 = acc[j][1];
            if (l == 0 && r0 == 0) { v0 += b2[n0]; v1 += b2[n0 + 1]; }
            if (r0 < g)
                *reinterpret_cast<float2*>(outn + (mbase + r0) * CC + n0) =
                    make_float2(v0, v1);
            if (r0 + 8 < g)
                *reinterpret_cast<float2*>(outn + (mbase + r0 + 8) * CC + n0) =
                    make_float2(acc[j][2], acc[j][3]);
        }
    }
}

extern "C" void kernel_launch(void* const* d_in, const int* in_sizes, int n_in,
                              void* d_out, int out_size)
{
    const float* x      = (const float*)d_in[0];
    const float* ln0_w  = (const float*)d_in[1];
    const float* ln0_b  = (const float*)d_in[2];
    const float* aff_w  = (const float*)d_in[3];
    const float* w1     = (const float*)d_in[4];
    const float* b1     = (const float*)d_in[5];
    const float* gate_w = (const float*)d_in[6];
    const float* gate_b = (const float*)d_in[7];
    const float* w2     = (const float*)d_in[8];
    const float* b2     = (const float*)d_in[9];
    const float* tg     = (const float*)d_in[10];
    const float* fg     = (const float*)d_in[11];
    float* out = (float*)d_out;

    prep_frags<<<(3936 * 32 + 255) / 256, 256>>>(w1, w2, tg, fg, gate_w);

    const int n_nodes = in_sizes[0] / (NSH * CC);
    const int smem_bytes = SMEM_FLOATS * (int)sizeof(float);
    cudaFuncSetAttribute(ffn_fused, cudaFuncAttributeMaxDynamicSharedMemorySize, smem_bytes);
    ffn_fused<<<n_nodes, 512, smem_bytes>>>(x, ln0_w, ln0_b, aff_w, b1,
                                            gate_b, b2, out);
}

// round 15
// speedup vs baseline: 4.7977x; 1.1391x over previous
#include <cuda_runtime.h>
#include <cuda_fp16.h>
#include <math.h>
#include <cstdint>

#define NSH  49
#define CC   128
#define HH   256
#define EPSV 1e-5f
#define XNS  136     // xnbf row stride (fp16 elems) -> 272B, ldsm conflict-free
#define GS   264     // h1/g/h2 row stride (fp16 elems) -> 528B, ldsm conflict-free

// ---------------- smem layout (floats), 100.3KB -> 2 CTAs/SM ----------------
// rbuf @0 (64)
// XB   @64: phase A-C: xnbf hi @64(4352) lo @4416(4352)
//           phase D:   g fp16 [64 p][264 c] @64(8448, overlays xnbf)
// h1 [64 i][264 c] fp16 @8768 (8448)
// h2 [64 i][264 c] fp16 @17216 (8448)
#define O_RBUF  0
#define O_XNBFH 64
#define O_XNBFL 4416
#define O_G     64
#define O_H1    8768
#define O_H2    17216
#define SMEM_FLOATS 25664

// fragment-linear global operand banks, all SINGLE fp16 (unchanged):
#define W1F_IDX(l,nt,ks)  (((l)*32 + (nt))*8 + (ks))
#define W2F_IDX(l,nt,ks)  (((l)*16 + (nt))*16 + (ks))
#define A1F_IDX(ch,mt,ks) ((((ch)*4 + (mt))*4 + (ks)))
__device__ uint2 g_w1f[2048*32];
__device__ uint2 g_w2f[1792*32];
__device__ uint4 g_a1f[48*32];
__device__ uint4 g_a2f[48*32];

__constant__ int c_ltab[NSH] = {
    0,
    1,1,1,
    2,2,2,2,2,
    3,3,3,3,3,3,3,
    4,4,4,4,4,4,4,4,4,
    5,5,5,5,5,5,5,5,5,5,5,
    6,6,6,6,6,6,6,6,6,6,6,6,6};

__constant__ float c_bal[NSH] = {
    0.0f,
    0.05555555556f,0.05555555556f,0.05555555556f,
    0.03333333333f,0.03333333333f,0.03333333333f,0.03333333333f,0.03333333333f,
    0.02380952381f,0.02380952381f,0.02380952381f,0.02380952381f,0.02380952381f,0.02380952381f,0.02380952381f,
    0.01851851852f,0.01851851852f,0.01851851852f,0.01851851852f,0.01851851852f,0.01851851852f,0.01851851852f,0.01851851852f,0.01851851852f,
    0.01515151515f,0.01515151515f,0.01515151515f,0.01515151515f,0.01515151515f,0.01515151515f,0.01515151515f,0.01515151515f,0.01515151515f,0.01515151515f,0.01515151515f,
    0.01282051282f,0.01282051282f,0.01282051282f,0.01282051282f,0.01282051282f,0.01282051282f,0.01282051282f,0.01282051282f,0.01282051282f,0.01282051282f,0.01282051282f,0.01282051282f,0.01282051282f};

__device__ __forceinline__ float fast_silu(float v) {
    return __fdividef(v, 1.0f + __expf(-v));
}
__device__ __forceinline__ uint16_t f16h(float v) {
    return __half_as_ushort(__float2half(v));
}
__device__ __forceinline__ uint16_t f16l(float v) {
    __half h = __float2half(v);
    return __half_as_ushort(__float2half(v - __half2float(h)));
}
__device__ __forceinline__ uint32_t pk(uint16_t a, uint16_t b) {
    return (uint32_t)a | ((uint32_t)b << 16);
}
__device__ __forceinline__ void st2(char* hi, char* lo, int elem_off, float a, float b) {
    *reinterpret_cast<uint32_t*>(hi + elem_off * 2) = pk(f16h(a), f16h(b));
    *reinterpret_cast<uint32_t*>(lo + elem_off * 2) = pk(f16l(a), f16l(b));
}
__device__ __forceinline__ void st1(char* hi, int elem_off, float a, float b) {
    *reinterpret_cast<uint32_t*>(hi + elem_off * 2) = pk(f16h(a), f16h(b));
}
__device__ __forceinline__ uint32_t smem_u32(const void* p) {
    uint32_t a;
    asm("{ .reg .u64 t; cvta.to.shared.u64 t, %1; cvt.u32.u64 %0, t; }" : "=r"(a) : "l"(p));
    return a;
}
__device__ __forceinline__ void mma16816(float* d, const uint32_t* a,
                                         uint32_t b0, uint32_t b1) {
    asm volatile(
        "mma.sync.aligned.m16n8k16.row.col.f32.f16.f16.f32 "
        "{%0,%1,%2,%3}, {%4,%5,%6,%7}, {%8,%9}, {%0,%1,%2,%3};\n"
        : "+f"(d[0]), "+f"(d[1]), "+f"(d[2]), "+f"(d[3])
        : "r"(a[0]), "r"(a[1]), "r"(a[2]), "r"(a[3]), "r"(b0), "r"(b1));
}
__device__ __forceinline__ void ldsm4(uint32_t* f, uint32_t a) {
    asm volatile("ldmatrix.sync.aligned.m8n8.x4.shared.b16 {%0,%1,%2,%3}, [%4];"
        : "=r"(f[0]), "=r"(f[1]), "=r"(f[2]), "=r"(f[3]) : "r"(a));
}
__device__ __forceinline__ void ldsm4t(uint32_t* f, uint32_t a) {
    asm volatile("ldmatrix.sync.aligned.m8n8.x4.trans.shared.b16 {%0,%1,%2,%3}, [%4];"
        : "=r"(f[0]), "=r"(f[1]), "=r"(f[2]), "=r"(f[3]) : "r"(a));
}
__device__ __forceinline__ uint32_t frag_off(int r_base, int c_base, int strideB, int lane) {
    int q = lane >> 3;
    return (uint32_t)((r_base + (lane & 7) + ((q & 1) << 3)) * strideB
                      + ((c_base + ((q >> 1) << 3)) << 1));
}

// ---------------- prep kernel (unchanged) ----------------
__global__ void prep_frags(const float* __restrict__ w1, const float* __restrict__ w2,
                           const float* __restrict__ tg, const float* __restrict__ fg,
                           const float* __restrict__ gate_w)
{
    int t = blockIdx.x * 256 + threadIdx.x;
    if (t >= 3936 * 32) return;
    int lane = t & 31;
    int r0 = lane >> 2, tig = lane & 3;
    int fi = t >> 5;

    if (fi < 2048) {
        int ks = fi & 7, nt = (fi >> 3) & 31, l = fi >> 8;
        int n = nt * 8 + r0, k = ks * 16 + 2 * tig;
        const float* s = (l < 7) ? (w1 + ((size_t)l * HH + n) * CC + k)
                                 : (gate_w + (size_t)n * CC + k);
        float v0 = s[0], v1 = s[1], v8 = s[8], v9 = s[9];
        g_w1f[(size_t)W1F_IDX(l, nt, ks) * 32 + lane] =
            make_uint2(pk(f16h(v0), f16h(v1)), pk(f16h(v8), f16h(v9)));
    } else if (fi < 3840) {
        int fj = fi - 2048;
        int ks = fj & 15, nt = (fj >> 4) & 15, l = fj >> 8;
        int n = nt * 8 + r0, k = ks * 16 + 2 * tig;
        const float* s = w2 + ((size_t)l * CC + n) * HH + k;
        float v0 = s[0], v1 = s[1], v8 = s[8], v9 = s[9];
        g_w2f[(size_t)W2F_IDX(l, nt, ks) * 32 + lane] =
            make_uint2(pk(f16h(v0), f16h(v1)), pk(f16h(v8), f16h(v9)));
    } else if (fi < 3888) {
        int fk = fi - 3840;
        int ks = fk & 3, mt = (fk >> 2) & 3, ch = fk >> 4;
        int pa = ch * 64 + mt * 16 + r0, pb = pa + 8;
        int ia = ks * 16 + 2 * tig;
        auto val = [&](int p, int i) -> float {
            return (p < 182 && i < NSH) ? tg[p * NSH + i] : 0.f;
        };
        g_a1f[(size_t)A1F_IDX(ch, mt, ks) * 32 + lane] =
            make_uint4(pk(f16h(val(pa, ia)),     f16h(val(pa, ia + 1))),
                       pk(f16h(val(pb, ia)),     f16h(val(pb, ia + 1))),
                       pk(f16h(val(pa, ia + 8)), f16h(val(pa, ia + 9))),
                       pk(f16h(val(pb, ia + 8)), f16h(val(pb, ia + 9))));
    } else {
        int fk = fi - 3888;
        int ks = fk & 3, mt = (fk >> 2) & 3, ch = fk >> 4;
        int ia = mt * 16 + r0, ib = ia + 8;
        int p0 = ch * 64 + ks * 16 + 2 * tig;
        auto val = [&](int i, int p) -> float {
            return (p < 182 && i < NSH) ? fg[p * NSH + i] : 0.f;
        };
        g_a2f[(size_t)A1F_IDX(ch, mt, ks) * 32 + lane] =
            make_uint4(pk(f16h(val(ia, p0)),     f16h(val(ia, p0 + 1))),
                       pk(f16h(val(ib, p0)),     f16h(val(ib, p0 + 1))),
                       pk(f16h(val(ia, p0 + 8)), f16h(val(ia, p0 + 9))),
                       pk(f16h(val(ib, p0 + 8)), f16h(val(ib, p0 + 9))));
    }
}

// ---------------- main kernel: 256 threads, 2 CTAs/SM ----------------
__global__ void __launch_bounds__(256, 2)
ffn_fused(const float* __restrict__ x,
          const float* __restrict__ ln0_w, const float* __restrict__ ln0_b,
          const float* __restrict__ aff_w,
          const float* __restrict__ b1,
          const float* __restrict__ gate_b,
          const float* __restrict__ b2,
          float* __restrict__ out)
{
    extern __shared__ float sm[];
    float* rbuf = sm + O_RBUF;

    char* xnh = reinterpret_cast<char*>(sm + O_XNBFH);
    char* xnl = reinterpret_cast<char*>(sm + O_XNBFL);
    char* gbp = reinterpret_cast<char*>(sm + O_G);
    char* h1b = reinterpret_cast<char*>(sm + O_H1);
    char* h2b = reinterpret_cast<char*>(sm + O_H2);

    const uint32_t u0    = smem_u32(sm);
    const uint32_t u_xnh = u0 + O_XNBFH * 4, u_xnl = u0 + O_XNBFL * 4;
    const uint32_t u_g   = u0 + O_G * 4;
    const uint32_t u_h1  = u0 + O_H1 * 4,    u_h2  = u0 + O_H2 * 4;

    const int tid = threadIdx.x;
    const int n   = blockIdx.x;
    const int wid = tid >> 5;
    const int lid = tid & 31;
    const int r0  = lid >> 2;
    const int tig = lid & 3;

    // ---- Phase A: norms read x directly from global; zero h1 pad rows ----
    const float4* xin = reinterpret_cast<const float4*>(x + (size_t)n * (NSH * CC));
    {
        float4* zh = reinterpret_cast<float4*>(sm + O_H1 + 49 * 132);
        const int cnt = (8448 - 49 * 132) / 4;
        for (int j = tid; j < cnt; j += 256) zh[j] = make_float4(0, 0, 0, 0);
    }

    float s0 = 0.f, q0 = 0.f, sw = 0.f;
    for (int j4 = tid; j4 < NSH * CC / 4; j4 += 256) {
        float4 v = xin[j4];
        int m = j4 >> 5;
        float d = v.x * v.x + v.y * v.y + v.z * v.z + v.w * v.w;
        if (m == 0) { s0 += v.x + v.y + v.z + v.w; q0 += d; }
        else        sw += c_bal[m] * d;
    }
    #pragma unroll
    for (int o = 16; o > 0; o >>= 1) {
        s0 += __shfl_xor_sync(0xffffffffu, s0, o);
        q0 += __shfl_xor_sync(0xffffffffu, q0, o);
        sw += __shfl_xor_sync(0xffffffffu, sw, o);
    }
    if (lid == 0) { rbuf[wid] = s0; rbuf[8 + wid] = q0; rbuf[16 + wid] = sw; }
    __syncthreads();
    if (tid == 0) {
        float a = 0.f, b = 0.f, c = 0.f;
        #pragma unroll
        for (int k = 0; k < 8; k++) { a += rbuf[k]; b += rbuf[8 + k]; c += rbuf[16 + k]; }
        float muv  = a * (1.0f / CC);
        float varv = b * (1.0f / CC) - muv * muv;
        rbuf[24] = muv;
        rbuf[25] = rsqrtf(varv + EPSV);
        rbuf[26] = rsqrtf(c * (1.0f / CC) + EPSV);
    }
    __syncthreads();
    const float mu = rbuf[24], rstd = rbuf[25], inv = rbuf[26];

    // normalize: re-read x (L1/L2-hot), write xnbf fp16 hi/lo
    for (int j4 = tid; j4 < NSH * CC / 4; j4 += 256) {
        float4 v = xin[j4];
        int m = j4 >> 5, c4 = (j4 & 31) << 2;
        if (m == 0) {
            float4 w = *reinterpret_cast<const float4*>(ln0_w + c4);
            float4 b = *reinterpret_cast<const float4*>(ln0_b + c4);
            v.x = (v.x - mu) * rstd * w.x + b.x;
            v.y = (v.y - mu) * rstd * w.y + b.y;
            v.z = (v.z - mu) * rstd * w.z + b.z;
            v.w = (v.w - mu) * rstd * w.w + b.w;
        } else {
            float4 a = *reinterpret_cast<const float4*>(aff_w + (c_ltab[m] - 1) * CC + c4);
            v.x *= inv * a.x; v.y *= inv * a.y; v.z *= inv * a.z; v.w *= inv * a.w;
        }
        st2(xnh, xnl, m * XNS + c4, v.x, v.y);
        st2(xnh, xnl, m * XNS + c4 + 2, v.z, v.w);
    }
    __syncthreads();

    // ---- Phase C: 8 warps, warp = l (l=7 is gate); 2-product fp16 A ----
    {
        const int l = wid;
        const bool isg = (l == 7);
        const int geff  = isg ? 1 : 2 * l + 1;
        const int mbase = isg ? 0 : l * l;
        for (int jb = 0; jb < 4; jb++) {
            float acc[8][4];
            #pragma unroll
            for (int j = 0; j < 8; j++)
                #pragma unroll
                for (int q = 0; q < 4; q++) acc[j][q] = 0.f;
            #pragma unroll
            for (int ks = 0; ks < 8; ks++) {
                uint32_t ah[4], al[4];
                uint32_t fo = frag_off(mbase, ks * 16, XNS * 2, lid);
                ldsm4(ah, u_xnh + fo);
                ldsm4(al, u_xnl + fo);
                #pragma unroll
                for (int j = 0; j < 8; j++) {
                    int nt = jb * 8 + j;
                    uint2 B = g_w1f[(size_t)W1F_IDX(l, nt, ks) * 32 + lid];
                    mma16816(acc[j], ah, B.x, B.y);
                    mma16816(acc[j], al, B.x, B.y);
                }
            }
            #pragma unroll
            for (int j = 0; j < 8; j++) {
                int nt = jb * 8 + j;
                int n0 = nt * 8 + 2 * tig;
                float v0 = acc[j][0], v1 = acc[j][1];
                if (isg) {
                    if (r0 == 0) {
                        v0 = fast_silu(v0 + gate_b[n0]);
                        v1 = fast_silu(v1 + gate_b[n0 + 1]);
                        st1(h2b, n0, v0, v1);        // h2 row 0
                    }
                } else {
                    if (l == 0 && r0 == 0) { v0 += b1[n0]; v1 += b1[n0 + 1]; }
                    if (r0 < geff)
                        st1(h1b, (mbase + r0) * GS + n0, v0, v1);
                    if (r0 + 8 < geff)
                        st1(h1b, (mbase + r0 + 8) * GS + n0, acc[j][2], acc[j][3]);
                }
            }
        }
    }
    __syncthreads();   // h1 + h2 row 0 done; xnbf reads done (g overlays it)

    // ---- Phase D: 8 warps = 2 mth x 4 ngp; each ngp = 64 cols as 2x32 passes ----
    {
        const int mth = wid & 1;
        const int ngp = wid >> 1;
        float acc2[2][2][4][4];   // [s][m2][j][q] persistent ht accumulators
        #pragma unroll
        for (int s = 0; s < 2; s++)
            #pragma unroll
            for (int m2 = 0; m2 < 2; m2++)
                #pragma unroll
                for (int j = 0; j < 4; j++)
                    #pragma unroll
                    for (int q = 0; q < 4; q++) acc2[s][m2][j][q] = 0.f;

        for (int ch = 0; ch < 3; ch++) {
            if (ch > 0) __syncthreads();   // prev G2 reads of g done
            // GEMM1: g = silu(T @ h1), two 32-col passes
            #pragma unroll
            for (int s = 0; s < 2; s++) {
                const int cbase = ngp * 64 + s * 32;
                float acc1[2][4][4];
                #pragma unroll
                for (int m2 = 0; m2 < 2; m2++)
                    #pragma unroll
                    for (int j = 0; j < 4; j++)
                        #pragma unroll
                        for (int q = 0; q < 4; q++) acc1[m2][j][q] = 0.f;
                #pragma unroll
                for (int ks = 0; ks < 4; ks++) {
                    uint32_t bh0[4], bh1[4];
                    ldsm4t(bh0, u_h1 + frag_off(ks * 16, cbase, GS * 2, lid));
                    ldsm4t(bh1, u_h1 + frag_off(ks * 16, cbase + 16, GS * 2, lid));
                    #pragma unroll
                    for (int m2 = 0; m2 < 2; m2++) {
                        uint4 A = g_a1f[(size_t)A1F_IDX(ch, 2 * mth + m2, ks) * 32 + lid];
                        uint32_t ah[4] = {A.x, A.y, A.z, A.w};
                        mma16816(acc1[m2][0], ah, bh0[0], bh0[1]);
                        mma16816(acc1[m2][1], ah, bh0[2], bh0[3]);
                        mma16816(acc1[m2][2], ah, bh1[0], bh1[1]);
                        mma16816(acc1[m2][3], ah, bh1[2], bh1[3]);
                    }
                }
                #pragma unroll
                for (int m2 = 0; m2 < 2; m2++) {
                    int p0 = (2 * mth + m2) * 16 + r0;
                    #pragma unroll
                    for (int j = 0; j < 4; j++) {
                        int c0 = cbase + j * 8 + 2 * tig;
                        st1(gbp, p0 * GS + c0, fast_silu(acc1[m2][j][0]), fast_silu(acc1[m2][j][1]));
                        st1(gbp, (p0 + 8) * GS + c0, fast_silu(acc1[m2][j][2]), fast_silu(acc1[m2][j][3]));
                    }
                }
            }
            __syncthreads();   // g complete
            // GEMM2: ht += F^T @ g, two 32-col passes
            #pragma unroll
            for (int s = 0; s < 2; s++) {
                const int cbase = ngp * 64 + s * 32;
                #pragma unroll
                for (int ks = 0; ks < 4; ks++) {
                    uint32_t bg0[4], bg1[4];
                    ldsm4t(bg0, u_g + frag_off(ks * 16, cbase, GS * 2, lid));
                    ldsm4t(bg1, u_g + frag_off(ks * 16, cbase + 16, GS * 2, lid));
                    #pragma unroll
                    for (int m2 = 0; m2 < 2; m2++) {
                        uint4 A = g_a2f[(size_t)A1F_IDX(ch, 2 * mth + m2, ks) * 32 + lid];
                        uint32_t ah[4] = {A.x, A.y, A.z, A.w};
                        mma16816(acc2[s][m2][0], ah, bg0[0], bg0[1]);
                        mma16816(acc2[s][m2][1], ah, bg0[2], bg0[3]);
                        mma16816(acc2[s][m2][2], ah, bg1[0], bg1[1]);
                        mma16816(acc2[s][m2][3], ah, bg1[2], bg1[3]);
                    }
                }
            }
        }
        // D epilogue: ht rows 1..48 -> h2 (row 0 written by gate in C)
        #pragma unroll
        for (int s = 0; s < 2; s++) {
            #pragma unroll
            for (int m2 = 0; m2 < 2; m2++) {
                int i0 = (2 * mth + m2) * 16 + r0, i1 = i0 + 8;
                #pragma unroll
                for (int j = 0; j < 4; j++) {
                    int c0 = ngp * 64 + s * 32 + j * 8 + 2 * tig;
                    if (i0 >= 1 && i0 <= 48)
                        st1(h2b, i0 * GS + c0, acc2[s][m2][j][0], acc2[s][m2][j][1]);
                    if (i1 <= 48)
                        st1(h2b, i1 * GS + c0, acc2[s][m2][j][2], acc2[s][m2][j][3]);
                }
            }
        }
        __syncthreads();
    }

    // ---- Phase E: 8 warps; warps 0-5: l=wid (both N-halves); 6,7: split l=6 ----
    {
        float* outn = out + (size_t)n * (NSH * CC);
        const int l   = (wid < 6) ? wid : 6;
        const int nhA = (wid < 6) ? 0 : (wid - 6);
        const int nhB = (wid < 6) ? 1 : (wid - 6);
        const int g = 2 * l + 1, mbase = l * l;
        for (int nh = nhA; nh <= nhB; nh++) {
            float acc[8][4];
            #pragma unroll
            for (int j = 0; j < 8; j++)
                #pragma unroll
                for (int q = 0; q < 4; q++) acc[j][q] = 0.f;
            #pragma unroll 4
            for (int ks = 0; ks < 16; ks++) {
                uint32_t ah[4];
                ldsm4(ah, u_h2 + frag_off(mbase, ks * 16, GS * 2, lid));
                #pragma unroll
                for (int j = 0; j < 8; j++) {
                    int nt = nh * 8 + j;
                    uint2 B = g_w2f[(size_t)W2F_IDX(l, nt, ks) * 32 + lid];
                    mma16816(acc[j], ah, B.x, B.y);
                }
            }
            #pragma unroll
            for (int j = 0; j < 8; j++) {
                int nt = nh * 8 + j;
                int n0 = nt * 8 + 2 * tig;
                float v0 = acc[j][0], v1 = acc[j][1];
                if (l == 0 && r0 == 0) { v0 += b2[n0]; v1 += b2[n0 + 1]; }
                if (r0 < g)
                    *reinterpret_cast<float2*>(outn + (mbase + r0) * CC + n0) =
                        make_float2(v0, v1);
                if (r0 + 8 < g)
                    *reinterpret_cast<float2*>(outn + (mbase + r0 + 8) * CC + n0) =
                        make_float2(acc[j][2], acc[j][3]);
            }
        }
    }
}

extern "C" void kernel_launch(void* const* d_in, const int* in_sizes, int n_in,
                              void* d_out, int out_size)
{
    const float* x      = (const float*)d_in[0];
    const float* ln0_w  = (const float*)d_in[1];
    const float* ln0_b  = (const float*)d_in[2];
    const float* aff_w  = (const float*)d_in[3];
    const float* w1     = (const float*)d_in[4];
    const float* b1     = (const float*)d_in[5];
    const float* gate_w = (const float*)d_in[6];
    const float* gate_b = (const float*)d_in[7];
    const float* w2     = (const float*)d_in[8];
    const float* b2     = (const float*)d_in[9];
    const float* tg     = (const float*)d_in[10];
    const float* fg     = (const float*)d_in[11];
    float* out = (float*)d_out;

    prep_frags<<<(3936 * 32 + 255) / 256, 256>>>(w1, w2, tg, fg, gate_w);

    const int n_nodes = in_sizes[0] / (NSH * CC);
    const int smem_bytes = SMEM_FLOATS * (int)sizeof(float);
    cudaFuncSetAttribute(ffn_fused, cudaFuncAttributeMaxDynamicSharedMemorySize, smem_bytes);
    ffn_fused<<<n_nodes, 256, smem_bytes>>>(x, ln0_w, ln0_b, aff_w, b1,
                                            gate_b, b2, out);
}

// round 16
// speedup vs baseline: 4.8170x; 1.0040x over previous
#include <cuda_runtime.h>
#include <cuda_fp16.h>
#include <math.h>
#include <cstdint>

#define NSH  49
#define CC   128
#define HH   256
#define EPSV 1e-5f
#define XNS  136     // xnbf row stride (fp16 elems) -> 272B, ldsm conflict-free
#define GS   264     // h1/g/h2 row stride (fp16 elems) -> 528B, ldsm conflict-free

// ---------------- smem layout (floats), <100KB -> 2 CTAs/SM ----------------
// rbuf @0 (64)
// XB @64: phase A-C: xnbf fp16 single @64 (4352)
//         phase D:   g fp16 [64 p][264 c] @64 (8448, overlays xnbf)
// h1 [64 i][264 c] fp16 @8768 (8448)
// h2 [64 i][264 c] fp16 @17216 (8448)
#define O_RBUF  0
#define O_XNBFH 64
#define O_G     64
#define O_H1    8768
#define O_H2    17216
#define SMEM_FLOATS 25664

// fragment-linear global operand banks, all SINGLE fp16:
#define W1F_IDX(l,nt,ks)  (((l)*32 + (nt))*8 + (ks))
#define W2F_IDX(l,nt,ks)  (((l)*16 + (nt))*16 + (ks))
#define A1F_IDX(ch,mt,ks) ((((ch)*4 + (mt))*4 + (ks)))
__device__ uint2 g_w1f[2048*32];
__device__ uint2 g_w2f[1792*32];
__device__ uint4 g_a1f[48*32];
__device__ uint4 g_a2f[48*32];

__constant__ int c_ltab[NSH] = {
    0,
    1,1,1,
    2,2,2,2,2,
    3,3,3,3,3,3,3,
    4,4,4,4,4,4,4,4,4,
    5,5,5,5,5,5,5,5,5,5,5,
    6,6,6,6,6,6,6,6,6,6,6,6,6};

__constant__ float c_bal[NSH] = {
    0.0f,
    0.05555555556f,0.05555555556f,0.05555555556f,
    0.03333333333f,0.03333333333f,0.03333333333f,0.03333333333f,0.03333333333f,
    0.02380952381f,0.02380952381f,0.02380952381f,0.02380952381f,0.02380952381f,0.02380952381f,0.02380952381f,
    0.01851851852f,0.01851851852f,0.01851851852f,0.01851851852f,0.01851851852f,0.01851851852f,0.01851851852f,0.01851851852f,0.01851851852f,
    0.01515151515f,0.01515151515f,0.01515151515f,0.01515151515f,0.01515151515f,0.01515151515f,0.01515151515f,0.01515151515f,0.01515151515f,0.01515151515f,0.01515151515f,
    0.01282051282f,0.01282051282f,0.01282051282f,0.01282051282f,0.01282051282f,0.01282051282f,0.01282051282f,0.01282051282f,0.01282051282f,0.01282051282f,0.01282051282f,0.01282051282f,0.01282051282f};

__device__ __forceinline__ float fast_silu(float v) {
    return __fdividef(v, 1.0f + __expf(-v));
}
__device__ __forceinline__ uint16_t f16h(float v) {
    return __half_as_ushort(__float2half(v));
}
__device__ __forceinline__ uint32_t pk(uint16_t a, uint16_t b) {
    return (uint32_t)a | ((uint32_t)b << 16);
}
__device__ __forceinline__ void st1(char* hi, int elem_off, float a, float b) {
    *reinterpret_cast<uint32_t*>(hi + elem_off * 2) = pk(f16h(a), f16h(b));
}
__device__ __forceinline__ uint32_t smem_u32(const void* p) {
    uint32_t a;
    asm("{ .reg .u64 t; cvta.to.shared.u64 t, %1; cvt.u32.u64 %0, t; }" : "=r"(a) : "l"(p));
    return a;
}
__device__ __forceinline__ void mma16816(float* d, const uint32_t* a,
                                         uint32_t b0, uint32_t b1) {
    asm volatile(
        "mma.sync.aligned.m16n8k16.row.col.f32.f16.f16.f32 "
        "{%0,%1,%2,%3}, {%4,%5,%6,%7}, {%8,%9}, {%0,%1,%2,%3};\n"
        : "+f"(d[0]), "+f"(d[1]), "+f"(d[2]), "+f"(d[3])
        : "r"(a[0]), "r"(a[1]), "r"(a[2]), "r"(a[3]), "r"(b0), "r"(b1));
}
__device__ __forceinline__ void ldsm4(uint32_t* f, uint32_t a) {
    asm volatile("ldmatrix.sync.aligned.m8n8.x4.shared.b16 {%0,%1,%2,%3}, [%4];"
        : "=r"(f[0]), "=r"(f[1]), "=r"(f[2]), "=r"(f[3]) : "r"(a));
}
__device__ __forceinline__ void ldsm4t(uint32_t* f, uint32_t a) {
    asm volatile("ldmatrix.sync.aligned.m8n8.x4.trans.shared.b16 {%0,%1,%2,%3}, [%4];"
        : "=r"(f[0]), "=r"(f[1]), "=r"(f[2]), "=r"(f[3]) : "r"(a));
}
__device__ __forceinline__ uint32_t frag_off(int r_base, int c_base, int strideB, int lane) {
    int q = lane >> 3;
    return (uint32_t)((r_base + (lane & 7) + ((q & 1) << 3)) * strideB
                      + ((c_base + ((q >> 1) << 3)) << 1));
}

// ---------------- prep kernel ----------------
__global__ void prep_frags(const float* __restrict__ w1, const float* __restrict__ w2,
                           const float* __restrict__ tg, const float* __restrict__ fg,
                           const float* __restrict__ gate_w)
{
    int t = blockIdx.x * 256 + threadIdx.x;
    if (t >= 3936 * 32) return;
    int lane = t & 31;
    int r0 = lane >> 2, tig = lane & 3;
    int fi = t >> 5;

    if (fi < 2048) {
        int ks = fi & 7, nt = (fi >> 3) & 31, l = fi >> 8;
        int n = nt * 8 + r0, k = ks * 16 + 2 * tig;
        const float* s = (l < 7) ? (w1 + ((size_t)l * HH + n) * CC + k)
                                 : (gate_w + (size_t)n * CC + k);
        float v0 = s[0], v1 = s[1], v8 = s[8], v9 = s[9];
        g_w1f[W1F_IDX(l, nt, ks) * 32 + lane] =
            make_uint2(pk(f16h(v0), f16h(v1)), pk(f16h(v8), f16h(v9)));
    } else if (fi < 3840) {
        int fj = fi - 2048;
        int ks = fj & 15, nt = (fj >> 4) & 15, l = fj >> 8;
        int n = nt * 8 + r0, k = ks * 16 + 2 * tig;
        const float* s = w2 + ((size_t)l * CC + n) * HH + k;
        float v0 = s[0], v1 = s[1], v8 = s[8], v9 = s[9];
        g_w2f[W2F_IDX(l, nt, ks) * 32 + lane] =
            make_uint2(pk(f16h(v0), f16h(v1)), pk(f16h(v8), f16h(v9)));
    } else if (fi < 3888) {
        int fk = fi - 3840;
        int ks = fk & 3, mt = (fk >> 2) & 3, ch = fk >> 4;
        int pa = ch * 64 + mt * 16 + r0, pb = pa + 8;
        int ia = ks * 16 + 2 * tig;
        auto val = [&](int p, int i) -> float {
            return (p < 182 && i < NSH) ? tg[p * NSH + i] : 0.f;
        };
        g_a1f[A1F_IDX(ch, mt, ks) * 32 + lane] =
            make_uint4(pk(f16h(val(pa, ia)),     f16h(val(pa, ia + 1))),
                       pk(f16h(val(pb, ia)),     f16h(val(pb, ia + 1))),
                       pk(f16h(val(pa, ia + 8)), f16h(val(pa, ia + 9))),
                       pk(f16h(val(pb, ia + 8)), f16h(val(pb, ia + 9))));
    } else {
        int fk = fi - 3888;
        int ks = fk & 3, mt = (fk >> 2) & 3, ch = fk >> 4;
        int ia = mt * 16 + r0, ib = ia + 8;
        int p0 = ch * 64 + ks * 16 + 2 * tig;
        auto val = [&](int i, int p) -> float {
            return (p < 182 && i < NSH) ? fg[p * NSH + i] : 0.f;
        };
        g_a2f[A1F_IDX(ch, mt, ks) * 32 + lane] =
            make_uint4(pk(f16h(val(ia, p0)),     f16h(val(ia, p0 + 1))),
                       pk(f16h(val(ib, p0)),     f16h(val(ib, p0 + 1))),
                       pk(f16h(val(ia, p0 + 8)), f16h(val(ia, p0 + 9))),
                       pk(f16h(val(ib, p0 + 8)), f16h(val(ib, p0 + 9))));
    }
}

// ---------------- main kernel: 256 threads, 2 CTAs/SM ----------------
__global__ void __launch_bounds__(256, 2)
ffn_fused(const float* __restrict__ x,
          const float* __restrict__ ln0_w, const float* __restrict__ ln0_b,
          const float* __restrict__ aff_w,
          const float* __restrict__ b1,
          const float* __restrict__ gate_b,
          const float* __restrict__ b2,
          float* __restrict__ out)
{
    extern __shared__ float sm[];
    float* rbuf = sm + O_RBUF;

    char* xnh = reinterpret_cast<char*>(sm + O_XNBFH);
    char* gbp = reinterpret_cast<char*>(sm + O_G);
    char* h1b = reinterpret_cast<char*>(sm + O_H1);
    char* h2b = reinterpret_cast<char*>(sm + O_H2);

    const uint32_t u0    = smem_u32(sm);
    const uint32_t u_xnh = u0 + O_XNBFH * 4;
    const uint32_t u_g   = u0 + O_G * 4;
    const uint32_t u_h1  = u0 + O_H1 * 4, u_h2 = u0 + O_H2 * 4;

    const int tid = threadIdx.x;
    const int n   = blockIdx.x;
    const int wid = tid >> 5;
    const int lid = tid & 31;
    const int r0  = lid >> 2;
    const int tig = lid & 3;

    // ---- Phase A: norms read x from global; zero h1 pad rows ----
    const float4* xin = reinterpret_cast<const float4*>(x + (size_t)n * (NSH * CC));
    {
        float4* zh = reinterpret_cast<float4*>(sm + O_H1 + 49 * 132);
        const int cnt = (8448 - 49 * 132) / 4;
        for (int j = tid; j < cnt; j += 256) zh[j] = make_float4(0, 0, 0, 0);
    }

    float s0 = 0.f, q0 = 0.f, sw = 0.f;
    for (int j4 = tid; j4 < NSH * CC / 4; j4 += 256) {
        float4 v = xin[j4];
        int m = j4 >> 5;
        float d = v.x * v.x + v.y * v.y + v.z * v.z + v.w * v.w;
        if (m == 0) { s0 += v.x + v.y + v.z + v.w; q0 += d; }
        else        sw += c_bal[m] * d;
    }
    #pragma unroll
    for (int o = 16; o > 0; o >>= 1) {
        s0 += __shfl_xor_sync(0xffffffffu, s0, o);
        q0 += __shfl_xor_sync(0xffffffffu, q0, o);
        sw += __shfl_xor_sync(0xffffffffu, sw, o);
    }
    if (lid == 0) { rbuf[wid] = s0; rbuf[8 + wid] = q0; rbuf[16 + wid] = sw; }
    __syncthreads();
    if (tid == 0) {
        float a = 0.f, b = 0.f, c = 0.f;
        #pragma unroll
        for (int k = 0; k < 8; k++) { a += rbuf[k]; b += rbuf[8 + k]; c += rbuf[16 + k]; }
        float muv  = a * (1.0f / CC);
        float varv = b * (1.0f / CC) - muv * muv;
        rbuf[24] = muv;
        rbuf[25] = rsqrtf(varv + EPSV);
        rbuf[26] = rsqrtf(c * (1.0f / CC) + EPSV);
    }
    __syncthreads();
    const float mu = rbuf[24], rstd = rbuf[25], inv = rbuf[26];

    // normalize: re-read x (L1/L2-hot), write xnbf single fp16
    for (int j4 = tid; j4 < NSH * CC / 4; j4 += 256) {
        float4 v = xin[j4];
        int m = j4 >> 5, c4 = (j4 & 31) << 2;
        if (m == 0) {
            float4 w = *reinterpret_cast<const float4*>(ln0_w + c4);
            float4 b = *reinterpret_cast<const float4*>(ln0_b + c4);
            v.x = (v.x - mu) * rstd * w.x + b.x;
            v.y = (v.y - mu) * rstd * w.y + b.y;
            v.z = (v.z - mu) * rstd * w.z + b.z;
            v.w = (v.w - mu) * rstd * w.w + b.w;
        } else {
            float4 a = *reinterpret_cast<const float4*>(aff_w + (c_ltab[m] - 1) * CC + c4);
            v.x *= inv * a.x; v.y *= inv * a.y; v.z *= inv * a.z; v.w *= inv * a.w;
        }
        st1(xnh, m * XNS + c4, v.x, v.y);
        st1(xnh, m * XNS + c4 + 2, v.z, v.w);
    }
    __syncthreads();

    // ---- Phase C: 8 warps, warp = l (l=7 is gate); single-product, A hoisted ----
    {
        const int l = wid;
        const bool isg = (l == 7);
        const int geff  = isg ? 1 : 2 * l + 1;
        const int mbase = isg ? 0 : l * l;
        uint32_t ah[8][4];
        #pragma unroll
        for (int ks = 0; ks < 8; ks++)
            ldsm4(ah[ks], u_xnh + frag_off(mbase, ks * 16, XNS * 2, lid));
        const uint2* w1p = g_w1f + W1F_IDX(l, 0, 0) * 32 + lid;
        for (int jb = 0; jb < 4; jb++) {
            float acc[8][4];
            #pragma unroll
            for (int j = 0; j < 8; j++)
                #pragma unroll
                for (int q = 0; q < 4; q++) acc[j][q] = 0.f;
            #pragma unroll
            for (int ks = 0; ks < 8; ks++) {
                #pragma unroll
                for (int j = 0; j < 8; j++) {
                    uint2 B = w1p[((jb * 8 + j) * 8 + ks) * 32];
                    mma16816(acc[j], ah[ks], B.x, B.y);
                }
            }
            #pragma unroll
            for (int j = 0; j < 8; j++) {
                int nt = jb * 8 + j;
                int n0 = nt * 8 + 2 * tig;
                float v0 = acc[j][0], v1 = acc[j][1];
                if (isg) {
                    if (r0 == 0) {
                        v0 = fast_silu(v0 + gate_b[n0]);
                        v1 = fast_silu(v1 + gate_b[n0 + 1]);
                        st1(h2b, n0, v0, v1);        // h2 row 0
                    }
                } else {
                    if (l == 0 && r0 == 0) { v0 += b1[n0]; v1 += b1[n0 + 1]; }
                    if (r0 < geff)
                        st1(h1b, (mbase + r0) * GS + n0, v0, v1);
                    if (r0 + 8 < geff)
                        st1(h1b, (mbase + r0 + 8) * GS + n0, acc[j][2], acc[j][3]);
                }
            }
        }
    }
    __syncthreads();   // h1 + h2 row 0 done; xnbf reads done (g overlays it)

    // ---- Phase D: 8 warps = 2 mth x 4 ngp; each ngp = 64 cols as 2x32 passes ----
    {
        const int mth = wid & 1;
        const int ngp = wid >> 1;
        const uint4* a1p = g_a1f + lid;
        const uint4* a2p = g_a2f + lid;
        float acc2[2][2][4][4];
        #pragma unroll
        for (int s = 0; s < 2; s++)
            #pragma unroll
            for (int m2 = 0; m2 < 2; m2++)
                #pragma unroll
                for (int j = 0; j < 4; j++)
                    #pragma unroll
                    for (int q = 0; q < 4; q++) acc2[s][m2][j][q] = 0.f;

        for (int ch = 0; ch < 3; ch++) {
            if (ch > 0) __syncthreads();   // prev G2 reads of g done
            const int abase = (ch * 4 + 2 * mth) * 4;
            // GEMM1: g = silu(T @ h1), two 32-col passes
            #pragma unroll
            for (int s = 0; s < 2; s++) {
                const int cbase = ngp * 64 + s * 32;
                float acc1[2][4][4];
                #pragma unroll
                for (int m2 = 0; m2 < 2; m2++)
                    #pragma unroll
                    for (int j = 0; j < 4; j++)
                        #pragma unroll
                        for (int q = 0; q < 4; q++) acc1[m2][j][q] = 0.f;
                #pragma unroll
                for (int ks = 0; ks < 4; ks++) {
                    uint32_t bh0[4], bh1[4];
                    ldsm4t(bh0, u_h1 + frag_off(ks * 16, cbase, GS * 2, lid));
                    ldsm4t(bh1, u_h1 + frag_off(ks * 16, cbase + 16, GS * 2, lid));
                    #pragma unroll
                    for (int m2 = 0; m2 < 2; m2++) {
                        uint4 A = a1p[((abase + m2 * 4) + ks) * 32];
                        uint32_t ah[4] = {A.x, A.y, A.z, A.w};
                        mma16816(acc1[m2][0], ah, bh0[0], bh0[1]);
                        mma16816(acc1[m2][1], ah, bh0[2], bh0[3]);
                        mma16816(acc1[m2][2], ah, bh1[0], bh1[1]);
                        mma16816(acc1[m2][3], ah, bh1[2], bh1[3]);
                    }
                }
                #pragma unroll
                for (int m2 = 0; m2 < 2; m2++) {
                    int p0 = (2 * mth + m2) * 16 + r0;
                    #pragma unroll
                    for (int j = 0; j < 4; j++) {
                        int c0 = cbase + j * 8 + 2 * tig;
                        st1(gbp, p0 * GS + c0, fast_silu(acc1[m2][j][0]), fast_silu(acc1[m2][j][1]));
                        st1(gbp, (p0 + 8) * GS + c0, fast_silu(acc1[m2][j][2]), fast_silu(acc1[m2][j][3]));
                    }
                }
            }
            __syncthreads();   // g complete
            // GEMM2: ht += F^T @ g, two 32-col passes
            #pragma unroll
            for (int s = 0; s < 2; s++) {
                const int cbase = ngp * 64 + s * 32;
                #pragma unroll
                for (int ks = 0; ks < 4; ks++) {
                    uint32_t bg0[4], bg1[4];
                    ldsm4t(bg0, u_g + frag_off(ks * 16, cbase, GS * 2, lid));
                    ldsm4t(bg1, u_g + frag_off(ks * 16, cbase + 16, GS * 2, lid));
                    #pragma unroll
                    for (int m2 = 0; m2 < 2; m2++) {
                        uint4 A = a2p[((abase + m2 * 4) + ks) * 32];
                        uint32_t ah[4] = {A.x, A.y, A.z, A.w};
                        mma16816(acc2[s][m2][0], ah, bg0[0], bg0[1]);
                        mma16816(acc2[s][m2][1], ah, bg0[2], bg0[3]);
                        mma16816(acc2[s][m2][2], ah, bg1[0], bg1[1]);
                        mma16816(acc2[s][m2][3], ah, bg1[2], bg1[3]);
                    }
                }
            }
        }
        // D epilogue: ht rows 1..48 -> h2 (row 0 written by gate in C)
        #pragma unroll
        for (int s = 0; s < 2; s++) {
            #pragma unroll
            for (int m2 = 0; m2 < 2; m2++) {
                int i0 = (2 * mth + m2) * 16 + r0, i1 = i0 + 8;
                #pragma unroll
                for (int j = 0; j < 4; j++) {
                    int c0 = ngp * 64 + s * 32 + j * 8 + 2 * tig;
                    if (i0 >= 1 && i0 <= 48)
                        st1(h2b, i0 * GS + c0, acc2[s][m2][j][0], acc2[s][m2][j][1]);
                    if (i1 <= 48)
                        st1(h2b, i1 * GS + c0, acc2[s][m2][j][2], acc2[s][m2][j][3]);
                }
            }
        }
        __syncthreads();
    }

    // ---- Phase E: 8 warps; 0-5: l=wid both N-halves; 6,7 split l=6; A hoisted ----
    {
        float* outn = out + (size_t)n * (NSH * CC);
        const int l   = (wid < 6) ? wid : 6;
        const int nhA = (wid < 6) ? 0 : (wid - 6);
        const int nhB = (wid < 6) ? 1 : (wid - 6);
        const int g = 2 * l + 1, mbase = l * l;
        uint32_t ah[16][4];
        #pragma unroll
        for (int ks = 0; ks < 16; ks++)
            ldsm4(ah[ks], u_h2 + frag_off(mbase, ks * 16, GS * 2, lid));
        const uint2* w2p = g_w2f + W2F_IDX(l, 0, 0) * 32 + lid;
        for (int nh = nhA; nh <= nhB; nh++) {
            float acc[8][4];
            #pragma unroll
            for (int j = 0; j < 8; j++)
                #pragma unroll
                for (int q = 0; q < 4; q++) acc[j][q] = 0.f;
            #pragma unroll 4
            for (int ks = 0; ks < 16; ks++) {
                #pragma unroll
                for (int j = 0; j < 8; j++) {
                    uint2 B = w2p[((nh * 8 + j) * 16 + ks) * 32];
                    mma16816(acc[j], ah[ks], B.x, B.y);
                }
            }
            #pragma unroll
            for (int j = 0; j < 8; j++) {
                int nt = nh * 8 + j;
                int n0 = nt * 8 + 2 * tig;
                float v0 = acc[j][0], v1 = acc[j][1];
                if (l == 0 && r0 == 0) { v0 += b2[n0]; v1 += b2[n0 + 1]; }
                if (r0 < g)
                    *reinterpret_cast<float2*>(outn + (mbase + r0) * CC + n0) =
                        make_float2(v0, v1);
                if (r0 + 8 < g)
                    *reinterpret_cast<float2*>(outn + (mbase + r0 + 8) * CC + n0) =
                        make_float2(acc[j][2], acc[j][3]);
            }
        }
    }
}

extern "C" void kernel_launch(void* const* d_in, const int* in_sizes, int n_in,
                              void* d_out, int out_size)
{
    const float* x      = (const float*)d_in[0];
    const float* ln0_w  = (const float*)d_in[1];
    const float* ln0_b  = (const float*)d_in[2];
    const float* aff_w  = (const float*)d_in[3];
    const float* w1     = (const float*)d_in[4];
    const float* b1     = (const float*)d_in[5];
    const float* gate_w = (const float*)d_in[6];
    const float* gate_b = (const float*)d_in[7];
    const float* w2     = (const float*)d_in[8];
    const float* b2     = (const float*)d_in[9];
    const float* tg     = (const float*)d_in[10];
    const float* fg     = (const float*)d_in[11];
    float* out = (float*)d_out;

    prep_frags<<<(3936 * 32 + 255) / 256, 256>>>(w1, w2, tg, fg, gate_w);

    const int n_nodes = in_sizes[0] / (NSH * CC);
    const int smem_bytes = SMEM_FLOATS * (int)sizeof(float);
    cudaFuncSetAttribute(ffn_fused, cudaFuncAttributeMaxDynamicSharedMemorySize, smem_bytes);
    ffn_fused<<<n_nodes, 256, smem_bytes>>>(x, ln0_w, ln0_b, aff_w, b1,
                                            gate_b, b2, out);
}

// round 17
// speedup vs baseline: 6.0241x; 1.2506x over previous
#include <cuda_runtime.h>
#include <cuda_fp16.h>
#include <math.h>
#include <cstdint>

#define NSH  49
#define CC   128
#define HH   256
#define EPSV 1e-5f
#define XNS  136     // xnbf row stride (fp16 elems) -> 272B
#define GS   264     // h1/g/h2 row stride (fp16 elems) -> 528B

// ---------------- smem layout (floats), 102.6KB -> 2 CTAs/SM ----------------
// rbuf @0 (64: node0 @0..26, node1 @32..58)
// gstash @64 (256 floats = 2 nodes x 256 fp16)
// XG @320: phase A-C: xnbf_A @320 (3552), xnbf_B @3872 (3552)
//          phase D:   g fp16 [64 p][264 c] @320 (8448)
// h1A/h2A [64][264] fp16 @8768 (8448)   (h2 overlays h1 after D)
// h1B/h2B [64][264] fp16 @17216 (8448)
#define O_RBUF  0
#define O_GATES 64
#define O_XA    320
#define O_XB2   3872
#define O_G     320
#define O_H1A   8768
#define O_H1B   17216
#define SMEM_FLOATS 25664

// fragment-linear global operand banks, all SINGLE fp16:
#define W1F_IDX(l,nt,ks)  (((l)*32 + (nt))*8 + (ks))
#define W2F_IDX(l,nt,ks)  (((l)*16 + (nt))*16 + (ks))
#define A1F_IDX(ch,mt,ks) ((((ch)*4 + (mt))*4 + (ks)))
__device__ uint2 g_w1f[2048*32];
__device__ uint2 g_w2f[1792*32];
__device__ uint4 g_a1f[48*32];
__device__ uint4 g_a2f[48*32];

__constant__ int c_ltab[NSH] = {
    0,
    1,1,1,
    2,2,2,2,2,
    3,3,3,3,3,3,3,
    4,4,4,4,4,4,4,4,4,
    5,5,5,5,5,5,5,5,5,5,5,
    6,6,6,6,6,6,6,6,6,6,6,6,6};

__constant__ float c_bal[NSH] = {
    0.0f,
    0.05555555556f,0.05555555556f,0.05555555556f,
    0.03333333333f,0.03333333333f,0.03333333333f,0.03333333333f,0.03333333333f,
    0.02380952381f,0.02380952381f,0.02380952381f,0.02380952381f,0.02380952381f,0.02380952381f,0.02380952381f,
    0.01851851852f,0.01851851852f,0.01851851852f,0.01851851852f,0.01851851852f,0.01851851852f,0.01851851852f,0.01851851852f,0.01851851852f,
    0.01515151515f,0.01515151515f,0.01515151515f,0.01515151515f,0.01515151515f,0.01515151515f,0.01515151515f,0.01515151515f,0.01515151515f,0.01515151515f,0.01515151515f,
    0.01282051282f,0.01282051282f,0.01282051282f,0.01282051282f,0.01282051282f,0.01282051282f,0.01282051282f,0.01282051282f,0.01282051282f,0.01282051282f,0.01282051282f,0.01282051282f,0.01282051282f};

__device__ __forceinline__ float fast_silu(float v) {
    return __fdividef(v, 1.0f + __expf(-v));
}
__device__ __forceinline__ uint16_t f16h(float v) {
    return __half_as_ushort(__float2half(v));
}
__device__ __forceinline__ uint32_t pk(uint16_t a, uint16_t b) {
    return (uint32_t)a | ((uint32_t)b << 16);
}
__device__ __forceinline__ void st1(char* hi, int elem_off, float a, float b) {
    *reinterpret_cast<uint32_t*>(hi + elem_off * 2) = pk(f16h(a), f16h(b));
}
__device__ __forceinline__ uint32_t smem_u32(const void* p) {
    uint32_t a;
    asm("{ .reg .u64 t; cvta.to.shared.u64 t, %1; cvt.u32.u64 %0, t; }" : "=r"(a) : "l"(p));
    return a;
}
__device__ __forceinline__ void mma16816(float* d, const uint32_t* a,
                                         uint32_t b0, uint32_t b1) {
    asm volatile(
        "mma.sync.aligned.m16n8k16.row.col.f32.f16.f16.f32 "
        "{%0,%1,%2,%3}, {%4,%5,%6,%7}, {%8,%9}, {%0,%1,%2,%3};\n"
        : "+f"(d[0]), "+f"(d[1]), "+f"(d[2]), "+f"(d[3])
        : "r"(a[0]), "r"(a[1]), "r"(a[2]), "r"(a[3]), "r"(b0), "r"(b1));
}
__device__ __forceinline__ void ldsm4(uint32_t* f, uint32_t a) {
    asm volatile("ldmatrix.sync.aligned.m8n8.x4.shared.b16 {%0,%1,%2,%3}, [%4];"
        : "=r"(f[0]), "=r"(f[1]), "=r"(f[2]), "=r"(f[3]) : "r"(a));
}
__device__ __forceinline__ void ldsm4t(uint32_t* f, uint32_t a) {
    asm volatile("ldmatrix.sync.aligned.m8n8.x4.trans.shared.b16 {%0,%1,%2,%3}, [%4];"
        : "=r"(f[0]), "=r"(f[1]), "=r"(f[2]), "=r"(f[3]) : "r"(a));
}
__device__ __forceinline__ uint32_t frag_off(int r_base, int c_base, int strideB, int lane) {
    int q = lane >> 3;
    return (uint32_t)((r_base + (lane & 7) + ((q & 1) << 3)) * strideB
                      + ((c_base + ((q >> 1) << 3)) << 1));
}

// ---------------- prep kernel (unchanged) ----------------
__global__ void prep_frags(const float* __restrict__ w1, const float* __restrict__ w2,
                           const float* __restrict__ tg, const float* __restrict__ fg,
                           const float* __restrict__ gate_w)
{
    int t = blockIdx.x * 256 + threadIdx.x;
    if (t >= 3936 * 32) return;
    int lane = t & 31;
    int r0 = lane >> 2, tig = lane & 3;
    int fi = t >> 5;

    if (fi < 2048) {
        int ks = fi & 7, nt = (fi >> 3) & 31, l = fi >> 8;
        int n = nt * 8 + r0, k = ks * 16 + 2 * tig;
        const float* s = (l < 7) ? (w1 + ((size_t)l * HH + n) * CC + k)
                                 : (gate_w + (size_t)n * CC + k);
        float v0 = s[0], v1 = s[1], v8 = s[8], v9 = s[9];
        g_w1f[W1F_IDX(l, nt, ks) * 32 + lane] =
            make_uint2(pk(f16h(v0), f16h(v1)), pk(f16h(v8), f16h(v9)));
    } else if (fi < 3840) {
        int fj = fi - 2048;
        int ks = fj & 15, nt = (fj >> 4) & 15, l = fj >> 8;
        int n = nt * 8 + r0, k = ks * 16 + 2 * tig;
        const float* s = w2 + ((size_t)l * CC + n) * HH + k;
        float v0 = s[0], v1 = s[1], v8 = s[8], v9 = s[9];
        g_w2f[W2F_IDX(l, nt, ks) * 32 + lane] =
            make_uint2(pk(f16h(v0), f16h(v1)), pk(f16h(v8), f16h(v9)));
    } else if (fi < 3888) {
        int fk = fi - 3840;
        int ks = fk & 3, mt = (fk >> 2) & 3, ch = fk >> 4;
        int pa = ch * 64 + mt * 16 + r0, pb = pa + 8;
        int ia = ks * 16 + 2 * tig;
        auto val = [&](int p, int i) -> float {
            return (p < 182 && i < NSH) ? tg[p * NSH + i] : 0.f;
        };
        g_a1f[A1F_IDX(ch, mt, ks) * 32 + lane] =
            make_uint4(pk(f16h(val(pa, ia)),     f16h(val(pa, ia + 1))),
                       pk(f16h(val(pb, ia)),     f16h(val(pb, ia + 1))),
                       pk(f16h(val(pa, ia + 8)), f16h(val(pa, ia + 9))),
                       pk(f16h(val(pb, ia + 8)), f16h(val(pb, ia + 9))));
    } else {
        int fk = fi - 3888;
        int ks = fk & 3, mt = (fk >> 2) & 3, ch = fk >> 4;
        int ia = mt * 16 + r0, ib = ia + 8;
        int p0 = ch * 64 + ks * 16 + 2 * tig;
        auto val = [&](int i, int p) -> float {
            return (p < 182 && i < NSH) ? fg[p * NSH + i] : 0.f;
        };
        g_a2f[A1F_IDX(ch, mt, ks) * 32 + lane] =
            make_uint4(pk(f16h(val(ia, p0)),     f16h(val(ia, p0 + 1))),
                       pk(f16h(val(ib, p0)),     f16h(val(ib, p0 + 1))),
                       pk(f16h(val(ia, p0 + 8)), f16h(val(ia, p0 + 9))),
                       pk(f16h(val(ib, p0 + 8)), f16h(val(ib, p0 + 9))));
    }
}

// ---------------- main kernel: 256 threads, 2 CTAs/SM, 2 nodes/CTA ----------------
__global__ void __launch_bounds__(256, 2)
ffn_fused(const float* __restrict__ x,
          const float* __restrict__ ln0_w, const float* __restrict__ ln0_b,
          const float* __restrict__ aff_w,
          const float* __restrict__ b1,
          const float* __restrict__ gate_b,
          const float* __restrict__ b2,
          float* __restrict__ out)
{
    extern __shared__ float sm[];
    float* rbuf = sm + O_RBUF;

    char* gst = reinterpret_cast<char*>(sm + O_GATES);
    char* xA  = reinterpret_cast<char*>(sm + O_XA);
    char* xB  = reinterpret_cast<char*>(sm + O_XB2);
    char* gbp = reinterpret_cast<char*>(sm + O_G);
    char* h1A = reinterpret_cast<char*>(sm + O_H1A);
    char* h1B = reinterpret_cast<char*>(sm + O_H1B);

    const uint32_t u0   = smem_u32(sm);
    const uint32_t u_xA = u0 + O_XA * 4, u_xB = u0 + O_XB2 * 4;
    const uint32_t u_g  = u0 + O_G * 4;
    const uint32_t u_hA = u0 + O_H1A * 4, u_hB = u0 + O_H1B * 4;

    const int tid = threadIdx.x;
    const int nb  = blockIdx.x;        // node pair
    const int wid = tid >> 5;
    const int lid = tid & 31;
    const int r0  = lid >> 2;
    const int tig = lid & 3;

    // ---- Phase A: norms + normalize for both nodes; zero h1 pad rows ----
    {
        float4* z1 = reinterpret_cast<float4*>(sm + O_H1A + 6468);
        float4* z2 = reinterpret_cast<float4*>(sm + O_H1B + 6468);
        for (int j = tid; j < 495; j += 256) {
            z1[j] = make_float4(0, 0, 0, 0);
            z2[j] = make_float4(0, 0, 0, 0);
        }
    }
    #pragma unroll
    for (int nn = 0; nn < 2; nn++) {
        const float4* xin = reinterpret_cast<const float4*>(
            x + (size_t)(2 * nb + nn) * (NSH * CC));
        float s0 = 0.f, q0 = 0.f, sw = 0.f;
        for (int j4 = tid; j4 < NSH * CC / 4; j4 += 256) {
            float4 v = xin[j4];
            int m = j4 >> 5;
            float d = v.x * v.x + v.y * v.y + v.z * v.z + v.w * v.w;
            if (m == 0) { s0 += v.x + v.y + v.z + v.w; q0 += d; }
            else        sw += c_bal[m] * d;
        }
        #pragma unroll
        for (int o = 16; o > 0; o >>= 1) {
            s0 += __shfl_xor_sync(0xffffffffu, s0, o);
            q0 += __shfl_xor_sync(0xffffffffu, q0, o);
            sw += __shfl_xor_sync(0xffffffffu, sw, o);
        }
        if (lid == 0) {
            rbuf[nn * 32 + wid] = s0;
            rbuf[nn * 32 + 8 + wid] = q0;
            rbuf[nn * 32 + 16 + wid] = sw;
        }
    }
    __syncthreads();
    if (tid < 2) {
        float a = 0.f, b = 0.f, c = 0.f;
        #pragma unroll
        for (int k = 0; k < 8; k++) {
            a += rbuf[tid * 32 + k];
            b += rbuf[tid * 32 + 8 + k];
            c += rbuf[tid * 32 + 16 + k];
        }
        float muv  = a * (1.0f / CC);
        float varv = b * (1.0f / CC) - muv * muv;
        rbuf[tid * 32 + 24] = muv;
        rbuf[tid * 32 + 25] = rsqrtf(varv + EPSV);
        rbuf[tid * 32 + 26] = rsqrtf(c * (1.0f / CC) + EPSV);
    }
    __syncthreads();
    #pragma unroll
    for (int nn = 0; nn < 2; nn++) {
        const float mu = rbuf[nn * 32 + 24], rstd = rbuf[nn * 32 + 25],
                    inv = rbuf[nn * 32 + 26];
        const float4* xin = reinterpret_cast<const float4*>(
            x + (size_t)(2 * nb + nn) * (NSH * CC));
        char* xb = nn ? xB : xA;
        for (int j4 = tid; j4 < NSH * CC / 4; j4 += 256) {
            float4 v = xin[j4];
            int m = j4 >> 5, c4 = (j4 & 31) << 2;
            if (m == 0) {
                float4 w = *reinterpret_cast<const float4*>(ln0_w + c4);
                float4 b = *reinterpret_cast<const float4*>(ln0_b + c4);
                v.x = (v.x - mu) * rstd * w.x + b.x;
                v.y = (v.y - mu) * rstd * w.y + b.y;
                v.z = (v.z - mu) * rstd * w.z + b.z;
                v.w = (v.w - mu) * rstd * w.w + b.w;
            } else {
                float4 a = *reinterpret_cast<const float4*>(aff_w + (c_ltab[m] - 1) * CC + c4);
                v.x *= inv * a.x; v.y *= inv * a.y; v.z *= inv * a.z; v.w *= inv * a.w;
            }
            st1(xb, m * XNS + c4, v.x, v.y);
            st1(xb, m * XNS + c4 + 2, v.z, v.w);
        }
    }
    __syncthreads();

    // ---- Phase C: warp = l (7 = gate); B loaded once, mma for both nodes ----
    {
        const int l = wid;
        const bool isg = (l == 7);
        const int geff  = isg ? 1 : 2 * l + 1;
        const int mbase = isg ? 0 : l * l;
        const uint32_t foC = frag_off(mbase, 0, XNS * 2, lid);
        const uint2* w1p = g_w1f + W1F_IDX(l, 0, 0) * 32 + lid;
        for (int jb = 0; jb < 4; jb++) {
            float accA[8][4], accB[8][4];
            #pragma unroll
            for (int j = 0; j < 8; j++)
                #pragma unroll
                for (int q = 0; q < 4; q++) { accA[j][q] = 0.f; accB[j][q] = 0.f; }
            #pragma unroll
            for (int ks = 0; ks < 8; ks++) {
                uint32_t aA[4], aB[4];
                ldsm4(aA, u_xA + foC + 32 * ks);
                ldsm4(aB, u_xB + foC + 32 * ks);
                #pragma unroll
                for (int j = 0; j < 8; j++) {
                    uint2 B = w1p[((jb * 8 + j) * 8 + ks) * 32];
                    mma16816(accA[j], aA, B.x, B.y);
                    mma16816(accB[j], aB, B.x, B.y);
                }
            }
            #pragma unroll
            for (int j = 0; j < 8; j++) {
                int n0 = (jb * 8 + j) * 8 + 2 * tig;
                if (isg) {
                    if (r0 == 0) {
                        float gb0 = gate_b[n0], gb1 = gate_b[n0 + 1];
                        st1(gst, n0, fast_silu(accA[j][0] + gb0), fast_silu(accA[j][1] + gb1));
                        st1(gst, 256 + n0, fast_silu(accB[j][0] + gb0), fast_silu(accB[j][1] + gb1));
                    }
                } else {
                    float vA0 = accA[j][0], vA1 = accA[j][1];
                    float vB0 = accB[j][0], vB1 = accB[j][1];
                    if (l == 0 && r0 == 0) {
                        float bb0 = b1[n0], bb1 = b1[n0 + 1];
                        vA0 += bb0; vA1 += bb1; vB0 += bb0; vB1 += bb1;
                    }
                    if (r0 < geff) {
                        st1(h1A, (mbase + r0) * GS + n0, vA0, vA1);
                        st1(h1B, (mbase + r0) * GS + n0, vB0, vB1);
                    }
                    if (r0 + 8 < geff) {
                        st1(h1A, (mbase + r0 + 8) * GS + n0, accA[j][2], accA[j][3]);
                        st1(h1B, (mbase + r0 + 8) * GS + n0, accB[j][2], accB[j][3]);
                    }
                }
            }
        }
    }

    // ---- Phase D: per node; 8 warps = 2 mth x 4 ngp, 2x32-col passes ----
    #pragma unroll 1
    for (int nn = 0; nn < 2; nn++) {
        const uint32_t u_h1 = nn ? u_hB : u_hA;
        char* h2c = nn ? h1B : h1A;
        const int mth = wid & 1;
        const int ngp = wid >> 1;
        const uint4* a1p = g_a1f + lid;
        const uint4* a2p = g_a2f + lid;
        float acc2[2][2][4][4];
        #pragma unroll
        for (int s = 0; s < 2; s++)
            #pragma unroll
            for (int m2 = 0; m2 < 2; m2++)
                #pragma unroll
                for (int j = 0; j < 4; j++)
                    #pragma unroll
                    for (int q = 0; q < 4; q++) acc2[s][m2][j][q] = 0.f;

        for (int ch = 0; ch < 3; ch++) {
            __syncthreads();   // g free (prev G2 readers done; first: C/h1 done)
            const int abase = (ch * 4 + 2 * mth) * 4;
            #pragma unroll
            for (int s = 0; s < 2; s++) {
                const int cbase = ngp * 64 + s * 32;
                const uint32_t fob0 = frag_off(0, cbase, GS * 2, lid);
                const uint32_t fob1 = frag_off(0, cbase + 16, GS * 2, lid);
                float acc1[2][4][4];
                #pragma unroll
                for (int m2 = 0; m2 < 2; m2++)
                    #pragma unroll
                    for (int j = 0; j < 4; j++)
                        #pragma unroll
                        for (int q = 0; q < 4; q++) acc1[m2][j][q] = 0.f;
                #pragma unroll
                for (int ks = 0; ks < 4; ks++) {
                    uint32_t bh0[4], bh1[4];
                    ldsm4t(bh0, u_h1 + fob0 + 8448 * ks);
                    ldsm4t(bh1, u_h1 + fob1 + 8448 * ks);
                    #pragma unroll
                    for (int m2 = 0; m2 < 2; m2++) {
                        uint4 A = a1p[(abase + m2 * 4 + ks) * 32];
                        uint32_t ah[4] = {A.x, A.y, A.z, A.w};
                        mma16816(acc1[m2][0], ah, bh0[0], bh0[1]);
                        mma16816(acc1[m2][1], ah, bh0[2], bh0[3]);
                        mma16816(acc1[m2][2], ah, bh1[0], bh1[1]);
                        mma16816(acc1[m2][3], ah, bh1[2], bh1[3]);
                    }
                }
                #pragma unroll
                for (int m2 = 0; m2 < 2; m2++) {
                    int p0 = (2 * mth + m2) * 16 + r0;
                    #pragma unroll
                    for (int j = 0; j < 4; j++) {
                        int c0 = cbase + j * 8 + 2 * tig;
                        st1(gbp, p0 * GS + c0, fast_silu(acc1[m2][j][0]), fast_silu(acc1[m2][j][1]));
                        st1(gbp, (p0 + 8) * GS + c0, fast_silu(acc1[m2][j][2]), fast_silu(acc1[m2][j][3]));
                    }
                }
            }
            __syncthreads();   // g complete
            #pragma unroll
            for (int s = 0; s < 2; s++) {
                const int cbase = ngp * 64 + s * 32;
                const uint32_t fob0 = frag_off(0, cbase, GS * 2, lid);
                const uint32_t fob1 = frag_off(0, cbase + 16, GS * 2, lid);
                #pragma unroll
                for (int ks = 0; ks < 4; ks++) {
                    uint32_t bg0[4], bg1[4];
                    ldsm4t(bg0, u_g + fob0 + 8448 * ks);
                    ldsm4t(bg1, u_g + fob1 + 8448 * ks);
                    #pragma unroll
                    for (int m2 = 0; m2 < 2; m2++) {
                        uint4 A = a2p[(abase + m2 * 4 + ks) * 32];
                        uint32_t ah[4] = {A.x, A.y, A.z, A.w};
                        mma16816(acc2[s][m2][0], ah, bg0[0], bg0[1]);
                        mma16816(acc2[s][m2][1], ah, bg0[2], bg0[3]);
                        mma16816(acc2[s][m2][2], ah, bg1[0], bg1[1]);
                        mma16816(acc2[s][m2][3], ah, bg1[2], bg1[3]);
                    }
                }
            }
        }
        // epilogue: ht rows 1..48 -> h2 (= h1 buffer, all G1 reads done); gate row 0
        #pragma unroll
        for (int s = 0; s < 2; s++) {
            #pragma unroll
            for (int m2 = 0; m2 < 2; m2++) {
                int i0 = (2 * mth + m2) * 16 + r0, i1 = i0 + 8;
                #pragma unroll
                for (int j = 0; j < 4; j++) {
                    int c0 = ngp * 64 + s * 32 + j * 8 + 2 * tig;
                    if (i0 >= 1 && i0 <= 48)
                        st1(h2c, i0 * GS + c0, acc2[s][m2][j][0], acc2[s][m2][j][1]);
                    if (i1 <= 48)
                        st1(h2c, i1 * GS + c0, acc2[s][m2][j][2], acc2[s][m2][j][3]);
                }
            }
        }
        if (tid < 128)
            *reinterpret_cast<uint32_t*>(h2c + tid * 4) =
                *reinterpret_cast<uint32_t*>(gst + nn * 512 + tid * 4);
    }
    __syncthreads();

    // ---- Phase E: B loaded once, mma for both nodes; 0-5: l, both nh; 6,7 split l=6 ----
    {
        float* outA = out + (size_t)(2 * nb) * (NSH * CC);
        float* outB = outA + NSH * CC;
        const int l   = (wid < 6) ? wid : 6;
        const int nhA = (wid < 6) ? 0 : (wid - 6);
        const int nhB = (wid < 6) ? 1 : (wid - 6);
        const int g = 2 * l + 1, mbase = l * l;
        const uint32_t foE = frag_off(mbase, 0, GS * 2, lid);
        const uint2* w2p = g_w2f + W2F_IDX(l, 0, 0) * 32 + lid;
        for (int nh = nhA; nh <= nhB; nh++) {
            float accA[8][4], accB[8][4];
            #pragma unroll
            for (int j = 0; j < 8; j++)
                #pragma unroll
                for (int q = 0; q < 4; q++) { accA[j][q] = 0.f; accB[j][q] = 0.f; }
            #pragma unroll 4
            for (int ks = 0; ks < 16; ks++) {
                uint32_t aA[4], aB[4];
                ldsm4(aA, u_hA + foE + 32 * ks);
                ldsm4(aB, u_hB + foE + 32 * ks);
                #pragma unroll
                for (int j = 0; j < 8; j++) {
                    uint2 B = w2p[((nh * 8 + j) * 16 + ks) * 32];
                    mma16816(accA[j], aA, B.x, B.y);
                    mma16816(accB[j], aB, B.x, B.y);
                }
            }
            #pragma unroll
            for (int j = 0; j < 8; j++) {
                int n0 = (nh * 8 + j) * 8 + 2 * tig;
                float vA0 = accA[j][0], vA1 = accA[j][1];
                float vB0 = accB[j][0], vB1 = accB[j][1];
                if (l == 0 && r0 == 0) {
                    float bb0 = b2[n0], bb1 = b2[n0 + 1];
                    vA0 += bb0; vA1 += bb1; vB0 += bb0; vB1 += bb1;
                }
                if (r0 < g) {
                    *reinterpret_cast<float2*>(outA + (mbase + r0) * CC + n0) =
                        make_float2(vA0, vA1);
                    *reinterpret_cast<float2*>(outB + (mbase + r0) * CC + n0) =
                        make_float2(vB0, vB1);
                }
                if (r0 + 8 < g) {
                    *reinterpret_cast<float2*>(outA + (mbase + r0 + 8) * CC + n0) =
                        make_float2(accA[j][2], accA[j][3]);
                    *reinterpret_cast<float2*>(outB + (mbase + r0 + 8) * CC + n0) =
                        make_float2(accB[j][2], accB[j][3]);
                }
            }
        }
    }
}

extern "C" void kernel_launch(void* const* d_in, const int* in_sizes, int n_in,
                              void* d_out, int out_size)
{
    const float* x      = (const float*)d_in[0];
    const float* ln0_w  = (const float*)d_in[1];
    const float* ln0_b  = (const float*)d_in[2];
    const float* aff_w  = (const float*)d_in[3];
    const float* w1     = (const float*)d_in[4];
    const float* b1     = (const float*)d_in[5];
    const float* gate_w = (const float*)d_in[6];
    const float* gate_b = (const float*)d_in[7];
    const float* w2     = (const float*)d_in[8];
    const float* b2     = (const float*)d_in[9];
    const float* tg     = (const float*)d_in[10];
    const float* fg     = (const float*)d_in[11];
    float* out = (float*)d_out;

    prep_frags<<<(3936 * 32 + 255) / 256, 256>>>(w1, w2, tg, fg, gate_w);

    const int n_nodes = in_sizes[0] / (NSH * CC);
    const int smem_bytes = SMEM_FLOATS * (int)sizeof(float);
    cudaFuncSetAttribute(ffn_fused, cudaFuncAttributeMaxDynamicSharedMemorySize, smem_bytes);
    ffn_fused<<<n_nodes / 2, 256, smem_bytes>>>(x, ln0_w, ln0_b, aff_w, b1,
                                                gate_b, b2, out);
}